// round 6
// baseline (speedup 1.0000x reference)
#include <cuda_runtime.h>
#include <cuda_bf16.h>
#include <math.h>
#include <stdint.h>

// ---------------- problem constants ----------------
#define BV   32000
#define TT   2048
#define HH   4
#define NN_  4096
#define DD   256
#define LL   6
#define KK   1024
#define BB   2
#define EPS  1e-5f

// ---------------- device scratch (no mallocs allowed) ----------------
__device__ float          g_v   [4096L*256];
__device__ __nv_bfloat16  g_v2a [4096L*512];     // [B*T, 2D] hi|lo
__device__ __nv_bfloat16  g_vT2 [2L*256*4096];   // [B][D, 2T]
__device__ float          g_x   [8L*2048*1024];  // [B,H,T,K] fp32
__device__ __nv_bfloat16  g_q2  [8L*2048*2048];  // [B,H,T,2K]
__device__ __nv_bfloat16  g_s2  [8L*2048*4096];  // [B,H,T,2T]
__device__ float          g_a   [8L*2048*256];
__device__ __nv_bfloat16  g_a2  [8L*2048*512];
__device__ __nv_bfloat16  g_y2  [2L*2048*8192];  // [B,T,2N]
__device__ float          g_yE  [2L*4096*256];   // 2 split-K partials
__device__ __nv_bfloat16  g_Dx2 [4L*1024*512];   // [H][K, 2D]
__device__ __nv_bfloat16  g_Dy2 [4L*1024*512];
__device__ __nv_bfloat16  g_E2  [256L*8192];     // [D, 2N]
__device__ __nv_bfloat16  g_ro2 [32000L*512];    // [V, 2D]
__device__ float          g_cos [2048L*1024];
__device__ float          g_sin [2048L*1024];

// ---------------- PTX helpers (baseline ISA only: sm_80-class) ----------------
__device__ __forceinline__ uint32_t smem_u32(const void* p) {
    uint32_t a;
    asm("{ .reg .u64 t; cvta.to.shared.u64 t, %1; cvt.u32.u64 %0, t; }" : "=r"(a) : "l"(p));
    return a;
}
#define CP_ASYNC16(saddr, gaddr) \
    asm volatile("cp.async.cg.shared.global [%0], [%1], 16;" :: "r"(saddr), "l"(gaddr))
#define CP_COMMIT() asm volatile("cp.async.commit_group;" ::: "memory")
#define CP_WAIT1()  asm volatile("cp.async.wait_group 1;" ::: "memory")
#define CP_WAIT0()  asm volatile("cp.async.wait_group 0;" ::: "memory")

#define LDSM_X4(r0, r1, r2, r3, addr) \
    asm volatile("ldmatrix.sync.aligned.m8n8.x4.shared.b16 {%0,%1,%2,%3}, [%4];" \
        : "=r"(r0), "=r"(r1), "=r"(r2), "=r"(r3) : "r"(addr))

#define MMA16816(d, a, b0, b1) \
    asm volatile("mma.sync.aligned.m16n8k16.row.col.f32.bf16.bf16.f32 " \
        "{%0,%1,%2,%3}, {%4,%5,%6,%7}, {%8,%9}, {%0,%1,%2,%3};" \
        : "+f"((d)[0]), "+f"((d)[1]), "+f"((d)[2]), "+f"((d)[3]) \
        : "r"((a)[0]), "r"((a)[1]), "r"((a)[2]), "r"((a)[3]), "r"(b0), "r"(b1))

__device__ __forceinline__ void split2(float f, __nv_bfloat16& h, __nv_bfloat16& l) {
    h = __float2bfloat16(f);
    l = __float2bfloat16(f - __bfloat162float(h));
}

// ---------------- block reduction (256 threads) ----------------
__device__ __forceinline__ float blockReduceSum256(float val) {
    __shared__ float s[8];
    __shared__ float res;
    int lane = threadIdx.x & 31, w = threadIdx.x >> 5;
    #pragma unroll
    for (int o = 16; o; o >>= 1) val += __shfl_xor_sync(0xffffffffu, val, o);
    if (lane == 0) s[w] = val;
    __syncthreads();
    if (threadIdx.x < 8) {
        float v = s[threadIdx.x];
        #pragma unroll
        for (int o = 4; o; o >>= 1) v += __shfl_xor_sync(0xffu, v, o);
        if (threadIdx.x == 0) res = v;
    }
    __syncthreads();
    float r = res;
    __syncthreads();
    return r;
}

// ---------------- elementwise kernels ----------------
__global__ void rope_table_kernel() {
    long idx = (long)blockIdx.x * blockDim.x + threadIdx.x;
    if (idx >= (long)TT * KK) return;
    int t = (int)(idx / KK);
    int k = (int)(idx % KK);
    int i = k & (KK / 2 - 1);
    float ex  = (2.0f * (float)i) / (float)KK;
    float inv = 1.0f / powf(10000.0f, ex);
    float th  = (float)t * inv;
    g_cos[idx] = cosf(th);
    g_sin[idx] = sinf(th);
}

__global__ void embed_ln_kernel(const int* __restrict__ input_,
                                const float* __restrict__ emb) {
    int row = blockIdx.x;
    int tok = input_[row];
    float x = emb[(long)tok * DD + threadIdx.x];
    float mu = blockReduceSum256(x) * (1.0f / DD);
    float d = x - mu;
    float var = blockReduceSum256(d * d) * (1.0f / DD);
    g_v[(long)row * DD + threadIdx.x] = d * rsqrtf(var + EPS);
}

__global__ void addpos_split_kernel(const float* __restrict__ pos) {
    int row = blockIdx.x;                  // B*T
    int t = row & (TT - 1);
    int d = threadIdx.x;
    long o = (long)row * DD + d;
    float f = g_v[o] + pos[(long)t * DD + d];
    g_v[o] = f;
    __nv_bfloat16 h, l; split2(f, h, l);
    g_v2a[(long)row * 2 * DD + d] = h;
    g_v2a[(long)row * 2 * DD + DD + d] = l;
}

__global__ void combine_split_kernel() {
    long row = blockIdx.x;                 // B*T
    float u = g_yE[row * DD + threadIdx.x] +
              g_yE[4096L * 256 + row * DD + threadIdx.x];
    float mu = blockReduceSum256(u) * (1.0f / DD);
    float d = u - mu;
    float var = blockReduceSum256(d * d) * (1.0f / DD);
    float w = g_v[row * DD + threadIdx.x] + d * rsqrtf(var + EPS);
    float mu2 = blockReduceSum256(w) * (1.0f / DD);
    float d2 = w - mu2;
    float var2 = blockReduceSum256(d2 * d2) * (1.0f / DD);
    float f = d2 * rsqrtf(var2 + EPS);
    g_v[row * DD + threadIdx.x] = f;
    __nv_bfloat16 h, l; split2(f, h, l);
    g_v2a[row * 2 * DD + threadIdx.x] = h;
    g_v2a[row * 2 * DD + DD + threadIdx.x] = l;
}

__global__ void ln_split_kernel() {
    long row = blockIdx.x;                 // B*H*T
    float x = g_a[row * DD + threadIdx.x];
    float mu = blockReduceSum256(x) * (1.0f / DD);
    float d = x - mu;
    float var = blockReduceSum256(d * d) * (1.0f / DD);
    float f = d * rsqrtf(var + EPS);
    __nv_bfloat16 h, l; split2(f, h, l);
    g_a2[row * 2 * DD + threadIdx.x] = h;
    g_a2[row * 2 * DD + DD + threadIdx.x] = l;
}

__global__ void rope_split_kernel() {
    long idx = (long)blockIdx.x * blockDim.x + threadIdx.x;  // B*H*T*K
    int k = (int)(idx & (KK - 1));
    long bht = idx >> 10;
    int t = (int)(bht & (TT - 1));
    float xv = g_x[idx];
    float other = (k < KK / 2) ? -g_x[idx + KK / 2] : g_x[idx - KK / 2];
    long tk = (long)t * KK + k;
    float qv = xv * g_cos[tk] + other * g_sin[tk];
    __nv_bfloat16 h, l; split2(qv, h, l);
    g_q2[bht * 2048 + k] = h;
    g_q2[bht * 2048 + KK + k] = l;
}

// X [R,C] fp32 -> Y [C, 2R] bf16 (hi cols [0,R), lo cols [R,2R))
__global__ void transpose_split_kernel(const float* __restrict__ X,
                                       __nv_bfloat16* __restrict__ Y,
                                       int R, int C, long inZ, long outZ) {
    __shared__ float tile[32][33];
    X += (long)blockIdx.z * inZ;
    Y += (long)blockIdx.z * outZ;
    int r0 = blockIdx.y * 32, c0 = blockIdx.x * 32;
    int tx = threadIdx.x, ty = threadIdx.y;   // (32,8)
    #pragma unroll
    for (int i = 0; i < 32; i += 8)
        tile[ty + i][tx] = X[(long)(r0 + ty + i) * C + c0 + tx];
    __syncthreads();
    #pragma unroll
    for (int i = 0; i < 32; i += 8) {
        float f = tile[tx][ty + i];           // X[r0+tx][c0+ty+i]
        __nv_bfloat16 h, l; split2(f, h, l);
        long orow = (long)(c0 + ty + i) * 2 * R;
        Y[orow + r0 + tx] = h;
        Y[orow + R + r0 + tx] = l;
    }
}

// ---------------- mma.sync GEMM (HMMA path) ----------------
// C[M,N] = A2[M,2K] x B2[N,2K]^T with bf16 hi/lo split (3 passes over K).
// CTA tile 128x128, K-chunk 64, 3-stage cp.async pipeline, 1 barrier/chunk.
// 8 warps in 2(m) x 4(n), warp tile 64x32 via 4x4 m16n8k16.
// Smem rows: 144B stride (128B data + 16B pad) -> conflict-free ldmatrix
// (r*144 mod 128 = r*16) and conflict-free cp.async stores (gcd(9,32)=1).
// EPI: 0=fp32, 1=relu fp32, 2=split bf16 (hi at col, lo at col+loOff),
//      3=relu*G split bf16
// SYM: A==B, M==N==2048; blockIdx.x enumerates 136 upper-tri block pairs,
//      mirror tile written via smem transpose.
// Split-K: nsplit in {1,2}; z = blockIdx.z -> (sp = z%nsplit, batch = z/nsplit).
#define ROWB 144
#define OPER_BYTES (128 * ROWB)            // 18432
#define STAGE_BYTES (2 * OPER_BYTES)       // 36864
#define SMEM_GEMM_BYTES (3 * STAGE_BYTES)  // 110592

template<int EPI, bool SYM>
__global__ void __launch_bounds__(256, 2)
gemm_mma(const __nv_bfloat16* __restrict__ A, const __nv_bfloat16* __restrict__ B,
         void* __restrict__ Cv, const float* __restrict__ G,
         int Kd, int KdLo, int lda, int ldb, int ldc, int ldgt, int loOff,
         long sAb, long sAh, long sBb, long sBh, long sCb, long sCh,
         long sGb, long sGh, int Hdim, int nsplit, long sSplitC)
{
    extern __shared__ char dsm[];
    uint32_t sbase = smem_u32(dsm);

    int tid = threadIdx.x;
    int lane = tid & 31;
    int wid = tid >> 5;
    int wm = wid >> 2;        // 0..1
    int wn = wid & 3;         // 0..3

    int zz = blockIdx.z;
    int sp = (nsplit > 1) ? (zz & 1) : 0;
    int z  = (nsplit > 1) ? (zz >> 1) : zz;
    int bb = z / Hdim, hh = z - bb * Hdim;
    A += bb * sAb + hh * sAh;
    B += bb * sBb + hh * sBh;
    long cOff = bb * sCb + hh * sCh + sp * sSplitC;
    if (EPI == 3) G += bb * sGb + hh * sGh;

    int m0, n0, diag = 0;
    if (SYM) {
        int L = blockIdx.x, ii = 0;
        while (L >= 16 - ii) { L -= 16 - ii; ii++; }
        m0 = ii * 128; n0 = (ii + L) * 128;
        diag = (L == 0);
    } else {
        m0 = blockIdx.y * 128;
        n0 = blockIdx.x * 128;
    }

    const int KC = Kd >> 6;       // 64-wide chunks per pass
    const int nch = 3 * KC;
    const int spK = sp * Kd;

    int lrow  = tid & 127;        // row within tile
    int lhalf = (tid >> 7) * 64;  // byte half of 128B row
    int lelem = (tid >> 7) * 32;  // element half

    auto issue = [&](int cc) {
        int p  = (cc < KC) ? 0 : ((cc < 2 * KC) ? 1 : 2);
        int kc = cc - p * KC;
        int aoff = ((p == 2) ? KdLo : 0) + spK + (kc << 6);
        int boff = ((p == 1) ? KdLo : 0) + spK + (kc << 6);
        uint32_t st = sbase + (cc % 3) * STAGE_BYTES;
        const __nv_bfloat16* ga = A + (long)(m0 + lrow) * lda + aoff + lelem;
        const __nv_bfloat16* gb = B + (long)(n0 + lrow) * ldb + boff + lelem;
        uint32_t da = st + lrow * ROWB + lhalf;
        uint32_t db = st + OPER_BYTES + lrow * ROWB + lhalf;
        #pragma unroll
        for (int j = 0; j < 4; j++) {
            CP_ASYNC16(da + j * 16, ga + j * 8);
            CP_ASYNC16(db + j * 16, gb + j * 8);
        }
    };

    float acc[4][4][4];
    #pragma unroll
    for (int i = 0; i < 4; i++)
        #pragma unroll
        for (int j = 0; j < 4; j++)
            #pragma unroll
            for (int r = 0; r < 4; r++) acc[i][j][r] = 0.0f;

    issue(0); CP_COMMIT();
    issue(1); CP_COMMIT();

    int rsel = lane & 15;
    int chalf = (lane >> 4) * 16;

    for (int c = 0; c < nch; c++) {
        CP_WAIT1();              // group c complete (newest committed = c+1)
        __syncthreads();         // all warps done computing chunk c-1
        if (c + 2 < nch) issue(c + 2);
        CP_COMMIT();             // always commit (empty group near tail)

        uint32_t sa = sbase + (c % 3) * STAGE_BYTES;
        uint32_t sb = sa + OPER_BYTES;

        #pragma unroll
        for (int ks = 0; ks < 4; ks++) {
            int colb = ks * 32 + chalf;
            uint32_t ar[4][4], br[2][4];
            #pragma unroll
            for (int mt = 0; mt < 4; mt++) {
                uint32_t addr = sa + (uint32_t)(wm * 64 + mt * 16 + rsel) * ROWB + colb;
                LDSM_X4(ar[mt][0], ar[mt][1], ar[mt][2], ar[mt][3], addr);
            }
            #pragma unroll
            for (int n2 = 0; n2 < 2; n2++) {
                uint32_t addr = sb + (uint32_t)(wn * 32 + n2 * 16 + rsel) * ROWB + colb;
                LDSM_X4(br[n2][0], br[n2][1], br[n2][2], br[n2][3], addr);
            }
            #pragma unroll
            for (int mt = 0; mt < 4; mt++)
                #pragma unroll
                for (int nt = 0; nt < 4; nt++) {
                    int n2 = nt >> 1, j = nt & 1;
                    MMA16816(acc[mt][nt], ar[mt], br[n2][j], br[n2][2 + j]);
                }
        }
    }

    // ---------------- epilogue ----------------
    int g = lane >> 2, tg = lane & 3;
    float* Cf = (float*)Cv;
    __nv_bfloat16* Cb = (__nv_bfloat16*)Cv;

    #pragma unroll
    for (int mt = 0; mt < 4; mt++) {
        #pragma unroll
        for (int half = 0; half < 2; half++) {
            long row = m0 + wm * 64 + mt * 16 + g + half * 8;
            #pragma unroll
            for (int nt = 0; nt < 4; nt++) {
                int co = n0 + wn * 32 + nt * 8 + tg * 2;
                float f0 = acc[mt][nt][half * 2 + 0];
                float f1 = acc[mt][nt][half * 2 + 1];
                if (EPI == 0) {
                    *reinterpret_cast<float2*>(&Cf[cOff + row * ldc + co]) =
                        make_float2(f0, f1);
                } else if (EPI == 1) {
                    *reinterpret_cast<float2*>(&Cf[cOff + row * ldc + co]) =
                        make_float2(fmaxf(f0, 0.f), fmaxf(f1, 0.f));
                } else {
                    if (EPI == 3) {
                        float2 gv = *reinterpret_cast<const float2*>(
                            &G[row * (long)ldgt + co]);
                        f0 = fmaxf(f0, 0.f) * gv.x;
                        f1 = fmaxf(f1, 0.f) * gv.y;
                    }
                    __nv_bfloat16 h0, l0, h1, l1;
                    split2(f0, h0, l0);
                    split2(f1, h1, l1);
                    uint32_t hp = (uint32_t)*(uint16_t*)&h0 |
                                  ((uint32_t)*(uint16_t*)&h1 << 16);
                    uint32_t lp = (uint32_t)*(uint16_t*)&l0 |
                                  ((uint32_t)*(uint16_t*)&l1 << 16);
                    *reinterpret_cast<uint32_t*>(&Cb[cOff + row * ldc + co]) = hp;
                    *reinterpret_cast<uint32_t*>(&Cb[cOff + row * ldc + co + loOff]) = lp;
                }
            }
        }
    }

    // mirror tile C[n,m] = C[m,n] via smem transpose (coalesced stores)
    if (SYM && !diag) {
        CP_WAIT0();
        __syncthreads();
        __nv_bfloat16* sm = (__nv_bfloat16*)dsm;   // 128 x 144 bf16
        #pragma unroll
        for (int ph = 0; ph < 2; ph++) {
            #pragma unroll
            for (int mt = 0; mt < 4; mt++)
                #pragma unroll
                for (int half = 0; half < 2; half++) {
                    int r = wm * 64 + mt * 16 + g + half * 8;
                    #pragma unroll
                    for (int nt = 0; nt < 4; nt++) {
                        int cc = wn * 32 + nt * 8 + tg * 2;
                        float f0 = acc[mt][nt][half * 2 + 0];
                        float f1 = acc[mt][nt][half * 2 + 1];
                        __nv_bfloat16 h0, l0, h1, l1;
                        split2(f0, h0, l0);
                        split2(f1, h1, l1);
                        sm[cc * 144 + r]       = ph ? l0 : h0;
                        sm[(cc + 1) * 144 + r] = ph ? l1 : h1;
                    }
                }
            __syncthreads();
            int cc2 = tid >> 1, seg = (tid & 1) * 64;
            const uint4* src = (const uint4*)(sm + cc2 * 144 + seg);
            uint4* dst = (uint4*)(&Cb[cOff + (long)(n0 + cc2) * ldc + m0 + seg +
                                      (ph ? loOff : 0)]);
            #pragma unroll
            for (int u = 0; u < 8; u++) dst[u] = src[u];
            __syncthreads();
        }
    }
}

// ---------------- host launch ----------------
extern "C" void kernel_launch(void* const* d_in, const int* in_sizes, int n_in,
                              void* d_out, int out_size) {
    const int*   input_  = (const int*)d_in[0];
    const float* emb     = (const float*)d_in[1];
    const float* pos     = (const float*)d_in[2];
    const float* Dx      = (const float*)d_in[3];
    const float* Dy      = (const float*)d_in[4];
    const float* E       = (const float*)d_in[5];
    const float* readout = (const float*)d_in[6];
    float* out = (float*)d_out;

    cudaFuncSetAttribute(gemm_mma<0, false>, cudaFuncAttributeMaxDynamicSharedMemorySize, SMEM_GEMM_BYTES);
    cudaFuncSetAttribute(gemm_mma<1, false>, cudaFuncAttributeMaxDynamicSharedMemorySize, SMEM_GEMM_BYTES);
    cudaFuncSetAttribute(gemm_mma<2, true>,  cudaFuncAttributeMaxDynamicSharedMemorySize, SMEM_GEMM_BYTES);
    cudaFuncSetAttribute(gemm_mma<3, false>, cudaFuncAttributeMaxDynamicSharedMemorySize, SMEM_GEMM_BYTES);

    float *v, *x, *a, *yE;
    __nv_bfloat16 *v2a, *vT2, *q2, *s2, *a2, *y2, *Dx2, *Dy2, *E2, *ro2;
    cudaGetSymbolAddress((void**)&v,   g_v);
    cudaGetSymbolAddress((void**)&v2a, g_v2a);
    cudaGetSymbolAddress((void**)&vT2, g_vT2);
    cudaGetSymbolAddress((void**)&x,   g_x);
    cudaGetSymbolAddress((void**)&q2,  g_q2);
    cudaGetSymbolAddress((void**)&s2,  g_s2);
    cudaGetSymbolAddress((void**)&a,   g_a);
    cudaGetSymbolAddress((void**)&a2,  g_a2);
    cudaGetSymbolAddress((void**)&y2,  g_y2);
    cudaGetSymbolAddress((void**)&yE,  g_yE);
    cudaGetSymbolAddress((void**)&Dx2, g_Dx2);
    cudaGetSymbolAddress((void**)&Dy2, g_Dy2);
    cudaGetSymbolAddress((void**)&E2,  g_E2);
    cudaGetSymbolAddress((void**)&ro2, g_ro2);

    dim3 tb(32, 8);

    rope_table_kernel<<<(TT * KK + 255) / 256, 256>>>();
    embed_ln_kernel<<<BB * TT, 256>>>(input_, emb);
    transpose_split_kernel<<<dim3(KK / 32, DD / 32, HH), tb>>>(Dx, Dx2, DD, KK, (long)DD * KK, (long)KK * 2 * DD);
    transpose_split_kernel<<<dim3(KK / 32, DD / 32, HH), tb>>>(Dy, Dy2, DD, KK, (long)DD * KK, (long)KK * 2 * DD);
    transpose_split_kernel<<<dim3(DD / 32, NN_ / 32, 1), tb>>>(E, E2, NN_, DD, 0, 0);
    transpose_split_kernel<<<dim3(BV / 32, DD / 32, 1), tb>>>(readout, ro2, DD, BV, 0, 0);

    const long TK  = (long)TT * KK;
    const long T2D = (long)TT * 2 * DD;
    const long T2K = (long)TT * 2 * KK;
    const long T2T = (long)TT * 2 * TT;
    const long T2N = (long)TT * 2 * NN_;
    const long TD  = (long)TT * DD;

    for (int l = 0; l < LL; l++) {
        addpos_split_kernel<<<BB * TT, 256>>>(pos);
        transpose_split_kernel<<<dim3(DD / 32, TT / 32, BB), tb>>>(v, vT2, TT, DD, TD, (long)DD * 2 * TT);

        // x[b,h] = relu(v2a_b @ Dx2_h^T) fp32 : M=2048 N=1024 Kd=256
        gemm_mma<1, false><<<dim3(KK / 128, TT / 128, BB * HH), 256, SMEM_GEMM_BYTES>>>(
            v2a, Dx2, x, nullptr,
            DD, DD, 2 * DD, 2 * DD, KK, 0, 0,
            T2D, 0, 0, (long)KK * 2 * DD, (long)HH * TK, TK, 0, 0, HH, 1, 0);

        rope_split_kernel<<<(int)((long)BB * HH * TT * KK / 256), 256>>>();

        // s2[b,h] = q2 @ q2^T (split out, SYMMETRIC) : 136 upper-tri blocks
        gemm_mma<2, true><<<dim3(136, 1, BB * HH), 256, SMEM_GEMM_BYTES>>>(
            q2, q2, s2, nullptr,
            KK, KK, 2 * KK, 2 * KK, 2 * TT, 0, TT,
            (long)HH * T2K, T2K, (long)HH * T2K, T2K, (long)HH * T2T, T2T, 0, 0, HH, 1, 0);

        // a[b,h] = s2 @ vT2^T fp32 : M=2048 N=256 Kd=2048
        gemm_mma<0, false><<<dim3(DD / 128, TT / 128, BB * HH), 256, SMEM_GEMM_BYTES>>>(
            s2, vT2, a, nullptr,
            TT, TT, 2 * TT, 2 * TT, DD, 0, 0,
            (long)HH * T2T, T2T, (long)DD * 2 * TT, 0, (long)HH * TD, TD, 0, 0, HH, 1, 0);

        ln_split_kernel<<<BB * HH * TT, 256>>>();

        // y2[b,t,h*K+n] = relu(a2 @ Dy2^T) * x (split, loOff=NN_)
        gemm_mma<3, false><<<dim3(KK / 128, TT / 128, BB * HH), 256, SMEM_GEMM_BYTES>>>(
            a2, Dy2, y2, x,
            DD, DD, 2 * DD, 2 * DD, 2 * NN_, KK, NN_,
            (long)HH * T2D, T2D, 0, (long)KK * 2 * DD,
            T2N, (long)KK, (long)HH * TK, TK, HH, 1, 0);

        // yE partials = y2 @ E2^T (split-K=2) : M=4096 N=256, Kd=2048/split
        gemm_mma<0, false><<<dim3(DD / 128, (BB * TT) / 128, 2), 256, SMEM_GEMM_BYTES>>>(
            y2, E2, yE, nullptr,
            NN_ / 2, NN_, 2 * NN_, 2 * NN_, DD, 0, 0,
            0, 0, 0, 0, 0, 0, 0, 0, 1, 2, 4096L * 256);

        combine_split_kernel<<<BB * TT, 256>>>();
    }

    // out = v2a @ ro2^T fp32 : M=4096 N=32000 Kd=256
    gemm_mma<0, false><<<dim3(BV / 128, (BB * TT) / 128, 1), 256, SMEM_GEMM_BYTES>>>(
        v2a, ro2, out, nullptr,
        DD, DD, 2 * DD, 2 * DD, BV, 0, 0,
        0, 0, 0, 0, 0, 0, 0, 0, 1, 1, 0);
}

// round 7
// speedup vs baseline: 1.5952x; 1.5952x over previous
#include <cuda_runtime.h>
#include <cuda_bf16.h>
#include <math.h>
#include <stdint.h>

// ---------------- problem constants ----------------
#define BV   32000
#define TT   2048
#define HH   4
#define NN_  4096
#define DD   256
#define LL   6
#define KK   1024
#define BB   2
#define EPS  1e-5f

// ---------------- device scratch (no mallocs allowed) ----------------
__device__ float          g_v   [4096L*256];
__device__ __nv_bfloat16  g_v2a [4096L*512];     // [B*T, 2D] hi|lo
__device__ __nv_bfloat16  g_vT2 [2L*256*4096];   // [B][D, 2T]
__device__ float          g_x   [8L*2048*1024];  // [B,H,T,K] fp32
__device__ __nv_bfloat16  g_q2  [8L*2048*2048];  // [B,H,T,2K]
__device__ __nv_bfloat16  g_s2  [8L*2048*4096];  // [B,H,T,2T]
__device__ float          g_a   [8L*2048*256];
__device__ __nv_bfloat16  g_a2  [8L*2048*512];
__device__ __nv_bfloat16  g_y2  [2L*2048*8192];  // [B,T,2N]
__device__ float          g_yE  [2L*4096*256];   // 2 split-K partials
__device__ __nv_bfloat16  g_Dx2 [4L*1024*512];   // [H][K, 2D]
__device__ __nv_bfloat16  g_Dy2 [4L*1024*512];
__device__ __nv_bfloat16  g_E2  [256L*8192];     // [D, 2N]
__device__ __nv_bfloat16  g_ro2 [32000L*512];    // [V, 2D]
__device__ float          g_cos [2048L*1024];
__device__ float          g_sin [2048L*1024];

// ---------------- PTX helpers (baseline ISA only: sm_80-class) ----------------
__device__ __forceinline__ uint32_t smem_u32(const void* p) {
    uint32_t a;
    asm("{ .reg .u64 t; cvta.to.shared.u64 t, %1; cvt.u32.u64 %0, t; }" : "=r"(a) : "l"(p));
    return a;
}
#define CP_ASYNC16(saddr, gaddr) \
    asm volatile("cp.async.cg.shared.global [%0], [%1], 16;" :: "r"(saddr), "l"(gaddr))
#define CP_COMMIT() asm volatile("cp.async.commit_group;" ::: "memory")
#define CP_WAIT0()  asm volatile("cp.async.wait_group 0;" ::: "memory")

#define LDSM_X4(r0, r1, r2, r3, addr) \
    asm volatile("ldmatrix.sync.aligned.m8n8.x4.shared.b16 {%0,%1,%2,%3}, [%4];" \
        : "=r"(r0), "=r"(r1), "=r"(r2), "=r"(r3) : "r"(addr))

#define MMA16816(d, a, b0, b1) \
    asm volatile("mma.sync.aligned.m16n8k16.row.col.f32.bf16.bf16.f32 " \
        "{%0,%1,%2,%3}, {%4,%5,%6,%7}, {%8,%9}, {%0,%1,%2,%3};" \
        : "+f"((d)[0]), "+f"((d)[1]), "+f"((d)[2]), "+f"((d)[3]) \
        : "r"((a)[0]), "r"((a)[1]), "r"((a)[2]), "r"((a)[3]), "r"(b0), "r"(b1))

__device__ __forceinline__ void split2(float f, __nv_bfloat16& h, __nv_bfloat16& l) {
    h = __float2bfloat16(f);
    l = __float2bfloat16(f - __bfloat162float(h));
}

// ---------------- block reduction (256 threads) ----------------
__device__ __forceinline__ float blockReduceSum256(float val) {
    __shared__ float s[8];
    __shared__ float res;
    int lane = threadIdx.x & 31, w = threadIdx.x >> 5;
    #pragma unroll
    for (int o = 16; o; o >>= 1) val += __shfl_xor_sync(0xffffffffu, val, o);
    if (lane == 0) s[w] = val;
    __syncthreads();
    if (threadIdx.x < 8) {
        float v = s[threadIdx.x];
        #pragma unroll
        for (int o = 4; o; o >>= 1) v += __shfl_xor_sync(0xffu, v, o);
        if (threadIdx.x == 0) res = v;
    }
    __syncthreads();
    float r = res;
    __syncthreads();
    return r;
}

// ---------------- elementwise kernels ----------------
__global__ void rope_table_kernel() {
    long idx = (long)blockIdx.x * blockDim.x + threadIdx.x;
    if (idx >= (long)TT * KK) return;
    int t = (int)(idx / KK);
    int k = (int)(idx % KK);
    int i = k & (KK / 2 - 1);
    float ex  = (2.0f * (float)i) / (float)KK;
    float inv = 1.0f / powf(10000.0f, ex);
    float th  = (float)t * inv;
    g_cos[idx] = cosf(th);
    g_sin[idx] = sinf(th);
}

__global__ void embed_ln_kernel(const int* __restrict__ input_,
                                const float* __restrict__ emb) {
    int row = blockIdx.x;
    int tok = input_[row];
    float x = emb[(long)tok * DD + threadIdx.x];
    float mu = blockReduceSum256(x) * (1.0f / DD);
    float d = x - mu;
    float var = blockReduceSum256(d * d) * (1.0f / DD);
    g_v[(long)row * DD + threadIdx.x] = d * rsqrtf(var + EPS);
}

__global__ void addpos_split_kernel(const float* __restrict__ pos) {
    int row = blockIdx.x;                  // B*T
    int t = row & (TT - 1);
    int d = threadIdx.x;
    long o = (long)row * DD + d;
    float f = g_v[o] + pos[(long)t * DD + d];
    g_v[o] = f;
    __nv_bfloat16 h, l; split2(f, h, l);
    g_v2a[(long)row * 2 * DD + d] = h;
    g_v2a[(long)row * 2 * DD + DD + d] = l;
}

__global__ void combine_split_kernel() {
    long row = blockIdx.x;                 // B*T
    float u = g_yE[row * DD + threadIdx.x] +
              g_yE[4096L * 256 + row * DD + threadIdx.x];
    float mu = blockReduceSum256(u) * (1.0f / DD);
    float d = u - mu;
    float var = blockReduceSum256(d * d) * (1.0f / DD);
    float w = g_v[row * DD + threadIdx.x] + d * rsqrtf(var + EPS);
    float mu2 = blockReduceSum256(w) * (1.0f / DD);
    float d2 = w - mu2;
    float var2 = blockReduceSum256(d2 * d2) * (1.0f / DD);
    float f = d2 * rsqrtf(var2 + EPS);
    g_v[row * DD + threadIdx.x] = f;
    __nv_bfloat16 h, l; split2(f, h, l);
    g_v2a[row * 2 * DD + threadIdx.x] = h;
    g_v2a[row * 2 * DD + DD + threadIdx.x] = l;
}

__global__ void ln_split_kernel() {
    long row = blockIdx.x;                 // B*H*T
    float x = g_a[row * DD + threadIdx.x];
    float mu = blockReduceSum256(x) * (1.0f / DD);
    float d = x - mu;
    float var = blockReduceSum256(d * d) * (1.0f / DD);
    float f = d * rsqrtf(var + EPS);
    __nv_bfloat16 h, l; split2(f, h, l);
    g_a2[row * 2 * DD + threadIdx.x] = h;
    g_a2[row * 2 * DD + DD + threadIdx.x] = l;
}

__global__ void rope_split_kernel() {
    long idx = (long)blockIdx.x * blockDim.x + threadIdx.x;  // B*H*T*K
    int k = (int)(idx & (KK - 1));
    long bht = idx >> 10;
    int t = (int)(bht & (TT - 1));
    float xv = g_x[idx];
    float other = (k < KK / 2) ? -g_x[idx + KK / 2] : g_x[idx - KK / 2];
    long tk = (long)t * KK + k;
    float qv = xv * g_cos[tk] + other * g_sin[tk];
    __nv_bfloat16 h, l; split2(qv, h, l);
    g_q2[bht * 2048 + k] = h;
    g_q2[bht * 2048 + KK + k] = l;
}

// X [R,C] fp32 -> Y [C, 2R] bf16 (hi cols [0,R), lo cols [R,2R))
__global__ void transpose_split_kernel(const float* __restrict__ X,
                                       __nv_bfloat16* __restrict__ Y,
                                       int R, int C, long inZ, long outZ) {
    __shared__ float tile[32][33];
    X += (long)blockIdx.z * inZ;
    Y += (long)blockIdx.z * outZ;
    int r0 = blockIdx.y * 32, c0 = blockIdx.x * 32;
    int tx = threadIdx.x, ty = threadIdx.y;   // (32,8)
    #pragma unroll
    for (int i = 0; i < 32; i += 8)
        tile[ty + i][tx] = X[(long)(r0 + ty + i) * C + c0 + tx];
    __syncthreads();
    #pragma unroll
    for (int i = 0; i < 32; i += 8) {
        float f = tile[tx][ty + i];           // X[r0+tx][c0+ty+i]
        __nv_bfloat16 h, l; split2(f, h, l);
        long orow = (long)(c0 + ty + i) * 2 * R;
        Y[orow + r0 + tx] = h;
        Y[orow + R + r0 + tx] = l;
    }
}

// ---------------- mma.sync GEMM (HMMA path, fused 3-pass) ----------------
// C[M,N] = A2[M,2K] x B2[N,2K]^T with bf16 hi/lo split.
// Fused: per 32-wide K chunk, load Ah, Al, Bh, Bl tiles once and do
// AhBh + AhBl + AlBh in registers -> 1.5x arithmetic intensity, 3x fewer
// barriers vs pass-sequential.
// CTA tile 128x128, 2-stage cp.async pipeline (stage = 4 x 10240B = 40KB),
// single __syncthreads per chunk. 8 warps 2(m) x 4(n), warp tile 64x32.
// EPI: 0=fp32, 1=relu fp32, 2=split bf16 (hi at col, lo at col+loOff),
//      3=relu*G split bf16
// SYM: A==B, M==N==2048; blockIdx.x enumerates 136 upper-tri block pairs,
//      mirror tile written via smem transpose.
// Split-K: nsplit in {1,2}.
#define OPER_BYTES 10240                   // 128 rows x 80B (64B data + pad)
#define STAGE_BYTES (4 * OPER_BYTES)       // 40960: Ah|Al|Bh|Bl
#define SMEM_GEMM_BYTES (2 * STAGE_BYTES)  // 81920

template<int EPI, bool SYM>
__global__ void __launch_bounds__(256, 2)
gemm_mma(const __nv_bfloat16* __restrict__ A, const __nv_bfloat16* __restrict__ B,
         void* __restrict__ Cv, const float* __restrict__ G,
         int Kd, int KdLo, int lda, int ldb, int ldc, int ldgt, int loOff,
         long sAb, long sAh, long sBb, long sBh, long sCb, long sCh,
         long sGb, long sGh, int Hdim, int nsplit, long sSplitC)
{
    extern __shared__ char dsm[];
    uint32_t sbase = smem_u32(dsm);

    int tid = threadIdx.x;
    int lane = tid & 31;
    int wid = tid >> 5;
    int wm = wid >> 2;        // 0..1
    int wn = wid & 3;         // 0..3

    int zz = blockIdx.z;
    int sp = (nsplit > 1) ? (zz & 1) : 0;
    int z  = (nsplit > 1) ? (zz >> 1) : zz;
    int bb = z / Hdim, hh = z - bb * Hdim;
    A += bb * sAb + hh * sAh;
    B += bb * sBb + hh * sBh;
    long cOff = bb * sCb + hh * sCh + sp * sSplitC;
    if (EPI == 3) G += bb * sGb + hh * sGh;

    int m0, n0, diag = 0;
    if (SYM) {
        int L = blockIdx.x, ii = 0;
        while (L >= 16 - ii) { L -= 16 - ii; ii++; }
        m0 = ii * 128; n0 = (ii + L) * 128;
        diag = (L == 0);
    } else {
        m0 = blockIdx.y * 128;
        n0 = blockIdx.x * 128;
    }

    const int KC = Kd >> 5;       // 32-wide chunks (one fused pass each)
    const int spK = sp * Kd;

    int lrow = tid >> 2;          // 0..63
    int lseg = tid & 3;

    auto issue = [&](int cc) {
        int koff = spK + (cc << 5);
        uint32_t st = sbase + (cc & 1) * STAGE_BYTES;
        #pragma unroll
        for (int i = 0; i < 2; i++) {
            int row = lrow + i * 64;
            uint32_t so = row * 80 + lseg * 16;
            long go = lseg * 8;
            const __nv_bfloat16* ga = A + (long)(m0 + row) * lda + koff + go;
            const __nv_bfloat16* gb = B + (long)(n0 + row) * ldb + koff + go;
            CP_ASYNC16(st + so,                  ga);           // A hi
            CP_ASYNC16(st + OPER_BYTES + so,     ga + KdLo);    // A lo
            CP_ASYNC16(st + 2 * OPER_BYTES + so, gb);           // B hi
            CP_ASYNC16(st + 3 * OPER_BYTES + so, gb + KdLo);    // B lo
        }
    };

    float acc[4][4][4];
    #pragma unroll
    for (int i = 0; i < 4; i++)
        #pragma unroll
        for (int j = 0; j < 4; j++)
            #pragma unroll
            for (int r = 0; r < 4; r++) acc[i][j][r] = 0.0f;

    issue(0); CP_COMMIT();

    int rsel = lane & 15;
    int chalf = (lane >> 4) * 16;

    for (int c = 0; c < KC; c++) {
        CP_WAIT0();              // chunk c data complete (this thread)
        __syncthreads();         // all threads' copies visible; prev compute done
        if (c + 1 < KC) issue(c + 1);
        CP_COMMIT();

        uint32_t sah = sbase + (c & 1) * STAGE_BYTES;
        uint32_t sal = sah + OPER_BYTES;
        uint32_t sbh = sah + 2 * OPER_BYTES;
        uint32_t sbl = sah + 3 * OPER_BYTES;

        #pragma unroll
        for (int ks = 0; ks < 2; ks++) {
            int colb = ks * 32 + chalf;
            uint32_t ar[4][4], brh[2][4], brl[2][4];
            #pragma unroll
            for (int mt = 0; mt < 4; mt++) {
                uint32_t addr = sah + (uint32_t)(wm * 64 + mt * 16 + rsel) * 80u + colb;
                LDSM_X4(ar[mt][0], ar[mt][1], ar[mt][2], ar[mt][3], addr);
            }
            #pragma unroll
            for (int n2 = 0; n2 < 2; n2++) {
                uint32_t addr = sbh + (uint32_t)(wn * 32 + n2 * 16 + rsel) * 80u + colb;
                LDSM_X4(brh[n2][0], brh[n2][1], brh[n2][2], brh[n2][3], addr);
            }
            #pragma unroll
            for (int n2 = 0; n2 < 2; n2++) {
                uint32_t addr = sbl + (uint32_t)(wn * 32 + n2 * 16 + rsel) * 80u + colb;
                LDSM_X4(brl[n2][0], brl[n2][1], brl[n2][2], brl[n2][3], addr);
            }
            // Ah x Bh
            #pragma unroll
            for (int mt = 0; mt < 4; mt++)
                #pragma unroll
                for (int nt = 0; nt < 4; nt++) {
                    int n2 = nt >> 1, j = nt & 1;
                    MMA16816(acc[mt][nt], ar[mt], brh[n2][j], brh[n2][2 + j]);
                }
            // Ah x Bl
            #pragma unroll
            for (int mt = 0; mt < 4; mt++)
                #pragma unroll
                for (int nt = 0; nt < 4; nt++) {
                    int n2 = nt >> 1, j = nt & 1;
                    MMA16816(acc[mt][nt], ar[mt], brl[n2][j], brl[n2][2 + j]);
                }
            // Al x Bh (reload A frags from lo tile)
            #pragma unroll
            for (int mt = 0; mt < 4; mt++) {
                uint32_t addr = sal + (uint32_t)(wm * 64 + mt * 16 + rsel) * 80u + colb;
                LDSM_X4(ar[mt][0], ar[mt][1], ar[mt][2], ar[mt][3], addr);
            }
            #pragma unroll
            for (int mt = 0; mt < 4; mt++)
                #pragma unroll
                for (int nt = 0; nt < 4; nt++) {
                    int n2 = nt >> 1, j = nt & 1;
                    MMA16816(acc[mt][nt], ar[mt], brh[n2][j], brh[n2][2 + j]);
                }
        }
    }

    // ---------------- epilogue ----------------
    int g = lane >> 2, tg = lane & 3;
    float* Cf = (float*)Cv;
    __nv_bfloat16* Cb = (__nv_bfloat16*)Cv;

    #pragma unroll
    for (int mt = 0; mt < 4; mt++) {
        #pragma unroll
        for (int half = 0; half < 2; half++) {
            long row = m0 + wm * 64 + mt * 16 + g + half * 8;
            #pragma unroll
            for (int nt = 0; nt < 4; nt++) {
                int co = n0 + wn * 32 + nt * 8 + tg * 2;
                float f0 = acc[mt][nt][half * 2 + 0];
                float f1 = acc[mt][nt][half * 2 + 1];
                if (EPI == 0) {
                    *reinterpret_cast<float2*>(&Cf[cOff + row * ldc + co]) =
                        make_float2(f0, f1);
                } else if (EPI == 1) {
                    *reinterpret_cast<float2*>(&Cf[cOff + row * ldc + co]) =
                        make_float2(fmaxf(f0, 0.f), fmaxf(f1, 0.f));
                } else {
                    if (EPI == 3) {
                        float2 gv = *reinterpret_cast<const float2*>(
                            &G[row * (long)ldgt + co]);
                        f0 = fmaxf(f0, 0.f) * gv.x;
                        f1 = fmaxf(f1, 0.f) * gv.y;
                    }
                    __nv_bfloat16 h0, l0, h1, l1;
                    split2(f0, h0, l0);
                    split2(f1, h1, l1);
                    uint32_t hp = (uint32_t)*(uint16_t*)&h0 |
                                  ((uint32_t)*(uint16_t*)&h1 << 16);
                    uint32_t lp = (uint32_t)*(uint16_t*)&l0 |
                                  ((uint32_t)*(uint16_t*)&l1 << 16);
                    *reinterpret_cast<uint32_t*>(&Cb[cOff + row * ldc + co]) = hp;
                    *reinterpret_cast<uint32_t*>(&Cb[cOff + row * ldc + co + loOff]) = lp;
                }
            }
        }
    }

    // mirror tile C[n,m] = C[m,n] via smem transpose (coalesced stores)
    if (SYM && !diag) {
        CP_WAIT0();
        __syncthreads();
        __nv_bfloat16* sm = (__nv_bfloat16*)dsm;   // 128 x 144 bf16
        #pragma unroll
        for (int ph = 0; ph < 2; ph++) {
            #pragma unroll
            for (int mt = 0; mt < 4; mt++)
                #pragma unroll
                for (int half = 0; half < 2; half++) {
                    int r = wm * 64 + mt * 16 + g + half * 8;
                    #pragma unroll
                    for (int nt = 0; nt < 4; nt++) {
                        int cc = wn * 32 + nt * 8 + tg * 2;
                        float f0 = acc[mt][nt][half * 2 + 0];
                        float f1 = acc[mt][nt][half * 2 + 1];
                        __nv_bfloat16 h0, l0, h1, l1;
                        split2(f0, h0, l0);
                        split2(f1, h1, l1);
                        sm[cc * 144 + r]       = ph ? l0 : h0;
                        sm[(cc + 1) * 144 + r] = ph ? l1 : h1;
                    }
                }
            __syncthreads();
            int cc2 = tid >> 1, seg = (tid & 1) * 64;
            const uint4* src = (const uint4*)(sm + cc2 * 144 + seg);
            uint4* dst = (uint4*)(&Cb[cOff + (long)(n0 + cc2) * ldc + m0 + seg +
                                      (ph ? loOff : 0)]);
            #pragma unroll
            for (int u = 0; u < 8; u++) dst[u] = src[u];
            __syncthreads();
        }
    }
}

// ---------------- host launch ----------------
extern "C" void kernel_launch(void* const* d_in, const int* in_sizes, int n_in,
                              void* d_out, int out_size) {
    const int*   input_  = (const int*)d_in[0];
    const float* emb     = (const float*)d_in[1];
    const float* pos     = (const float*)d_in[2];
    const float* Dx      = (const float*)d_in[3];
    const float* Dy      = (const float*)d_in[4];
    const float* E       = (const float*)d_in[5];
    const float* readout = (const float*)d_in[6];
    float* out = (float*)d_out;

    cudaFuncSetAttribute(gemm_mma<0, false>, cudaFuncAttributeMaxDynamicSharedMemorySize, SMEM_GEMM_BYTES);
    cudaFuncSetAttribute(gemm_mma<1, false>, cudaFuncAttributeMaxDynamicSharedMemorySize, SMEM_GEMM_BYTES);
    cudaFuncSetAttribute(gemm_mma<2, true>,  cudaFuncAttributeMaxDynamicSharedMemorySize, SMEM_GEMM_BYTES);
    cudaFuncSetAttribute(gemm_mma<3, false>, cudaFuncAttributeMaxDynamicSharedMemorySize, SMEM_GEMM_BYTES);

    float *v, *x, *a, *yE;
    __nv_bfloat16 *v2a, *vT2, *q2, *s2, *a2, *y2, *Dx2, *Dy2, *E2, *ro2;
    cudaGetSymbolAddress((void**)&v,   g_v);
    cudaGetSymbolAddress((void**)&v2a, g_v2a);
    cudaGetSymbolAddress((void**)&vT2, g_vT2);
    cudaGetSymbolAddress((void**)&x,   g_x);
    cudaGetSymbolAddress((void**)&q2,  g_q2);
    cudaGetSymbolAddress((void**)&s2,  g_s2);
    cudaGetSymbolAddress((void**)&a,   g_a);
    cudaGetSymbolAddress((void**)&a2,  g_a2);
    cudaGetSymbolAddress((void**)&y2,  g_y2);
    cudaGetSymbolAddress((void**)&yE,  g_yE);
    cudaGetSymbolAddress((void**)&Dx2, g_Dx2);
    cudaGetSymbolAddress((void**)&Dy2, g_Dy2);
    cudaGetSymbolAddress((void**)&E2,  g_E2);
    cudaGetSymbolAddress((void**)&ro2, g_ro2);

    dim3 tb(32, 8);

    rope_table_kernel<<<(TT * KK + 255) / 256, 256>>>();
    embed_ln_kernel<<<BB * TT, 256>>>(input_, emb);
    transpose_split_kernel<<<dim3(KK / 32, DD / 32, HH), tb>>>(Dx, Dx2, DD, KK, (long)DD * KK, (long)KK * 2 * DD);
    transpose_split_kernel<<<dim3(KK / 32, DD / 32, HH), tb>>>(Dy, Dy2, DD, KK, (long)DD * KK, (long)KK * 2 * DD);
    transpose_split_kernel<<<dim3(DD / 32, NN_ / 32, 1), tb>>>(E, E2, NN_, DD, 0, 0);
    transpose_split_kernel<<<dim3(BV / 32, DD / 32, 1), tb>>>(readout, ro2, DD, BV, 0, 0);

    const long TK  = (long)TT * KK;
    const long T2D = (long)TT * 2 * DD;
    const long T2K = (long)TT * 2 * KK;
    const long T2T = (long)TT * 2 * TT;
    const long T2N = (long)TT * 2 * NN_;
    const long TD  = (long)TT * DD;

    for (int l = 0; l < LL; l++) {
        addpos_split_kernel<<<BB * TT, 256>>>(pos);
        transpose_split_kernel<<<dim3(DD / 32, TT / 32, BB), tb>>>(v, vT2, TT, DD, TD, (long)DD * 2 * TT);

        // x[b,h] = relu(v2a_b @ Dx2_h^T) fp32 : M=2048 N=1024 Kd=256
        gemm_mma<1, false><<<dim3(KK / 128, TT / 128, BB * HH), 256, SMEM_GEMM_BYTES>>>(
            v2a, Dx2, x, nullptr,
            DD, DD, 2 * DD, 2 * DD, KK, 0, 0,
            T2D, 0, 0, (long)KK * 2 * DD, (long)HH * TK, TK, 0, 0, HH, 1, 0);

        rope_split_kernel<<<(int)((long)BB * HH * TT * KK / 256), 256>>>();

        // s2[b,h] = q2 @ q2^T (split out, SYMMETRIC) : 136 upper-tri blocks
        gemm_mma<2, true><<<dim3(136, 1, BB * HH), 256, SMEM_GEMM_BYTES>>>(
            q2, q2, s2, nullptr,
            KK, KK, 2 * KK, 2 * KK, 2 * TT, 0, TT,
            (long)HH * T2K, T2K, (long)HH * T2K, T2K, (long)HH * T2T, T2T, 0, 0, HH, 1, 0);

        // a[b,h] = s2 @ vT2^T fp32 : M=2048 N=256 Kd=2048
        gemm_mma<0, false><<<dim3(DD / 128, TT / 128, BB * HH), 256, SMEM_GEMM_BYTES>>>(
            s2, vT2, a, nullptr,
            TT, TT, 2 * TT, 2 * TT, DD, 0, 0,
            (long)HH * T2T, T2T, (long)DD * 2 * TT, 0, (long)HH * TD, TD, 0, 0, HH, 1, 0);

        ln_split_kernel<<<BB * HH * TT, 256>>>();

        // y2[b,t,h*K+n] = relu(a2 @ Dy2^T) * x (split, loOff=NN_)
        gemm_mma<3, false><<<dim3(KK / 128, TT / 128, BB * HH), 256, SMEM_GEMM_BYTES>>>(
            a2, Dy2, y2, x,
            DD, DD, 2 * DD, 2 * DD, 2 * NN_, KK, NN_,
            (long)HH * T2D, T2D, 0, (long)KK * 2 * DD,
            T2N, (long)KK, (long)HH * TK, TK, HH, 1, 0);

        // yE partials = y2 @ E2^T (split-K=2) : M=4096 N=256, Kd=2048/split
        gemm_mma<0, false><<<dim3(DD / 128, (BB * TT) / 128, 2), 256, SMEM_GEMM_BYTES>>>(
            y2, E2, yE, nullptr,
            NN_ / 2, NN_, 2 * NN_, 2 * NN_, DD, 0, 0,
            0, 0, 0, 0, 0, 0, 0, 0, 1, 2, 4096L * 256);

        combine_split_kernel<<<BB * TT, 256>>>();
    }

    // out = v2a @ ro2^T fp32 : M=4096 N=32000 Kd=256
    gemm_mma<0, false><<<dim3(BV / 128, (BB * TT) / 128, 1), 256, SMEM_GEMM_BYTES>>>(
        v2a, ro2, out, nullptr,
        DD, DD, 2 * DD, 2 * DD, BV, 0, 0,
        0, 0, 0, 0, 0, 0, 0, 0, 1, 1, 0);
}

// round 8
// speedup vs baseline: 1.8195x; 1.1406x over previous
#include <cuda_runtime.h>
#include <cuda_bf16.h>
#include <math.h>
#include <stdint.h>

// ---------------- problem constants ----------------
#define BV   32000
#define TT   2048
#define HH   4
#define NN_  4096
#define DD   256
#define LL   6
#define KK   1024
#define BB   2
#define EPS  1e-5f

// ---------------- device scratch (no mallocs allowed) ----------------
__device__ float          g_v   [4096L*256];
__device__ __nv_bfloat16  g_v2a [4096L*512];     // [B*T, 2D] hi|lo
__device__ __nv_bfloat16  g_vT2 [2L*256*4096];   // [B][D, 2T]
__device__ float          g_x   [8L*2048*1024];  // [B,H,T,K] fp32
__device__ __nv_bfloat16  g_q2  [8L*2048*2048];  // [B,H,T,2K]
__device__ __nv_bfloat16  g_s2  [8L*2048*4096];  // [B,H,T,2T]
__device__ float          g_a   [8L*2048*256];
__device__ __nv_bfloat16  g_a2  [8L*2048*512];
__device__ __nv_bfloat16  g_y2  [2L*2048*8192];  // [B,T,2N]
__device__ float          g_yE  [4L*4096*256];   // 4 split-K partials
__device__ __nv_bfloat16  g_Dx2 [4L*1024*512];   // [H][K, 2D]
__device__ __nv_bfloat16  g_Dy2 [4L*1024*512];
__device__ __nv_bfloat16  g_E2  [256L*8192];     // [D, 2N]
__device__ __nv_bfloat16  g_ro2 [32000L*512];    // [V, 2D]
__device__ float          g_cos [2048L*1024];
__device__ float          g_sin [2048L*1024];

// ---------------- PTX helpers (baseline ISA only: sm_80-class) ----------------
__device__ __forceinline__ uint32_t smem_u32(const void* p) {
    uint32_t a;
    asm("{ .reg .u64 t; cvta.to.shared.u64 t, %1; cvt.u32.u64 %0, t; }" : "=r"(a) : "l"(p));
    return a;
}
#define CP_ASYNC16(saddr, gaddr) \
    asm volatile("cp.async.cg.shared.global [%0], [%1], 16;" :: "r"(saddr), "l"(gaddr))
#define CP_COMMIT() asm volatile("cp.async.commit_group;" ::: "memory")
#define CP_WAIT1()  asm volatile("cp.async.wait_group 1;" ::: "memory")
#define CP_WAIT0()  asm volatile("cp.async.wait_group 0;" ::: "memory")

#define LDSM_X4(r0, r1, r2, r3, addr) \
    asm volatile("ldmatrix.sync.aligned.m8n8.x4.shared.b16 {%0,%1,%2,%3}, [%4];" \
        : "=r"(r0), "=r"(r1), "=r"(r2), "=r"(r3) : "r"(addr))

#define MMA16816(d, a, b0, b1) \
    asm volatile("mma.sync.aligned.m16n8k16.row.col.f32.bf16.bf16.f32 " \
        "{%0,%1,%2,%3}, {%4,%5,%6,%7}, {%8,%9}, {%0,%1,%2,%3};" \
        : "+f"((d)[0]), "+f"((d)[1]), "+f"((d)[2]), "+f"((d)[3]) \
        : "r"((a)[0]), "r"((a)[1]), "r"((a)[2]), "r"((a)[3]), "r"(b0), "r"(b1))

__device__ __forceinline__ void split2(float f, __nv_bfloat16& h, __nv_bfloat16& l) {
    h = __float2bfloat16(f);
    l = __float2bfloat16(f - __bfloat162float(h));
}

// swizzled smem offset: 64B rows, seg' = seg ^ ((row>>1)&3)
__device__ __forceinline__ uint32_t swz(uint32_t row, uint32_t seg) {
    return row * 64u + (((seg) ^ ((row >> 1) & 3u)) << 4);
}

// ---------------- block reduction (256 threads) ----------------
__device__ __forceinline__ float blockReduceSum256(float val) {
    __shared__ float s[8];
    __shared__ float res;
    int lane = threadIdx.x & 31, w = threadIdx.x >> 5;
    #pragma unroll
    for (int o = 16; o; o >>= 1) val += __shfl_xor_sync(0xffffffffu, val, o);
    if (lane == 0) s[w] = val;
    __syncthreads();
    if (threadIdx.x < 8) {
        float v = s[threadIdx.x];
        #pragma unroll
        for (int o = 4; o; o >>= 1) v += __shfl_xor_sync(0xffu, v, o);
        if (threadIdx.x == 0) res = v;
    }
    __syncthreads();
    float r = res;
    __syncthreads();
    return r;
}

// ---------------- elementwise kernels ----------------
__global__ void rope_table_kernel() {
    long idx = (long)blockIdx.x * blockDim.x + threadIdx.x;
    if (idx >= (long)TT * KK) return;
    int t = (int)(idx / KK);
    int k = (int)(idx % KK);
    int i = k & (KK / 2 - 1);
    float ex  = (2.0f * (float)i) / (float)KK;
    float inv = 1.0f / powf(10000.0f, ex);
    float th  = (float)t * inv;
    g_cos[idx] = cosf(th);
    g_sin[idx] = sinf(th);
}

// v = ln(emb[input]) + pos   (fused layer-0 addpos), plus hi/lo split
__global__ void embed_ln_kernel(const int* __restrict__ input_,
                                const float* __restrict__ emb,
                                const float* __restrict__ pos) {
    int row = blockIdx.x;                 // B*T
    int t = row & (TT - 1);
    int tok = input_[row];
    float x = emb[(long)tok * DD + threadIdx.x];
    float mu = blockReduceSum256(x) * (1.0f / DD);
    float d = x - mu;
    float var = blockReduceSum256(d * d) * (1.0f / DD);
    float f = d * rsqrtf(var + EPS) + pos[(long)t * DD + threadIdx.x];
    g_v[(long)row * DD + threadIdx.x] = f;
    __nv_bfloat16 h, l; split2(f, h, l);
    g_v2a[(long)row * 2 * DD + threadIdx.x] = h;
    g_v2a[(long)row * 2 * DD + DD + threadIdx.x] = l;
}

// v = ln(v + ln(sum of 4 yE partials)) [+ pos for next layer], plus split
__global__ void combine_split_kernel(const float* __restrict__ pos, int do_pos) {
    long row = blockIdx.x;                 // B*T
    const long P = 4096L * 256;
    float u = g_yE[row * DD + threadIdx.x] + g_yE[P + row * DD + threadIdx.x] +
              g_yE[2 * P + row * DD + threadIdx.x] + g_yE[3 * P + row * DD + threadIdx.x];
    float mu = blockReduceSum256(u) * (1.0f / DD);
    float d = u - mu;
    float var = blockReduceSum256(d * d) * (1.0f / DD);
    float w = g_v[row * DD + threadIdx.x] + d * rsqrtf(var + EPS);
    float mu2 = blockReduceSum256(w) * (1.0f / DD);
    float d2 = w - mu2;
    float var2 = blockReduceSum256(d2 * d2) * (1.0f / DD);
    float f = d2 * rsqrtf(var2 + EPS);
    if (do_pos) {
        int t = (int)(row & (TT - 1));
        f += pos[(long)t * DD + threadIdx.x];
    }
    g_v[row * DD + threadIdx.x] = f;
    __nv_bfloat16 h, l; split2(f, h, l);
    g_v2a[row * 2 * DD + threadIdx.x] = h;
    g_v2a[row * 2 * DD + DD + threadIdx.x] = l;
}

__global__ void ln_split_kernel() {
    long row = blockIdx.x;                 // B*H*T
    float x = g_a[row * DD + threadIdx.x];
    float mu = blockReduceSum256(x) * (1.0f / DD);
    float d = x - mu;
    float var = blockReduceSum256(d * d) * (1.0f / DD);
    float f = d * rsqrtf(var + EPS);
    __nv_bfloat16 h, l; split2(f, h, l);
    g_a2[row * 2 * DD + threadIdx.x] = h;
    g_a2[row * 2 * DD + DD + threadIdx.x] = l;
}

__global__ void rope_split_kernel() {
    long idx = (long)blockIdx.x * blockDim.x + threadIdx.x;  // B*H*T*K
    int k = (int)(idx & (KK - 1));
    long bht = idx >> 10;
    int t = (int)(bht & (TT - 1));
    float xv = g_x[idx];
    float other = (k < KK / 2) ? -g_x[idx + KK / 2] : g_x[idx - KK / 2];
    long tk = (long)t * KK + k;
    float qv = xv * g_cos[tk] + other * g_sin[tk];
    __nv_bfloat16 h, l; split2(qv, h, l);
    g_q2[bht * 2048 + k] = h;
    g_q2[bht * 2048 + KK + k] = l;
}

// X [R,C] fp32 -> Y [C, 2R] bf16 (hi cols [0,R), lo cols [R,2R))
__global__ void transpose_split_kernel(const float* __restrict__ X,
                                       __nv_bfloat16* __restrict__ Y,
                                       int R, int C, long inZ, long outZ) {
    __shared__ float tile[32][33];
    X += (long)blockIdx.z * inZ;
    Y += (long)blockIdx.z * outZ;
    int r0 = blockIdx.y * 32, c0 = blockIdx.x * 32;
    int tx = threadIdx.x, ty = threadIdx.y;   // (32,8)
    #pragma unroll
    for (int i = 0; i < 32; i += 8)
        tile[ty + i][tx] = X[(long)(r0 + ty + i) * C + c0 + tx];
    __syncthreads();
    #pragma unroll
    for (int i = 0; i < 32; i += 8) {
        float f = tile[tx][ty + i];           // X[r0+tx][c0+ty+i]
        __nv_bfloat16 h, l; split2(f, h, l);
        long orow = (long)(c0 + ty + i) * 2 * R;
        Y[orow + r0 + tx] = h;
        Y[orow + R + r0 + tx] = l;
    }
}

// ---------------- mma.sync GEMM (HMMA path, fused 3-pass) ----------------
// C[M,N] = A2[M,2K] x B2[N,2K]^T with bf16 hi/lo split.
// Fused: per 32-wide K chunk, load Ah, Al, Bh, Bl tiles once; do
// AhBh + AhBl + AlBh.
// CTA tile 128x128, 3-stage cp.async pipeline (stage = 4 x 8192B = 32KB),
// XOR-swizzled 64B smem rows (conflict-free ldmatrix AND cp.async stores),
// single __syncthreads per chunk. 8 warps 2(m) x 4(n), warp tile 64x32.
// EPI: 0=fp32, 1=relu fp32, 2=split bf16 (hi at col, lo at col+loOff),
//      3=relu*G split bf16
// SYM: A==B, M==N==2048; blockIdx.x enumerates 136 upper-tri block pairs,
//      mirror tile written via smem transpose.
// Split-K: nsplit partials, sp = blockIdx.z % nsplit.
#define OPER_BYTES 8192                    // 128 rows x 64B
#define STAGE_BYTES (4 * OPER_BYTES)       // 32768: Ah|Al|Bh|Bl
#define SMEM_GEMM_BYTES (3 * STAGE_BYTES)  // 98304

template<int EPI, bool SYM>
__global__ void __launch_bounds__(256, 2)
gemm_mma(const __nv_bfloat16* __restrict__ A, const __nv_bfloat16* __restrict__ B,
         void* __restrict__ Cv, const float* __restrict__ G,
         int Kd, int KdLo, int lda, int ldb, int ldc, int ldgt, int loOff,
         long sAb, long sAh, long sBb, long sBh, long sCb, long sCh,
         long sGb, long sGh, int Hdim, int nsplit, long sSplitC)
{
    extern __shared__ char dsm[];
    uint32_t sbase = smem_u32(dsm);

    int tid = threadIdx.x;
    int lane = tid & 31;
    int wid = tid >> 5;
    int wm = wid >> 2;        // 0..1
    int wn = wid & 3;         // 0..3

    int zz = blockIdx.z;
    int sp = 0, z = zz;
    if (nsplit > 1) { sp = zz % nsplit; z = zz / nsplit; }
    int bb = z / Hdim, hh = z - bb * Hdim;
    A += bb * sAb + hh * sAh;
    B += bb * sBb + hh * sBh;
    long cOff = bb * sCb + hh * sCh + sp * sSplitC;
    if (EPI == 3) G += bb * sGb + hh * sGh;

    int m0, n0, diag = 0;
    if (SYM) {
        int L = blockIdx.x, ii = 0;
        while (L >= 16 - ii) { L -= 16 - ii; ii++; }
        m0 = ii * 128; n0 = (ii + L) * 128;
        diag = (L == 0);
    } else {
        m0 = blockIdx.y * 128;
        n0 = blockIdx.x * 128;
    }

    const int KC = Kd >> 5;       // 32-wide chunks (one fused pass each)
    const int spK = sp * Kd;

    int lrow = tid >> 2;          // 0..63
    int lseg = tid & 3;

    auto issue = [&](int cc) {
        int koff = spK + (cc << 5);
        uint32_t st = sbase + (cc % 3) * STAGE_BYTES;
        #pragma unroll
        for (int i = 0; i < 2; i++) {
            uint32_t row = lrow + i * 64;
            uint32_t so = swz(row, (uint32_t)lseg);
            long go = lseg * 8;
            const __nv_bfloat16* ga = A + (long)(m0 + row) * lda + koff + go;
            const __nv_bfloat16* gb = B + (long)(n0 + row) * ldb + koff + go;
            CP_ASYNC16(st + so,                  ga);           // A hi
            CP_ASYNC16(st + OPER_BYTES + so,     ga + KdLo);    // A lo
            CP_ASYNC16(st + 2 * OPER_BYTES + so, gb);           // B hi
            CP_ASYNC16(st + 3 * OPER_BYTES + so, gb + KdLo);    // B lo
        }
    };

    float acc[4][4][4];
    #pragma unroll
    for (int i = 0; i < 4; i++)
        #pragma unroll
        for (int j = 0; j < 4; j++)
            #pragma unroll
            for (int r = 0; r < 4; r++) acc[i][j][r] = 0.0f;

    issue(0); CP_COMMIT();
    issue(1); CP_COMMIT();

    int rsel = lane & 15;
    int hi16 = lane >> 4;         // 0 or 1: second 16B seg of the k16 block

    for (int c = 0; c < KC; c++) {
        CP_WAIT1();              // chunk c data complete
        __syncthreads();         // copies visible to all; compute c-1 done
        if (c + 2 < KC) issue(c + 2);
        CP_COMMIT();

        uint32_t sah = sbase + (c % 3) * STAGE_BYTES;
        uint32_t sal = sah + OPER_BYTES;
        uint32_t sbh = sah + 2 * OPER_BYTES;
        uint32_t sbl = sah + 3 * OPER_BYTES;

        #pragma unroll
        for (int ks = 0; ks < 2; ks++) {
            uint32_t segb = (uint32_t)(ks * 2 + hi16);
            uint32_t ar[4][4], brh[2][4], brl[2][4];
            #pragma unroll
            for (int mt = 0; mt < 4; mt++) {
                uint32_t row = (uint32_t)(wm * 64 + mt * 16 + rsel);
                LDSM_X4(ar[mt][0], ar[mt][1], ar[mt][2], ar[mt][3], sah + swz(row, segb));
            }
            #pragma unroll
            for (int n2 = 0; n2 < 2; n2++) {
                uint32_t row = (uint32_t)(wn * 32 + n2 * 16 + rsel);
                LDSM_X4(brh[n2][0], brh[n2][1], brh[n2][2], brh[n2][3], sbh + swz(row, segb));
            }
            #pragma unroll
            for (int n2 = 0; n2 < 2; n2++) {
                uint32_t row = (uint32_t)(wn * 32 + n2 * 16 + rsel);
                LDSM_X4(brl[n2][0], brl[n2][1], brl[n2][2], brl[n2][3], sbl + swz(row, segb));
            }
            // Ah x Bh
            #pragma unroll
            for (int mt = 0; mt < 4; mt++)
                #pragma unroll
                for (int nt = 0; nt < 4; nt++) {
                    int n2 = nt >> 1, j = nt & 1;
                    MMA16816(acc[mt][nt], ar[mt], brh[n2][j], brh[n2][2 + j]);
                }
            // Ah x Bl
            #pragma unroll
            for (int mt = 0; mt < 4; mt++)
                #pragma unroll
                for (int nt = 0; nt < 4; nt++) {
                    int n2 = nt >> 1, j = nt & 1;
                    MMA16816(acc[mt][nt], ar[mt], brl[n2][j], brl[n2][2 + j]);
                }
            // Al x Bh (reload A frags from lo tile)
            #pragma unroll
            for (int mt = 0; mt < 4; mt++) {
                uint32_t row = (uint32_t)(wm * 64 + mt * 16 + rsel);
                LDSM_X4(ar[mt][0], ar[mt][1], ar[mt][2], ar[mt][3], sal + swz(row, segb));
            }
            #pragma unroll
            for (int mt = 0; mt < 4; mt++)
                #pragma unroll
                for (int nt = 0; nt < 4; nt++) {
                    int n2 = nt >> 1, j = nt & 1;
                    MMA16816(acc[mt][nt], ar[mt], brh[n2][j], brh[n2][2 + j]);
                }
        }
    }

    // ---------------- epilogue ----------------
    int g = lane >> 2, tg = lane & 3;
    float* Cf = (float*)Cv;
    __nv_bfloat16* Cb = (__nv_bfloat16*)Cv;

    #pragma unroll
    for (int mt = 0; mt < 4; mt++) {
        #pragma unroll
        for (int half = 0; half < 2; half++) {
            long row = m0 + wm * 64 + mt * 16 + g + half * 8;
            #pragma unroll
            for (int nt = 0; nt < 4; nt++) {
                int co = n0 + wn * 32 + nt * 8 + tg * 2;
                float f0 = acc[mt][nt][half * 2 + 0];
                float f1 = acc[mt][nt][half * 2 + 1];
                if (EPI == 0) {
                    *reinterpret_cast<float2*>(&Cf[cOff + row * ldc + co]) =
                        make_float2(f0, f1);
                } else if (EPI == 1) {
                    *reinterpret_cast<float2*>(&Cf[cOff + row * ldc + co]) =
                        make_float2(fmaxf(f0, 0.f), fmaxf(f1, 0.f));
                } else {
                    if (EPI == 3) {
                        float2 gv = *reinterpret_cast<const float2*>(
                            &G[row * (long)ldgt + co]);
                        f0 = fmaxf(f0, 0.f) * gv.x;
                        f1 = fmaxf(f1, 0.f) * gv.y;
                    }
                    __nv_bfloat16 h0, l0, h1, l1;
                    split2(f0, h0, l0);
                    split2(f1, h1, l1);
                    uint32_t hp = (uint32_t)*(uint16_t*)&h0 |
                                  ((uint32_t)*(uint16_t*)&h1 << 16);
                    uint32_t lp = (uint32_t)*(uint16_t*)&l0 |
                                  ((uint32_t)*(uint16_t*)&l1 << 16);
                    *reinterpret_cast<uint32_t*>(&Cb[cOff + row * ldc + co]) = hp;
                    *reinterpret_cast<uint32_t*>(&Cb[cOff + row * ldc + co + loOff]) = lp;
                }
            }
        }
    }

    // mirror tile C[n,m] = C[m,n] via smem transpose (coalesced stores)
    if (SYM && !diag) {
        CP_WAIT0();
        __syncthreads();
        __nv_bfloat16* sm = (__nv_bfloat16*)dsm;   // 128 x 144 bf16
        #pragma unroll
        for (int ph = 0; ph < 2; ph++) {
            #pragma unroll
            for (int mt = 0; mt < 4; mt++)
                #pragma unroll
                for (int half = 0; half < 2; half++) {
                    int r = wm * 64 + mt * 16 + g + half * 8;
                    #pragma unroll
                    for (int nt = 0; nt < 4; nt++) {
                        int cc = wn * 32 + nt * 8 + tg * 2;
                        float f0 = acc[mt][nt][half * 2 + 0];
                        float f1 = acc[mt][nt][half * 2 + 1];
                        __nv_bfloat16 h0, l0, h1, l1;
                        split2(f0, h0, l0);
                        split2(f1, h1, l1);
                        sm[cc * 144 + r]       = ph ? l0 : h0;
                        sm[(cc + 1) * 144 + r] = ph ? l1 : h1;
                    }
                }
            __syncthreads();
            int cc2 = tid >> 1, seg = (tid & 1) * 64;
            const uint4* src = (const uint4*)(sm + cc2 * 144 + seg);
            uint4* dst = (uint4*)(&Cb[cOff + (long)(n0 + cc2) * ldc + m0 + seg +
                                      (ph ? loOff : 0)]);
            #pragma unroll
            for (int u = 0; u < 8; u++) dst[u] = src[u];
            __syncthreads();
        }
    }
}

// ---------------- host launch ----------------
extern "C" void kernel_launch(void* const* d_in, const int* in_sizes, int n_in,
                              void* d_out, int out_size) {
    const int*   input_  = (const int*)d_in[0];
    const float* emb     = (const float*)d_in[1];
    const float* pos     = (const float*)d_in[2];
    const float* Dx      = (const float*)d_in[3];
    const float* Dy      = (const float*)d_in[4];
    const float* E       = (const float*)d_in[5];
    const float* readout = (const float*)d_in[6];
    float* out = (float*)d_out;

    cudaFuncSetAttribute(gemm_mma<0, false>, cudaFuncAttributeMaxDynamicSharedMemorySize, SMEM_GEMM_BYTES);
    cudaFuncSetAttribute(gemm_mma<1, false>, cudaFuncAttributeMaxDynamicSharedMemorySize, SMEM_GEMM_BYTES);
    cudaFuncSetAttribute(gemm_mma<2, true>,  cudaFuncAttributeMaxDynamicSharedMemorySize, SMEM_GEMM_BYTES);
    cudaFuncSetAttribute(gemm_mma<3, false>, cudaFuncAttributeMaxDynamicSharedMemorySize, SMEM_GEMM_BYTES);

    float *v, *x, *a, *yE;
    __nv_bfloat16 *v2a, *vT2, *q2, *s2, *a2, *y2, *Dx2, *Dy2, *E2, *ro2;
    cudaGetSymbolAddress((void**)&v,   g_v);
    cudaGetSymbolAddress((void**)&v2a, g_v2a);
    cudaGetSymbolAddress((void**)&vT2, g_vT2);
    cudaGetSymbolAddress((void**)&x,   g_x);
    cudaGetSymbolAddress((void**)&q2,  g_q2);
    cudaGetSymbolAddress((void**)&s2,  g_s2);
    cudaGetSymbolAddress((void**)&a,   g_a);
    cudaGetSymbolAddress((void**)&a2,  g_a2);
    cudaGetSymbolAddress((void**)&y2,  g_y2);
    cudaGetSymbolAddress((void**)&yE,  g_yE);
    cudaGetSymbolAddress((void**)&Dx2, g_Dx2);
    cudaGetSymbolAddress((void**)&Dy2, g_Dy2);
    cudaGetSymbolAddress((void**)&E2,  g_E2);
    cudaGetSymbolAddress((void**)&ro2, g_ro2);

    dim3 tb(32, 8);

    rope_table_kernel<<<(TT * KK + 255) / 256, 256>>>();
    embed_ln_kernel<<<BB * TT, 256>>>(input_, emb, pos);
    transpose_split_kernel<<<dim3(KK / 32, DD / 32, HH), tb>>>(Dx, Dx2, DD, KK, (long)DD * KK, (long)KK * 2 * DD);
    transpose_split_kernel<<<dim3(KK / 32, DD / 32, HH), tb>>>(Dy, Dy2, DD, KK, (long)DD * KK, (long)KK * 2 * DD);
    transpose_split_kernel<<<dim3(DD / 32, NN_ / 32, 1), tb>>>(E, E2, NN_, DD, 0, 0);
    transpose_split_kernel<<<dim3(BV / 32, DD / 32, 1), tb>>>(readout, ro2, DD, BV, 0, 0);

    const long TK  = (long)TT * KK;
    const long T2D = (long)TT * 2 * DD;
    const long T2K = (long)TT * 2 * KK;
    const long T2T = (long)TT * 2 * TT;
    const long T2N = (long)TT * 2 * NN_;
    const long TD  = (long)TT * DD;

    for (int l = 0; l < LL; l++) {
        transpose_split_kernel<<<dim3(DD / 32, TT / 32, BB), tb>>>(v, vT2, TT, DD, TD, (long)DD * 2 * TT);

        // x[b,h] = relu(v2a_b @ Dx2_h^T) fp32 : M=2048 N=1024 Kd=256
        gemm_mma<1, false><<<dim3(KK / 128, TT / 128, BB * HH), 256, SMEM_GEMM_BYTES>>>(
            v2a, Dx2, x, nullptr,
            DD, DD, 2 * DD, 2 * DD, KK, 0, 0,
            T2D, 0, 0, (long)KK * 2 * DD, (long)HH * TK, TK, 0, 0, HH, 1, 0);

        rope_split_kernel<<<(int)((long)BB * HH * TT * KK / 256), 256>>>();

        // s2[b,h] = q2 @ q2^T (split out, SYMMETRIC) : 136 upper-tri blocks
        gemm_mma<2, true><<<dim3(136, 1, BB * HH), 256, SMEM_GEMM_BYTES>>>(
            q2, q2, s2, nullptr,
            KK, KK, 2 * KK, 2 * KK, 2 * TT, 0, TT,
            (long)HH * T2K, T2K, (long)HH * T2K, T2K, (long)HH * T2T, T2T, 0, 0, HH, 1, 0);

        // a[b,h] = s2 @ vT2^T fp32 : M=2048 N=256 Kd=2048
        gemm_mma<0, false><<<dim3(DD / 128, TT / 128, BB * HH), 256, SMEM_GEMM_BYTES>>>(
            s2, vT2, a, nullptr,
            TT, TT, 2 * TT, 2 * TT, DD, 0, 0,
            (long)HH * T2T, T2T, (long)DD * 2 * TT, 0, (long)HH * TD, TD, 0, 0, HH, 1, 0);

        ln_split_kernel<<<BB * HH * TT, 256>>>();

        // y2[b,t,h*K+n] = relu(a2 @ Dy2^T) * x (split, loOff=NN_)
        gemm_mma<3, false><<<dim3(KK / 128, TT / 128, BB * HH), 256, SMEM_GEMM_BYTES>>>(
            a2, Dy2, y2, x,
            DD, DD, 2 * DD, 2 * DD, 2 * NN_, KK, NN_,
            (long)HH * T2D, T2D, 0, (long)KK * 2 * DD,
            T2N, (long)KK, (long)HH * TK, TK, HH, 1, 0);

        // yE partials = y2 @ E2^T (split-K=4) : M=4096 N=256, Kd=1024/split
        gemm_mma<0, false><<<dim3(DD / 128, (BB * TT) / 128, 4), 256, SMEM_GEMM_BYTES>>>(
            y2, E2, yE, nullptr,
            NN_ / 4, NN_, 2 * NN_, 2 * NN_, DD, 0, 0,
            0, 0, 0, 0, 0, 0, 0, 0, 1, 4, 4096L * 256);

        combine_split_kernel<<<BB * TT, 256>>>(pos, l < LL - 1 ? 1 : 0);
    }

    // out = v2a @ ro2^T fp32 : M=4096 N=32000 Kd=256
    gemm_mma<0, false><<<dim3(BV / 128, (BB * TT) / 128, 1), 256, SMEM_GEMM_BYTES>>>(
        v2a, ro2, out, nullptr,
        DD, DD, 2 * DD, 2 * DD, BV, 0, 0,
        0, 0, 0, 0, 0, 0, 0, 0, 1, 1, 0);
}

// round 9
// speedup vs baseline: 1.8950x; 1.0415x over previous
#include <cuda_runtime.h>
#include <cuda_bf16.h>
#include <math.h>
#include <stdint.h>

// ---------------- problem constants ----------------
#define BV   32000
#define TT   2048
#define HH   4
#define NN_  4096
#define DD   256
#define LL   6
#define KK   1024
#define BB   2
#define EPS  1e-5f

// ---------------- device scratch (no mallocs allowed) ----------------
__device__ float          g_v   [4096L*256];
__device__ __nv_bfloat16  g_v2a [4096L*512];     // [B*T, 2D] hi|lo
__device__ __nv_bfloat16  g_vT2 [2L*256*4096];   // [B][D, 2T]
__device__ float          g_x   [8L*2048*1024];  // [B,H,T,K] fp32
__device__ __nv_bfloat16  g_q2  [8L*2048*2048];  // [B,H,T,2K]
__device__ __nv_bfloat16  g_s2  [8L*2048*4096];  // [B,H,T,2T]
__device__ float          g_a   [8L*2048*256];
__device__ __nv_bfloat16  g_a2  [8L*2048*512];
__device__ __nv_bfloat16  g_y2  [2L*2048*8192];  // [B,T,2N]
__device__ float          g_yE  [4L*4096*256];   // 4 split-K partials
__device__ __nv_bfloat16  g_Dx2 [4L*1024*512];   // [H][K, 2D]
__device__ __nv_bfloat16  g_Dy2 [4L*1024*512];
__device__ __nv_bfloat16  g_E2  [256L*8192];     // [D, 2N]
__device__ __nv_bfloat16  g_ro2 [32000L*512];    // [V, 2D]
__device__ float          g_cos [2048L*1024];
__device__ float          g_sin [2048L*1024];

// ---------------- PTX helpers (baseline ISA only: sm_80-class) ----------------
__device__ __forceinline__ uint32_t smem_u32(const void* p) {
    uint32_t a;
    asm("{ .reg .u64 t; cvta.to.shared.u64 t, %1; cvt.u32.u64 %0, t; }" : "=r"(a) : "l"(p));
    return a;
}
#define CP_ASYNC16(saddr, gaddr) \
    asm volatile("cp.async.cg.shared.global [%0], [%1], 16;" :: "r"(saddr), "l"(gaddr))
#define CP_COMMIT() asm volatile("cp.async.commit_group;" ::: "memory")
#define CP_WAIT1()  asm volatile("cp.async.wait_group 1;" ::: "memory")
#define CP_WAIT0()  asm volatile("cp.async.wait_group 0;" ::: "memory")

#define LDSM_X4(r0, r1, r2, r3, addr) \
    asm volatile("ldmatrix.sync.aligned.m8n8.x4.shared.b16 {%0,%1,%2,%3}, [%4];" \
        : "=r"(r0), "=r"(r1), "=r"(r2), "=r"(r3) : "r"(addr))

#define MMA16816(d, a, b0, b1) \
    asm volatile("mma.sync.aligned.m16n8k16.row.col.f32.bf16.bf16.f32 " \
        "{%0,%1,%2,%3}, {%4,%5,%6,%7}, {%8,%9}, {%0,%1,%2,%3};" \
        : "+f"((d)[0]), "+f"((d)[1]), "+f"((d)[2]), "+f"((d)[3]) \
        : "r"((a)[0]), "r"((a)[1]), "r"((a)[2]), "r"((a)[3]), "r"(b0), "r"(b1))

__device__ __forceinline__ void split2(float f, __nv_bfloat16& h, __nv_bfloat16& l) {
    h = __float2bfloat16(f);
    l = __float2bfloat16(f - __bfloat162float(h));
}

// swizzled smem offset: 64B rows, seg' = seg ^ ((row>>1)&3)
__device__ __forceinline__ uint32_t swz(uint32_t row, uint32_t seg) {
    return row * 64u + (((seg) ^ ((row >> 1) & 3u)) << 4);
}

// ---------------- block reduction (256 threads) ----------------
__device__ __forceinline__ float blockReduceSum256(float val) {
    __shared__ float s[8];
    __shared__ float res;
    int lane = threadIdx.x & 31, w = threadIdx.x >> 5;
    #pragma unroll
    for (int o = 16; o; o >>= 1) val += __shfl_xor_sync(0xffffffffu, val, o);
    if (lane == 0) s[w] = val;
    __syncthreads();
    if (threadIdx.x < 8) {
        float v = s[threadIdx.x];
        #pragma unroll
        for (int o = 4; o; o >>= 1) v += __shfl_xor_sync(0xffu, v, o);
        if (threadIdx.x == 0) res = v;
    }
    __syncthreads();
    float r = res;
    __syncthreads();
    return r;
}

// ---------------- elementwise kernels ----------------
__global__ void rope_table_kernel() {
    long idx = (long)blockIdx.x * blockDim.x + threadIdx.x;
    if (idx >= (long)TT * KK) return;
    int t = (int)(idx / KK);
    int k = (int)(idx % KK);
    int i = k & (KK / 2 - 1);
    float ex  = (2.0f * (float)i) / (float)KK;
    float inv = 1.0f / powf(10000.0f, ex);
    float th  = (float)t * inv;
    g_cos[idx] = cosf(th);
    g_sin[idx] = sinf(th);
}

// v = ln(emb[input]) + pos   (fused layer-0 addpos), plus hi/lo split
__global__ void embed_ln_kernel(const int* __restrict__ input_,
                                const float* __restrict__ emb,
                                const float* __restrict__ pos) {
    int row = blockIdx.x;                 // B*T
    int t = row & (TT - 1);
    int tok = input_[row];
    float x = emb[(long)tok * DD + threadIdx.x];
    float mu = blockReduceSum256(x) * (1.0f / DD);
    float d = x - mu;
    float var = blockReduceSum256(d * d) * (1.0f / DD);
    float f = d * rsqrtf(var + EPS) + pos[(long)t * DD + threadIdx.x];
    g_v[(long)row * DD + threadIdx.x] = f;
    __nv_bfloat16 h, l; split2(f, h, l);
    g_v2a[(long)row * 2 * DD + threadIdx.x] = h;
    g_v2a[(long)row * 2 * DD + DD + threadIdx.x] = l;
}

// v = ln(v + ln(sum of 4 yE partials)) [+ pos for next layer], plus split
__global__ void combine_split_kernel(const float* __restrict__ pos, int do_pos) {
    long row = blockIdx.x;                 // B*T
    const long P = 4096L * 256;
    float u = g_yE[row * DD + threadIdx.x] + g_yE[P + row * DD + threadIdx.x] +
              g_yE[2 * P + row * DD + threadIdx.x] + g_yE[3 * P + row * DD + threadIdx.x];
    float mu = blockReduceSum256(u) * (1.0f / DD);
    float d = u - mu;
    float var = blockReduceSum256(d * d) * (1.0f / DD);
    float w = g_v[row * DD + threadIdx.x] + d * rsqrtf(var + EPS);
    float mu2 = blockReduceSum256(w) * (1.0f / DD);
    float d2 = w - mu2;
    float var2 = blockReduceSum256(d2 * d2) * (1.0f / DD);
    float f = d2 * rsqrtf(var2 + EPS);
    if (do_pos) {
        int t = (int)(row & (TT - 1));
        f += pos[(long)t * DD + threadIdx.x];
    }
    g_v[row * DD + threadIdx.x] = f;
    __nv_bfloat16 h, l; split2(f, h, l);
    g_v2a[row * 2 * DD + threadIdx.x] = h;
    g_v2a[row * 2 * DD + DD + threadIdx.x] = l;
}

__global__ void ln_split_kernel() {
    long row = blockIdx.x;                 // B*H*T
    float x = g_a[row * DD + threadIdx.x];
    float mu = blockReduceSum256(x) * (1.0f / DD);
    float d = x - mu;
    float var = blockReduceSum256(d * d) * (1.0f / DD);
    float f = d * rsqrtf(var + EPS);
    __nv_bfloat16 h, l; split2(f, h, l);
    g_a2[row * 2 * DD + threadIdx.x] = h;
    g_a2[row * 2 * DD + DD + threadIdx.x] = l;
}

__global__ void rope_split_kernel() {
    long idx = (long)blockIdx.x * blockDim.x + threadIdx.x;  // B*H*T*K
    int k = (int)(idx & (KK - 1));
    long bht = idx >> 10;
    int t = (int)(bht & (TT - 1));
    float xv = g_x[idx];
    float other = (k < KK / 2) ? -g_x[idx + KK / 2] : g_x[idx - KK / 2];
    long tk = (long)t * KK + k;
    float qv = xv * g_cos[tk] + other * g_sin[tk];
    __nv_bfloat16 h, l; split2(qv, h, l);
    g_q2[bht * 2048 + k] = h;
    g_q2[bht * 2048 + KK + k] = l;
}

// X [R,C] fp32 -> Y [C, 2R] bf16 (hi cols [0,R), lo cols [R,2R))
__global__ void transpose_split_kernel(const float* __restrict__ X,
                                       __nv_bfloat16* __restrict__ Y,
                                       int R, int C, long inZ, long outZ) {
    __shared__ float tile[32][33];
    X += (long)blockIdx.z * inZ;
    Y += (long)blockIdx.z * outZ;
    int r0 = blockIdx.y * 32, c0 = blockIdx.x * 32;
    int tx = threadIdx.x, ty = threadIdx.y;   // (32,8)
    #pragma unroll
    for (int i = 0; i < 32; i += 8)
        tile[ty + i][tx] = X[(long)(r0 + ty + i) * C + c0 + tx];
    __syncthreads();
    #pragma unroll
    for (int i = 0; i < 32; i += 8) {
        float f = tile[tx][ty + i];           // X[r0+tx][c0+ty+i]
        __nv_bfloat16 h, l; split2(f, h, l);
        long orow = (long)(c0 + ty + i) * 2 * R;
        Y[orow + r0 + tx] = h;
        Y[orow + R + r0 + tx] = l;
    }
}

// ---------------- mma.sync GEMM (HMMA path, fused 3-pass) ----------------
// C[M,N] = A2[M,2K] x B2[N,2K]^T with bf16 hi/lo split.
// Fused: per 32-wide K chunk, load Ah, Al, Bh, Bl tiles once; do
// AhBh + AhBl + AlBh. cp.async issues for chunk c+2 are emitted between
// the first and second MMA pass (tensor-pipe shadow).
// CTA tile 128x128, 3-stage cp.async pipeline (stage = 4 x 8192B = 32KB),
// XOR-swizzled 64B smem rows, single __syncthreads per chunk.
// 8 warps 2(m) x 4(n), warp tile 64x32.
// EPI: 0=fp32, 1=relu fp32, 2=split bf16 (hi at col, lo at col+loOff),
//      3=relu*G split bf16
// SYM: A==B, M==N==2048; blockIdx.x enumerates 136 upper-tri block pairs,
//      mirror tile written via smem transpose.
// Split-K: nsplit partials, sp = blockIdx.z % nsplit.
#define OPER_BYTES 8192                    // 128 rows x 64B
#define STAGE_BYTES (4 * OPER_BYTES)       // 32768: Ah|Al|Bh|Bl
#define SMEM_GEMM_BYTES (3 * STAGE_BYTES)  // 98304

template<int EPI, bool SYM>
__global__ void __launch_bounds__(256, 2)
gemm_mma(const __nv_bfloat16* __restrict__ A, const __nv_bfloat16* __restrict__ B,
         void* __restrict__ Cv, const float* __restrict__ G,
         int Kd, int KdLo, int lda, int ldb, int ldc, int ldgt, int loOff,
         long sAb, long sAh, long sBb, long sBh, long sCb, long sCh,
         long sGb, long sGh, int Hdim, int nsplit, long sSplitC)
{
    extern __shared__ char dsm[];
    uint32_t sbase = smem_u32(dsm);

    int tid = threadIdx.x;
    int lane = tid & 31;
    int wid = tid >> 5;
    int wm = wid >> 2;        // 0..1
    int wn = wid & 3;         // 0..3

    int zz = blockIdx.z;
    int sp = 0, z = zz;
    if (nsplit > 1) { sp = zz % nsplit; z = zz / nsplit; }
    int bb = z / Hdim, hh = z - bb * Hdim;
    A += bb * sAb + hh * sAh;
    B += bb * sBb + hh * sBh;
    long cOff = bb * sCb + hh * sCh + sp * sSplitC;
    if (EPI == 3) G += bb * sGb + hh * sGh;

    int m0, n0, diag = 0;
    if (SYM) {
        int L = blockIdx.x, ii = 0;
        while (L >= 16 - ii) { L -= 16 - ii; ii++; }
        m0 = ii * 128; n0 = (ii + L) * 128;
        diag = (L == 0);
    } else {
        m0 = blockIdx.y * 128;
        n0 = blockIdx.x * 128;
    }

    const int KC = Kd >> 5;       // 32-wide chunks (one fused pass each)
    const int spK = sp * Kd;

    int lrow = tid >> 2;          // 0..63
    int lseg = tid & 3;

    auto issue = [&](int cc) {
        int koff = spK + (cc << 5);
        uint32_t st = sbase + (cc % 3) * STAGE_BYTES;
        #pragma unroll
        for (int i = 0; i < 2; i++) {
            uint32_t row = lrow + i * 64;
            uint32_t so = swz(row, (uint32_t)lseg);
            long go = lseg * 8;
            const __nv_bfloat16* ga = A + (long)(m0 + row) * lda + koff + go;
            const __nv_bfloat16* gb = B + (long)(n0 + row) * ldb + koff + go;
            CP_ASYNC16(st + so,                  ga);           // A hi
            CP_ASYNC16(st + OPER_BYTES + so,     ga + KdLo);    // A lo
            CP_ASYNC16(st + 2 * OPER_BYTES + so, gb);           // B hi
            CP_ASYNC16(st + 3 * OPER_BYTES + so, gb + KdLo);    // B lo
        }
    };

    float acc[4][4][4];
    #pragma unroll
    for (int i = 0; i < 4; i++)
        #pragma unroll
        for (int j = 0; j < 4; j++)
            #pragma unroll
            for (int r = 0; r < 4; r++) acc[i][j][r] = 0.0f;

    issue(0); CP_COMMIT();
    issue(1); CP_COMMIT();

    int rsel = lane & 15;
    int hi16 = lane >> 4;         // 0 or 1: second 16B seg of the k16 block

    for (int c = 0; c < KC; c++) {
        CP_WAIT1();              // chunk c data complete
        __syncthreads();         // copies visible to all; compute c-1 done

        uint32_t sah = sbase + (c % 3) * STAGE_BYTES;
        uint32_t sal = sah + OPER_BYTES;
        uint32_t sbh = sah + 2 * OPER_BYTES;
        uint32_t sbl = sah + 3 * OPER_BYTES;

        #pragma unroll
        for (int ks = 0; ks < 2; ks++) {
            uint32_t segb = (uint32_t)(ks * 2 + hi16);
            uint32_t ar[4][4], brh[2][4], brl[2][4];
            // B frags (hi+lo) + A-hi frags up front
            #pragma unroll
            for (int n2 = 0; n2 < 2; n2++) {
                uint32_t row = (uint32_t)(wn * 32 + n2 * 16 + rsel);
                LDSM_X4(brh[n2][0], brh[n2][1], brh[n2][2], brh[n2][3], sbh + swz(row, segb));
            }
            #pragma unroll
            for (int n2 = 0; n2 < 2; n2++) {
                uint32_t row = (uint32_t)(wn * 32 + n2 * 16 + rsel);
                LDSM_X4(brl[n2][0], brl[n2][1], brl[n2][2], brl[n2][3], sbl + swz(row, segb));
            }
            #pragma unroll
            for (int mt = 0; mt < 4; mt++) {
                uint32_t row = (uint32_t)(wm * 64 + mt * 16 + rsel);
                LDSM_X4(ar[mt][0], ar[mt][1], ar[mt][2], ar[mt][3], sah + swz(row, segb));
            }
            // pass 1: Ah x Bh
            #pragma unroll
            for (int mt = 0; mt < 4; mt++)
                #pragma unroll
                for (int nt = 0; nt < 4; nt++) {
                    int n2 = nt >> 1, j = nt & 1;
                    MMA16816(acc[mt][nt], ar[mt], brh[n2][j], brh[n2][2 + j]);
                }
            // hide next-chunk copy issue under the tensor-pipe shadow
            if (ks == 0) {
                if (c + 2 < KC) issue(c + 2);
                CP_COMMIT();
            }
            // pass 2: Ah x Bl
            #pragma unroll
            for (int mt = 0; mt < 4; mt++)
                #pragma unroll
                for (int nt = 0; nt < 4; nt++) {
                    int n2 = nt >> 1, j = nt & 1;
                    MMA16816(acc[mt][nt], ar[mt], brl[n2][j], brl[n2][2 + j]);
                }
            // pass 3: Al x Bh (reload A frags from lo tile)
            #pragma unroll
            for (int mt = 0; mt < 4; mt++) {
                uint32_t row = (uint32_t)(wm * 64 + mt * 16 + rsel);
                LDSM_X4(ar[mt][0], ar[mt][1], ar[mt][2], ar[mt][3], sal + swz(row, segb));
            }
            #pragma unroll
            for (int mt = 0; mt < 4; mt++)
                #pragma unroll
                for (int nt = 0; nt < 4; nt++) {
                    int n2 = nt >> 1, j = nt & 1;
                    MMA16816(acc[mt][nt], ar[mt], brh[n2][j], brh[n2][2 + j]);
                }
        }
    }

    // ---------------- epilogue ----------------
    int g = lane >> 2, tg = lane & 3;
    float* Cf = (float*)Cv;
    __nv_bfloat16* Cb = (__nv_bfloat16*)Cv;

    #pragma unroll
    for (int mt = 0; mt < 4; mt++) {
        #pragma unroll
        for (int half = 0; half < 2; half++) {
            long row = m0 + wm * 64 + mt * 16 + g + half * 8;
            #pragma unroll
            for (int nt = 0; nt < 4; nt++) {
                int co = n0 + wn * 32 + nt * 8 + tg * 2;
                float f0 = acc[mt][nt][half * 2 + 0];
                float f1 = acc[mt][nt][half * 2 + 1];
                if (EPI == 0) {
                    *reinterpret_cast<float2*>(&Cf[cOff + row * ldc + co]) =
                        make_float2(f0, f1);
                } else if (EPI == 1) {
                    *reinterpret_cast<float2*>(&Cf[cOff + row * ldc + co]) =
                        make_float2(fmaxf(f0, 0.f), fmaxf(f1, 0.f));
                } else {
                    if (EPI == 3) {
                        float2 gv = *reinterpret_cast<const float2*>(
                            &G[row * (long)ldgt + co]);
                        f0 = fmaxf(f0, 0.f) * gv.x;
                        f1 = fmaxf(f1, 0.f) * gv.y;
                    }
                    __nv_bfloat16 h0, l0, h1, l1;
                    split2(f0, h0, l0);
                    split2(f1, h1, l1);
                    uint32_t hp = (uint32_t)*(uint16_t*)&h0 |
                                  ((uint32_t)*(uint16_t*)&h1 << 16);
                    uint32_t lp = (uint32_t)*(uint16_t*)&l0 |
                                  ((uint32_t)*(uint16_t*)&l1 << 16);
                    *reinterpret_cast<uint32_t*>(&Cb[cOff + row * ldc + co]) = hp;
                    *reinterpret_cast<uint32_t*>(&Cb[cOff + row * ldc + co + loOff]) = lp;
                }
            }
        }
    }

    // mirror tile C[n,m] = C[m,n] via smem transpose (coalesced stores)
    if (SYM && !diag) {
        CP_WAIT0();
        __syncthreads();
        __nv_bfloat16* sm = (__nv_bfloat16*)dsm;   // 128 x 144 bf16
        #pragma unroll
        for (int ph = 0; ph < 2; ph++) {
            #pragma unroll
            for (int mt = 0; mt < 4; mt++)
                #pragma unroll
                for (int half = 0; half < 2; half++) {
                    int r = wm * 64 + mt * 16 + g + half * 8;
                    #pragma unroll
                    for (int nt = 0; nt < 4; nt++) {
                        int cc = wn * 32 + nt * 8 + tg * 2;
                        float f0 = acc[mt][nt][half * 2 + 0];
                        float f1 = acc[mt][nt][half * 2 + 1];
                        __nv_bfloat16 h0, l0, h1, l1;
                        split2(f0, h0, l0);
                        split2(f1, h1, l1);
                        sm[cc * 144 + r]       = ph ? l0 : h0;
                        sm[(cc + 1) * 144 + r] = ph ? l1 : h1;
                    }
                }
            __syncthreads();
            int cc2 = tid >> 1, seg = (tid & 1) * 64;
            const uint4* src = (const uint4*)(sm + cc2 * 144 + seg);
            uint4* dst = (uint4*)(&Cb[cOff + (long)(n0 + cc2) * ldc + m0 + seg +
                                      (ph ? loOff : 0)]);
            #pragma unroll
            for (int u = 0; u < 8; u++) dst[u] = src[u];
            __syncthreads();
        }
    }
}

// ---------------- host launch ----------------
extern "C" void kernel_launch(void* const* d_in, const int* in_sizes, int n_in,
                              void* d_out, int out_size) {
    const int*   input_  = (const int*)d_in[0];
    const float* emb     = (const float*)d_in[1];
    const float* pos     = (const float*)d_in[2];
    const float* Dx      = (const float*)d_in[3];
    const float* Dy      = (const float*)d_in[4];
    const float* E       = (const float*)d_in[5];
    const float* readout = (const float*)d_in[6];
    float* out = (float*)d_out;

    cudaFuncSetAttribute(gemm_mma<0, false>, cudaFuncAttributeMaxDynamicSharedMemorySize, SMEM_GEMM_BYTES);
    cudaFuncSetAttribute(gemm_mma<1, false>, cudaFuncAttributeMaxDynamicSharedMemorySize, SMEM_GEMM_BYTES);
    cudaFuncSetAttribute(gemm_mma<2, true>,  cudaFuncAttributeMaxDynamicSharedMemorySize, SMEM_GEMM_BYTES);
    cudaFuncSetAttribute(gemm_mma<3, false>, cudaFuncAttributeMaxDynamicSharedMemorySize, SMEM_GEMM_BYTES);

    float *v, *x, *a, *yE;
    __nv_bfloat16 *v2a, *vT2, *q2, *s2, *a2, *y2, *Dx2, *Dy2, *E2, *ro2;
    cudaGetSymbolAddress((void**)&v,   g_v);
    cudaGetSymbolAddress((void**)&v2a, g_v2a);
    cudaGetSymbolAddress((void**)&vT2, g_vT2);
    cudaGetSymbolAddress((void**)&x,   g_x);
    cudaGetSymbolAddress((void**)&q2,  g_q2);
    cudaGetSymbolAddress((void**)&s2,  g_s2);
    cudaGetSymbolAddress((void**)&a,   g_a);
    cudaGetSymbolAddress((void**)&a2,  g_a2);
    cudaGetSymbolAddress((void**)&y2,  g_y2);
    cudaGetSymbolAddress((void**)&yE,  g_yE);
    cudaGetSymbolAddress((void**)&Dx2, g_Dx2);
    cudaGetSymbolAddress((void**)&Dy2, g_Dy2);
    cudaGetSymbolAddress((void**)&E2,  g_E2);
    cudaGetSymbolAddress((void**)&ro2, g_ro2);

    dim3 tb(32, 8);

    rope_table_kernel<<<(TT * KK + 255) / 256, 256>>>();
    embed_ln_kernel<<<BB * TT, 256>>>(input_, emb, pos);
    transpose_split_kernel<<<dim3(KK / 32, DD / 32, HH), tb>>>(Dx, Dx2, DD, KK, (long)DD * KK, (long)KK * 2 * DD);
    transpose_split_kernel<<<dim3(KK / 32, DD / 32, HH), tb>>>(Dy, Dy2, DD, KK, (long)DD * KK, (long)KK * 2 * DD);
    transpose_split_kernel<<<dim3(DD / 32, NN_ / 32, 1), tb>>>(E, E2, NN_, DD, 0, 0);
    transpose_split_kernel<<<dim3(BV / 32, DD / 32, 1), tb>>>(readout, ro2, DD, BV, 0, 0);

    const long TK  = (long)TT * KK;
    const long T2D = (long)TT * 2 * DD;
    const long T2K = (long)TT * 2 * KK;
    const long T2T = (long)TT * 2 * TT;
    const long T2N = (long)TT * 2 * NN_;
    const long TD  = (long)TT * DD;

    for (int l = 0; l < LL; l++) {
        transpose_split_kernel<<<dim3(DD / 32, TT / 32, BB), tb>>>(v, vT2, TT, DD, TD, (long)DD * 2 * TT);

        // x[b,h] = relu(v2a_b @ Dx2_h^T) fp32 : M=2048 N=1024 Kd=256
        gemm_mma<1, false><<<dim3(KK / 128, TT / 128, BB * HH), 256, SMEM_GEMM_BYTES>>>(
            v2a, Dx2, x, nullptr,
            DD, DD, 2 * DD, 2 * DD, KK, 0, 0,
            T2D, 0, 0, (long)KK * 2 * DD, (long)HH * TK, TK, 0, 0, HH, 1, 0);

        rope_split_kernel<<<(int)((long)BB * HH * TT * KK / 256), 256>>>();

        // s2[b,h] = q2 @ q2^T (split out, SYMMETRIC) : 136 upper-tri blocks
        gemm_mma<2, true><<<dim3(136, 1, BB * HH), 256, SMEM_GEMM_BYTES>>>(
            q2, q2, s2, nullptr,
            KK, KK, 2 * KK, 2 * KK, 2 * TT, 0, TT,
            (long)HH * T2K, T2K, (long)HH * T2K, T2K, (long)HH * T2T, T2T, 0, 0, HH, 1, 0);

        // a[b,h] = s2 @ vT2^T fp32 : M=2048 N=256 Kd=2048
        gemm_mma<0, false><<<dim3(DD / 128, TT / 128, BB * HH), 256, SMEM_GEMM_BYTES>>>(
            s2, vT2, a, nullptr,
            TT, TT, 2 * TT, 2 * TT, DD, 0, 0,
            (long)HH * T2T, T2T, (long)DD * 2 * TT, 0, (long)HH * TD, TD, 0, 0, HH, 1, 0);

        ln_split_kernel<<<BB * HH * TT, 256>>>();

        // y2[b,t,h*K+n] = relu(a2 @ Dy2^T) * x (split, loOff=NN_)
        gemm_mma<3, false><<<dim3(KK / 128, TT / 128, BB * HH), 256, SMEM_GEMM_BYTES>>>(
            a2, Dy2, y2, x,
            DD, DD, 2 * DD, 2 * DD, 2 * NN_, KK, NN_,
            (long)HH * T2D, T2D, 0, (long)KK * 2 * DD,
            T2N, (long)KK, (long)HH * TK, TK, HH, 1, 0);

        // yE partials = y2 @ E2^T (split-K=4) : M=4096 N=256, Kd=1024/split
        gemm_mma<0, false><<<dim3(DD / 128, (BB * TT) / 128, 4), 256, SMEM_GEMM_BYTES>>>(
            y2, E2, yE, nullptr,
            NN_ / 4, NN_, 2 * NN_, 2 * NN_, DD, 0, 0,
            0, 0, 0, 0, 0, 0, 0, 0, 1, 4, 4096L * 256);

        combine_split_kernel<<<BB * TT, 256>>>(pos, l < LL - 1 ? 1 : 0);
    }

    // out = v2a @ ro2^T fp32 : M=4096 N=32000 Kd=256
    gemm_mma<0, false><<<dim3(BV / 128, (BB * TT) / 128, 1), 256, SMEM_GEMM_BYTES>>>(
        v2a, ro2, out, nullptr,
        DD, DD, 2 * DD, 2 * DD, BV, 0, 0,
        0, 0, 0, 0, 0, 0, 0, 0, 1, 1, 0);
}

// round 10
// speedup vs baseline: 1.9541x; 1.0312x over previous
#include <cuda_runtime.h>
#include <cuda_bf16.h>
#include <math.h>
#include <stdint.h>

// ---------------- problem constants ----------------
#define BV   32000
#define TT   2048
#define HH   4
#define NN_  4096
#define DD   256
#define LL   6
#define KK   1024
#define BB   2
#define EPS  1e-5f

// ---------------- device scratch (no mallocs allowed) ----------------
__device__ float          g_v   [4096L*256];
__device__ __nv_bfloat16  g_v2a [4096L*512];     // [B*T, 2D] hi|lo
__device__ __nv_bfloat16  g_vT2 [2L*256*4096];   // [B][D, 2T]
__device__ float          g_x   [8L*2048*1024];  // [B,H,T,K] fp32 (PERMUTED cols)
__device__ __nv_bfloat16  g_q2  [8L*2048*2048];  // [B,H,T,2K]   (PERMUTED cols)
__device__ __nv_bfloat16  g_s2  [8L*2048*4096];  // [B,H,T,2T]
__device__ float          g_a   [8L*2048*256];
__device__ __nv_bfloat16  g_a2  [8L*2048*512];
__device__ __nv_bfloat16  g_y2  [2L*2048*8192];  // [B,T,2N]     (PERMUTED cols/head)
__device__ float          g_yE  [4L*4096*256];   // 4 split-K partials
__device__ __nv_bfloat16  g_Dx2 [4L*1024*512];   // [H][K, 2D]   (PERMUTED rows)
__device__ __nv_bfloat16  g_Dy2 [4L*1024*512];   // (PERMUTED rows)
__device__ __nv_bfloat16  g_E2  [256L*8192];     // [D, 2N]      (PERMUTED cols/head)
__device__ __nv_bfloat16  g_ro2 [32000L*512];    // [V, 2D]
__device__ float          g_cos [2048L*512];     // [T, 512]
__device__ float          g_sin [2048L*512];

// per-head column permutation: k<512 -> 2k ; k>=512 -> 2k-1023
__host__ __device__ __forceinline__ int permk(int k) {
    return (k < 512) ? (2 * k) : (2 * k - 1023);
}

// ---------------- PTX helpers (baseline ISA only: sm_80-class) ----------------
__device__ __forceinline__ uint32_t smem_u32(const void* p) {
    uint32_t a;
    asm("{ .reg .u64 t; cvta.to.shared.u64 t, %1; cvt.u32.u64 %0, t; }" : "=r"(a) : "l"(p));
    return a;
}
#define CP_ASYNC16(saddr, gaddr) \
    asm volatile("cp.async.cg.shared.global [%0], [%1], 16;" :: "r"(saddr), "l"(gaddr))
#define CP_COMMIT() asm volatile("cp.async.commit_group;" ::: "memory")
#define CP_WAIT1()  asm volatile("cp.async.wait_group 1;" ::: "memory")
#define CP_WAIT0()  asm volatile("cp.async.wait_group 0;" ::: "memory")

#define LDSM_X4(r0, r1, r2, r3, addr) \
    asm volatile("ldmatrix.sync.aligned.m8n8.x4.shared.b16 {%0,%1,%2,%3}, [%4];" \
        : "=r"(r0), "=r"(r1), "=r"(r2), "=r"(r3) : "r"(addr))

#define MMA16816(d, a, b0, b1) \
    asm volatile("mma.sync.aligned.m16n8k16.row.col.f32.bf16.bf16.f32 " \
        "{%0,%1,%2,%3}, {%4,%5,%6,%7}, {%8,%9}, {%0,%1,%2,%3};" \
        : "+f"((d)[0]), "+f"((d)[1]), "+f"((d)[2]), "+f"((d)[3]) \
        : "r"((a)[0]), "r"((a)[1]), "r"((a)[2]), "r"((a)[3]), "r"(b0), "r"(b1))

__device__ __forceinline__ void split2(float f, __nv_bfloat16& h, __nv_bfloat16& l) {
    h = __float2bfloat16(f);
    l = __float2bfloat16(f - __bfloat162float(h));
}

// swizzled smem offset: 64B rows, seg' = seg ^ ((row>>1)&3)
__device__ __forceinline__ uint32_t swz(uint32_t row, uint32_t seg) {
    return row * 64u + (((seg) ^ ((row >> 1) & 3u)) << 4);
}

// ---------------- block reduction (256 threads) ----------------
__device__ __forceinline__ float blockReduceSum256(float val) {
    __shared__ float s[8];
    __shared__ float res;
    int lane = threadIdx.x & 31, w = threadIdx.x >> 5;
    #pragma unroll
    for (int o = 16; o; o >>= 1) val += __shfl_xor_sync(0xffffffffu, val, o);
    if (lane == 0) s[w] = val;
    __syncthreads();
    if (threadIdx.x < 8) {
        float v = s[threadIdx.x];
        #pragma unroll
        for (int o = 4; o; o >>= 1) v += __shfl_xor_sync(0xffu, v, o);
        if (threadIdx.x == 0) res = v;
    }
    __syncthreads();
    float r = res;
    __syncthreads();
    return r;
}

// ---------------- elementwise kernels ----------------
// [T, 512] tables (cos[t,i+512]==cos[t,i], so only first half stored)
__global__ void rope_table_kernel() {
    long idx = (long)blockIdx.x * blockDim.x + threadIdx.x;
    if (idx >= (long)TT * 512) return;
    int t = (int)(idx >> 9);
    int i = (int)(idx & 511);
    float ex  = (2.0f * (float)i) / (float)KK;
    float inv = 1.0f / powf(10000.0f, ex);
    float th  = (float)t * inv;
    g_cos[idx] = cosf(th);
    g_sin[idx] = sinf(th);
}

// v = ln(emb[input]) + pos   (fused layer-0 addpos), plus hi/lo split
__global__ void embed_ln_kernel(const int* __restrict__ input_,
                                const float* __restrict__ emb,
                                const float* __restrict__ pos) {
    int row = blockIdx.x;                 // B*T
    int t = row & (TT - 1);
    int tok = input_[row];
    float x = emb[(long)tok * DD + threadIdx.x];
    float mu = blockReduceSum256(x) * (1.0f / DD);
    float d = x - mu;
    float var = blockReduceSum256(d * d) * (1.0f / DD);
    float f = d * rsqrtf(var + EPS) + pos[(long)t * DD + threadIdx.x];
    g_v[(long)row * DD + threadIdx.x] = f;
    __nv_bfloat16 h, l; split2(f, h, l);
    g_v2a[(long)row * 2 * DD + threadIdx.x] = h;
    g_v2a[(long)row * 2 * DD + DD + threadIdx.x] = l;
}

// v = ln(v + ln(sum of 4 yE partials)) [+ pos for next layer], plus split
__global__ void combine_split_kernel(const float* __restrict__ pos, int do_pos) {
    long row = blockIdx.x;                 // B*T
    const long P = 4096L * 256;
    float u = g_yE[row * DD + threadIdx.x] + g_yE[P + row * DD + threadIdx.x] +
              g_yE[2 * P + row * DD + threadIdx.x] + g_yE[3 * P + row * DD + threadIdx.x];
    float mu = blockReduceSum256(u) * (1.0f / DD);
    float d = u - mu;
    float var = blockReduceSum256(d * d) * (1.0f / DD);
    float w = g_v[row * DD + threadIdx.x] + d * rsqrtf(var + EPS);
    float mu2 = blockReduceSum256(w) * (1.0f / DD);
    float d2 = w - mu2;
    float var2 = blockReduceSum256(d2 * d2) * (1.0f / DD);
    float f = d2 * rsqrtf(var2 + EPS);
    if (do_pos) {
        int t = (int)(row & (TT - 1));
        f += pos[(long)t * DD + threadIdx.x];
    }
    g_v[row * DD + threadIdx.x] = f;
    __nv_bfloat16 h, l; split2(f, h, l);
    g_v2a[row * 2 * DD + threadIdx.x] = h;
    g_v2a[row * 2 * DD + DD + threadIdx.x] = l;
}

__global__ void ln_split_kernel() {
    long row = blockIdx.x;                 // B*H*T
    float x = g_a[row * DD + threadIdx.x];
    float mu = blockReduceSum256(x) * (1.0f / DD);
    float d = x - mu;
    float var = blockReduceSum256(d * d) * (1.0f / DD);
    float f = d * rsqrtf(var + EPS);
    __nv_bfloat16 h, l; split2(f, h, l);
    g_a2[row * 2 * DD + threadIdx.x] = h;
    g_a2[row * 2 * DD + DD + threadIdx.x] = l;
}

// X [R,C] fp32 -> Y [C, 2R] bf16 (hi cols [0,R), lo cols [R,2R))
// PERM: 0 = none; 1 = permute OUT-ROW index (X column) per 1024-block;
//       2 = permute OUT-COL index (X row) per 1024-block.
__global__ void transpose_split_kernel(const float* __restrict__ X,
                                       __nv_bfloat16* __restrict__ Y,
                                       int R, int C, long inZ, long outZ, int PERM) {
    __shared__ float tile[32][33];
    X += (long)blockIdx.z * inZ;
    Y += (long)blockIdx.z * outZ;
    int r0 = blockIdx.y * 32, c0 = blockIdx.x * 32;
    int tx = threadIdx.x, ty = threadIdx.y;   // (32,8)
    #pragma unroll
    for (int i = 0; i < 32; i += 8)
        tile[ty + i][tx] = X[(long)(r0 + ty + i) * C + c0 + tx];
    __syncthreads();
    #pragma unroll
    for (int i = 0; i < 32; i += 8) {
        float f = tile[tx][ty + i];           // X[r0+tx][c0+ty+i]
        __nv_bfloat16 h, l; split2(f, h, l);
        int orowi = c0 + ty + i;
        int ocol  = r0 + tx;
        if (PERM == 1) {
            int blk = orowi & ~1023;
            orowi = blk + permk(orowi & 1023);
        } else if (PERM == 2) {
            int blk = ocol & ~1023;
            ocol = blk + permk(ocol & 1023);
        }
        long orow = (long)orowi * 2 * R;
        Y[orow + ocol] = h;
        Y[orow + R + ocol] = l;
    }
}

// ---------------- mma.sync GEMM (HMMA path, fused 3-pass) ----------------
// C[M,N] = A2[M,2K] x B2[N,2K]^T with bf16 hi/lo split.
// Fused: per 32-wide K chunk, load Ah, Al, Bh, Bl tiles once; do
// AhBh + AhBl + AlBh. cp.async issues for chunk c+2 are emitted between
// the first and second MMA pass (tensor-pipe shadow).
// CTA tile 128x128, 3-stage cp.async pipeline, XOR-swizzled 64B smem rows,
// single __syncthreads per chunk. 8 warps 2(m) x 4(n), warp tile 64x32.
// EPI: 0=fp32, 2=split bf16, 3=relu*G split bf16,
//      4=relu fp32 + fused RoPE into Q (split bf16, paired-permuted cols)
// SYM: A==B symmetric tiles; Split-K: nsplit partials.
#define OPER_BYTES 8192                    // 128 rows x 64B
#define STAGE_BYTES (4 * OPER_BYTES)       // 32768: Ah|Al|Bh|Bl
#define SMEM_GEMM_BYTES (3 * STAGE_BYTES)  // 98304

template<int EPI, bool SYM>
__global__ void __launch_bounds__(256, 2)
gemm_mma(const __nv_bfloat16* __restrict__ A, const __nv_bfloat16* __restrict__ B,
         void* __restrict__ Cv, const float* __restrict__ G,
         int Kd, int KdLo, int lda, int ldb, int ldc, int ldgt, int loOff,
         long sAb, long sAh, long sBb, long sBh, long sCb, long sCh,
         long sGb, long sGh, int Hdim, int nsplit, long sSplitC,
         __nv_bfloat16* __restrict__ Q, long sQb, long sQh,
         const float* __restrict__ CT, const float* __restrict__ ST)
{
    extern __shared__ char dsm[];
    uint32_t sbase = smem_u32(dsm);

    int tid = threadIdx.x;
    int lane = tid & 31;
    int wid = tid >> 5;
    int wm = wid >> 2;        // 0..1
    int wn = wid & 3;         // 0..3

    int zz = blockIdx.z;
    int sp = 0, z = zz;
    if (nsplit > 1) { sp = zz % nsplit; z = zz / nsplit; }
    int bb = z / Hdim, hh = z - bb * Hdim;
    A += bb * sAb + hh * sAh;
    B += bb * sBb + hh * sBh;
    long cOff = bb * sCb + hh * sCh + sp * sSplitC;
    if (EPI == 3) G += bb * sGb + hh * sGh;
    long qOff = 0;
    if (EPI == 4) qOff = bb * sQb + hh * sQh;

    int m0, n0, diag = 0;
    if (SYM) {
        int L = blockIdx.x, ii = 0;
        while (L >= 16 - ii) { L -= 16 - ii; ii++; }
        m0 = ii * 128; n0 = (ii + L) * 128;
        diag = (L == 0);
    } else {
        m0 = blockIdx.y * 128;
        n0 = blockIdx.x * 128;
    }

    const int KC = Kd >> 5;       // 32-wide chunks (one fused pass each)
    const int spK = sp * Kd;

    int lrow = tid >> 2;          // 0..63
    int lseg = tid & 3;

    auto issue = [&](int cc) {
        int koff = spK + (cc << 5);
        uint32_t st = sbase + (cc % 3) * STAGE_BYTES;
        #pragma unroll
        for (int i = 0; i < 2; i++) {
            uint32_t row = lrow + i * 64;
            uint32_t so = swz(row, (uint32_t)lseg);
            long go = lseg * 8;
            const __nv_bfloat16* ga = A + (long)(m0 + row) * lda + koff + go;
            const __nv_bfloat16* gb = B + (long)(n0 + row) * ldb + koff + go;
            CP_ASYNC16(st + so,                  ga);           // A hi
            CP_ASYNC16(st + OPER_BYTES + so,     ga + KdLo);    // A lo
            CP_ASYNC16(st + 2 * OPER_BYTES + so, gb);           // B hi
            CP_ASYNC16(st + 3 * OPER_BYTES + so, gb + KdLo);    // B lo
        }
    };

    float acc[4][4][4];
    #pragma unroll
    for (int i = 0; i < 4; i++)
        #pragma unroll
        for (int j = 0; j < 4; j++)
            #pragma unroll
            for (int r = 0; r < 4; r++) acc[i][j][r] = 0.0f;

    issue(0); CP_COMMIT();
    issue(1); CP_COMMIT();

    int rsel = lane & 15;
    int hi16 = lane >> 4;         // 0 or 1: second 16B seg of the k16 block

    for (int c = 0; c < KC; c++) {
        CP_WAIT1();              // chunk c data complete
        __syncthreads();         // copies visible to all; compute c-1 done

        uint32_t sah = sbase + (c % 3) * STAGE_BYTES;
        uint32_t sal = sah + OPER_BYTES;
        uint32_t sbh = sah + 2 * OPER_BYTES;
        uint32_t sbl = sah + 3 * OPER_BYTES;

        #pragma unroll
        for (int ks = 0; ks < 2; ks++) {
            uint32_t segb = (uint32_t)(ks * 2 + hi16);
            uint32_t ar[4][4], brh[2][4], brl[2][4];
            #pragma unroll
            for (int n2 = 0; n2 < 2; n2++) {
                uint32_t row = (uint32_t)(wn * 32 + n2 * 16 + rsel);
                LDSM_X4(brh[n2][0], brh[n2][1], brh[n2][2], brh[n2][3], sbh + swz(row, segb));
            }
            #pragma unroll
            for (int n2 = 0; n2 < 2; n2++) {
                uint32_t row = (uint32_t)(wn * 32 + n2 * 16 + rsel);
                LDSM_X4(brl[n2][0], brl[n2][1], brl[n2][2], brl[n2][3], sbl + swz(row, segb));
            }
            #pragma unroll
            for (int mt = 0; mt < 4; mt++) {
                uint32_t row = (uint32_t)(wm * 64 + mt * 16 + rsel);
                LDSM_X4(ar[mt][0], ar[mt][1], ar[mt][2], ar[mt][3], sah + swz(row, segb));
            }
            // pass 1: Ah x Bh
            #pragma unroll
            for (int mt = 0; mt < 4; mt++)
                #pragma unroll
                for (int nt = 0; nt < 4; nt++) {
                    int n2 = nt >> 1, j = nt & 1;
                    MMA16816(acc[mt][nt], ar[mt], brh[n2][j], brh[n2][2 + j]);
                }
            if (ks == 0) {
                if (c + 2 < KC) issue(c + 2);
                CP_COMMIT();
            }
            // pass 2: Ah x Bl
            #pragma unroll
            for (int mt = 0; mt < 4; mt++)
                #pragma unroll
                for (int nt = 0; nt < 4; nt++) {
                    int n2 = nt >> 1, j = nt & 1;
                    MMA16816(acc[mt][nt], ar[mt], brl[n2][j], brl[n2][2 + j]);
                }
            // pass 3: Al x Bh (reload A frags from lo tile)
            #pragma unroll
            for (int mt = 0; mt < 4; mt++) {
                uint32_t row = (uint32_t)(wm * 64 + mt * 16 + rsel);
                LDSM_X4(ar[mt][0], ar[mt][1], ar[mt][2], ar[mt][3], sal + swz(row, segb));
            }
            #pragma unroll
            for (int mt = 0; mt < 4; mt++)
                #pragma unroll
                for (int nt = 0; nt < 4; nt++) {
                    int n2 = nt >> 1, j = nt & 1;
                    MMA16816(acc[mt][nt], ar[mt], brh[n2][j], brh[n2][2 + j]);
                }
        }
    }

    // ---------------- epilogue ----------------
    int g = lane >> 2, tg = lane & 3;
    float* Cf = (float*)Cv;
    __nv_bfloat16* Cb = (__nv_bfloat16*)Cv;

    #pragma unroll
    for (int mt = 0; mt < 4; mt++) {
        #pragma unroll
        for (int half = 0; half < 2; half++) {
            long row = m0 + wm * 64 + mt * 16 + g + half * 8;
            #pragma unroll
            for (int nt = 0; nt < 4; nt++) {
                int co = n0 + wn * 32 + nt * 8 + tg * 2;
                float f0 = acc[mt][nt][half * 2 + 0];
                float f1 = acc[mt][nt][half * 2 + 1];
                if (EPI == 0) {
                    *reinterpret_cast<float2*>(&Cf[cOff + row * ldc + co]) =
                        make_float2(f0, f1);
                } else if (EPI == 4) {
                    f0 = fmaxf(f0, 0.f);
                    f1 = fmaxf(f1, 0.f);
                    // gate copy (permuted x)
                    *reinterpret_cast<float2*>(&Cf[cOff + row * ldc + co]) =
                        make_float2(f0, f1);
                    // RoPE: pair (co, co+1) = original (i, i+512), i = co/2
                    int i = co >> 1;
                    long tb = row * 512 + i;   // row == t
                    float cv = CT[tb], sv = ST[tb];
                    float qa = f0 * cv - f1 * sv;
                    float qb = f1 * cv + f0 * sv;
                    __nv_bfloat16 h0, l0, h1, l1;
                    split2(qa, h0, l0);
                    split2(qb, h1, l1);
                    uint32_t hp = (uint32_t)*(uint16_t*)&h0 |
                                  ((uint32_t)*(uint16_t*)&h1 << 16);
                    uint32_t lp = (uint32_t)*(uint16_t*)&l0 |
                                  ((uint32_t)*(uint16_t*)&l1 << 16);
                    *reinterpret_cast<uint32_t*>(&Q[qOff + row * 2048 + co]) = hp;
                    *reinterpret_cast<uint32_t*>(&Q[qOff + row * 2048 + co + KK]) = lp;
                } else {
                    if (EPI == 3) {
                        float2 gv = *reinterpret_cast<const float2*>(
                            &G[row * (long)ldgt + co]);
                        f0 = fmaxf(f0, 0.f) * gv.x;
                        f1 = fmaxf(f1, 0.f) * gv.y;
                    }
                    __nv_bfloat16 h0, l0, h1, l1;
                    split2(f0, h0, l0);
                    split2(f1, h1, l1);
                    uint32_t hp = (uint32_t)*(uint16_t*)&h0 |
                                  ((uint32_t)*(uint16_t*)&h1 << 16);
                    uint32_t lp = (uint32_t)*(uint16_t*)&l0 |
                                  ((uint32_t)*(uint16_t*)&l1 << 16);
                    *reinterpret_cast<uint32_t*>(&Cb[cOff + row * ldc + co]) = hp;
                    *reinterpret_cast<uint32_t*>(&Cb[cOff + row * ldc + co + loOff]) = lp;
                }
            }
        }
    }

    // mirror tile C[n,m] = C[m,n] via smem transpose (coalesced stores)
    if (SYM && !diag) {
        CP_WAIT0();
        __syncthreads();
        __nv_bfloat16* sm = (__nv_bfloat16*)dsm;   // 128 x 144 bf16
        #pragma unroll
        for (int ph = 0; ph < 2; ph++) {
            #pragma unroll
            for (int mt = 0; mt < 4; mt++)
                #pragma unroll
                for (int half = 0; half < 2; half++) {
                    int r = wm * 64 + mt * 16 + g + half * 8;
                    #pragma unroll
                    for (int nt = 0; nt < 4; nt++) {
                        int cc = wn * 32 + nt * 8 + tg * 2;
                        float f0 = acc[mt][nt][half * 2 + 0];
                        float f1 = acc[mt][nt][half * 2 + 1];
                        __nv_bfloat16 h0, l0, h1, l1;
                        split2(f0, h0, l0);
                        split2(f1, h1, l1);
                        sm[cc * 144 + r]       = ph ? l0 : h0;
                        sm[(cc + 1) * 144 + r] = ph ? l1 : h1;
                    }
                }
            __syncthreads();
            int cc2 = tid >> 1, seg = (tid & 1) * 64;
            const uint4* src = (const uint4*)(sm + cc2 * 144 + seg);
            uint4* dst = (uint4*)(&Cb[cOff + (long)(n0 + cc2) * ldc + m0 + seg +
                                      (ph ? loOff : 0)]);
            #pragma unroll
            for (int u = 0; u < 8; u++) dst[u] = src[u];
            __syncthreads();
        }
    }
}

// ---------------- host launch ----------------
extern "C" void kernel_launch(void* const* d_in, const int* in_sizes, int n_in,
                              void* d_out, int out_size) {
    const int*   input_  = (const int*)d_in[0];
    const float* emb     = (const float*)d_in[1];
    const float* pos     = (const float*)d_in[2];
    const float* Dx      = (const float*)d_in[3];
    const float* Dy      = (const float*)d_in[4];
    const float* E       = (const float*)d_in[5];
    const float* readout = (const float*)d_in[6];
    float* out = (float*)d_out;

    cudaFuncSetAttribute(gemm_mma<0, false>, cudaFuncAttributeMaxDynamicSharedMemorySize, SMEM_GEMM_BYTES);
    cudaFuncSetAttribute(gemm_mma<2, true>,  cudaFuncAttributeMaxDynamicSharedMemorySize, SMEM_GEMM_BYTES);
    cudaFuncSetAttribute(gemm_mma<3, false>, cudaFuncAttributeMaxDynamicSharedMemorySize, SMEM_GEMM_BYTES);
    cudaFuncSetAttribute(gemm_mma<4, false>, cudaFuncAttributeMaxDynamicSharedMemorySize, SMEM_GEMM_BYTES);

    float *v, *x, *a, *yE, *ct, *st;
    __nv_bfloat16 *v2a, *vT2, *q2, *s2, *a2, *y2, *Dx2, *Dy2, *E2, *ro2;
    cudaGetSymbolAddress((void**)&v,   g_v);
    cudaGetSymbolAddress((void**)&v2a, g_v2a);
    cudaGetSymbolAddress((void**)&vT2, g_vT2);
    cudaGetSymbolAddress((void**)&x,   g_x);
    cudaGetSymbolAddress((void**)&q2,  g_q2);
    cudaGetSymbolAddress((void**)&s2,  g_s2);
    cudaGetSymbolAddress((void**)&a,   g_a);
    cudaGetSymbolAddress((void**)&a2,  g_a2);
    cudaGetSymbolAddress((void**)&y2,  g_y2);
    cudaGetSymbolAddress((void**)&yE,  g_yE);
    cudaGetSymbolAddress((void**)&Dx2, g_Dx2);
    cudaGetSymbolAddress((void**)&Dy2, g_Dy2);
    cudaGetSymbolAddress((void**)&E2,  g_E2);
    cudaGetSymbolAddress((void**)&ro2, g_ro2);
    cudaGetSymbolAddress((void**)&ct,  g_cos);
    cudaGetSymbolAddress((void**)&st,  g_sin);

    dim3 tb(32, 8);

    rope_table_kernel<<<(TT * 512 + 255) / 256, 256>>>();
    embed_ln_kernel<<<BB * TT, 256>>>(input_, emb, pos);
    // weights: permuted per 1024-block
    transpose_split_kernel<<<dim3(KK / 32, DD / 32, HH), tb>>>(Dx, Dx2, DD, KK, (long)DD * KK, (long)KK * 2 * DD, 1);
    transpose_split_kernel<<<dim3(KK / 32, DD / 32, HH), tb>>>(Dy, Dy2, DD, KK, (long)DD * KK, (long)KK * 2 * DD, 1);
    transpose_split_kernel<<<dim3(DD / 32, NN_ / 32, 1), tb>>>(E, E2, NN_, DD, 0, 0, 2);
    transpose_split_kernel<<<dim3(BV / 32, DD / 32, 1), tb>>>(readout, ro2, DD, BV, 0, 0, 0);

    const long TK  = (long)TT * KK;
    const long T2D = (long)TT * 2 * DD;
    const long T2K = (long)TT * 2 * KK;
    const long T2T = (long)TT * 2 * TT;
    const long T2N = (long)TT * 2 * NN_;
    const long TD  = (long)TT * DD;

    for (int l = 0; l < LL; l++) {
        transpose_split_kernel<<<dim3(DD / 32, TT / 32, BB), tb>>>(v, vT2, TT, DD, TD, (long)DD * 2 * TT, 0);

        // x = relu(v2a @ Dx2^T) fp32 (permuted cols) + fused RoPE -> q2
        gemm_mma<4, false><<<dim3(KK / 128, TT / 128, BB * HH), 256, SMEM_GEMM_BYTES>>>(
            v2a, Dx2, x, nullptr,
            DD, DD, 2 * DD, 2 * DD, KK, 0, 0,
            T2D, 0, 0, (long)KK * 2 * DD, (long)HH * TK, TK, 0, 0, HH, 1, 0,
            q2, (long)HH * T2K, T2K, ct, st);

        // s2[b,h] = q2 @ q2^T (split out, SYMMETRIC) : 136 upper-tri blocks
        gemm_mma<2, true><<<dim3(136, 1, BB * HH), 256, SMEM_GEMM_BYTES>>>(
            q2, q2, s2, nullptr,
            KK, KK, 2 * KK, 2 * KK, 2 * TT, 0, TT,
            (long)HH * T2K, T2K, (long)HH * T2K, T2K, (long)HH * T2T, T2T, 0, 0, HH, 1, 0,
            nullptr, 0, 0, nullptr, nullptr);

        // a[b,h] = s2 @ vT2^T fp32 : M=2048 N=256 Kd=2048
        gemm_mma<0, false><<<dim3(DD / 128, TT / 128, BB * HH), 256, SMEM_GEMM_BYTES>>>(
            s2, vT2, a, nullptr,
            TT, TT, 2 * TT, 2 * TT, DD, 0, 0,
            (long)HH * T2T, T2T, (long)DD * 2 * TT, 0, (long)HH * TD, TD, 0, 0, HH, 1, 0,
            nullptr, 0, 0, nullptr, nullptr);

        ln_split_kernel<<<BB * HH * TT, 256>>>();

        // y2[b,t,h*K+n'] = relu(a2 @ Dy2^T) * x (split, permuted cols, loOff=NN_)
        gemm_mma<3, false><<<dim3(KK / 128, TT / 128, BB * HH), 256, SMEM_GEMM_BYTES>>>(
            a2, Dy2, y2, x,
            DD, DD, 2 * DD, 2 * DD, 2 * NN_, KK, NN_,
            (long)HH * T2D, T2D, 0, (long)KK * 2 * DD,
            T2N, (long)KK, (long)HH * TK, TK, HH, 1, 0,
            nullptr, 0, 0, nullptr, nullptr);

        // yE partials = y2 @ E2^T (split-K=4) : M=4096 N=256, Kd=1024/split
        gemm_mma<0, false><<<dim3(DD / 128, (BB * TT) / 128, 4), 256, SMEM_GEMM_BYTES>>>(
            y2, E2, yE, nullptr,
            NN_ / 4, NN_, 2 * NN_, 2 * NN_, DD, 0, 0,
            0, 0, 0, 0, 0, 0, 0, 0, 1, 4, 4096L * 256,
            nullptr, 0, 0, nullptr, nullptr);

        combine_split_kernel<<<BB * TT, 256>>>(pos, l < LL - 1 ? 1 : 0);
    }

    // out = v2a @ ro2^T fp32 : M=4096 N=32000 Kd=256
    gemm_mma<0, false><<<dim3(BV / 128, (BB * TT) / 128, 1), 256, SMEM_GEMM_BYTES>>>(
        v2a, ro2, out, nullptr,
        DD, DD, 2 * DD, 2 * DD, BV, 0, 0,
        0, 0, 0, 0, 0, 0, 0, 0, 1, 1, 0,
        nullptr, 0, 0, nullptr, nullptr);
}

// round 11
// speedup vs baseline: 2.8863x; 1.4771x over previous
#include <cuda_runtime.h>
#include <cuda_fp16.h>
#include <math.h>
#include <stdint.h>

// ---------------- problem constants ----------------
#define BV   32000
#define TT   2048
#define HH   4
#define NN_  4096
#define DD   256
#define LL   6
#define KK   1024
#define BB   2
#define EPS  1e-5f

// ---------------- device scratch (no mallocs allowed) ----------------
__device__ float  g_v   [4096L*256];
__device__ __half g_v2a [4096L*256];     // [B*T, D] hi only (A operand)
__device__ __half g_vT2 [2L*256*4096];   // [B][D, 2T] hi|lo (B operand)
__device__ float  g_x   [8L*2048*1024];  // [B,H,T,K] fp32 (PERMUTED cols)
__device__ __half g_q2  [8L*2048*2048];  // [B,H,T,2K] hi|lo (PERMUTED cols)
__device__ __half g_s2  [8L*2048*2048];  // [B,H,T,T] hi only
__device__ float  g_a   [8L*2048*256];
__device__ __half g_a2  [8L*2048*256];   // hi only
__device__ __half g_y2  [2L*2048*4096];  // [B,T,N] hi only (PERMUTED cols/head)
__device__ float  g_yE  [4L*4096*256];   // 4 split-K partials
__device__ __half g_Dx2 [4L*1024*512];   // [H][K, 2D] hi|lo (PERMUTED rows)
__device__ __half g_Dy2 [4L*1024*512];
__device__ __half g_E2  [256L*8192];     // [D, 2N] hi|lo (PERMUTED cols/head)
__device__ __half g_ro2 [32000L*512];    // [V, 2D] hi|lo
__device__ float  g_cos [2048L*512];     // [T, 512]
__device__ float  g_sin [2048L*512];

// per-head column permutation: k<512 -> 2k ; k>=512 -> 2k-1023
__host__ __device__ __forceinline__ int permk(int k) {
    return (k < 512) ? (2 * k) : (2 * k - 1023);
}

// ---------------- PTX helpers (baseline ISA only: sm_80-class) ----------------
__device__ __forceinline__ uint32_t smem_u32(const void* p) {
    uint32_t a;
    asm("{ .reg .u64 t; cvta.to.shared.u64 t, %1; cvt.u32.u64 %0, t; }" : "=r"(a) : "l"(p));
    return a;
}
#define CP_ASYNC16(saddr, gaddr) \
    asm volatile("cp.async.cg.shared.global [%0], [%1], 16;" :: "r"(saddr), "l"(gaddr))
#define CP_COMMIT() asm volatile("cp.async.commit_group;" ::: "memory")
#define CP_WAIT1()  asm volatile("cp.async.wait_group 1;" ::: "memory")
#define CP_WAIT0()  asm volatile("cp.async.wait_group 0;" ::: "memory")

#define LDSM_X4(r0, r1, r2, r3, addr) \
    asm volatile("ldmatrix.sync.aligned.m8n8.x4.shared.b16 {%0,%1,%2,%3}, [%4];" \
        : "=r"(r0), "=r"(r1), "=r"(r2), "=r"(r3) : "r"(addr))

#define MMA16816(d, a, b0, b1) \
    asm volatile("mma.sync.aligned.m16n8k16.row.col.f32.f16.f16.f32 " \
        "{%0,%1,%2,%3}, {%4,%5,%6,%7}, {%8,%9}, {%0,%1,%2,%3};" \
        : "+f"((d)[0]), "+f"((d)[1]), "+f"((d)[2]), "+f"((d)[3]) \
        : "r"((a)[0]), "r"((a)[1]), "r"((a)[2]), "r"((a)[3]), "r"(b0), "r"(b1))

__device__ __forceinline__ void split2h(float f, __half& h, __half& l) {
    h = __float2half_rn(f);
    l = __float2half_rn(f - __half2float(h));
}
__device__ __forceinline__ uint32_t pack2(__half a, __half b) {
    return (uint32_t)__half_as_ushort(a) | ((uint32_t)__half_as_ushort(b) << 16);
}

// swizzled smem offset: 64B rows, seg' = seg ^ ((row>>1)&3)
__device__ __forceinline__ uint32_t swz(uint32_t row, uint32_t seg) {
    return row * 64u + (((seg) ^ ((row >> 1) & 3u)) << 4);
}

// ---------------- block reduction (256 threads) ----------------
__device__ __forceinline__ float blockReduceSum256(float val) {
    __shared__ float s[8];
    __shared__ float res;
    int lane = threadIdx.x & 31, w = threadIdx.x >> 5;
    #pragma unroll
    for (int o = 16; o; o >>= 1) val += __shfl_xor_sync(0xffffffffu, val, o);
    if (lane == 0) s[w] = val;
    __syncthreads();
    if (threadIdx.x < 8) {
        float v = s[threadIdx.x];
        #pragma unroll
        for (int o = 4; o; o >>= 1) v += __shfl_xor_sync(0xffu, v, o);
        if (threadIdx.x == 0) res = v;
    }
    __syncthreads();
    float r = res;
    __syncthreads();
    return r;
}

// ---------------- elementwise kernels ----------------
__global__ void rope_table_kernel() {
    long idx = (long)blockIdx.x * blockDim.x + threadIdx.x;
    if (idx >= (long)TT * 512) return;
    int t = (int)(idx >> 9);
    int i = (int)(idx & 511);
    float ex  = (2.0f * (float)i) / (float)KK;
    float inv = 1.0f / powf(10000.0f, ex);
    float th  = (float)t * inv;
    g_cos[idx] = cosf(th);
    g_sin[idx] = sinf(th);
}

// v = ln(emb[input]) + pos, store fp32 + fp16 hi
__global__ void embed_ln_kernel(const int* __restrict__ input_,
                                const float* __restrict__ emb,
                                const float* __restrict__ pos) {
    int row = blockIdx.x;                 // B*T
    int t = row & (TT - 1);
    int tok = input_[row];
    float x = emb[(long)tok * DD + threadIdx.x];
    float mu = blockReduceSum256(x) * (1.0f / DD);
    float d = x - mu;
    float var = blockReduceSum256(d * d) * (1.0f / DD);
    float f = d * rsqrtf(var + EPS) + pos[(long)t * DD + threadIdx.x];
    g_v[(long)row * DD + threadIdx.x] = f;
    g_v2a[(long)row * DD + threadIdx.x] = __float2half_rn(f);
}

// v = ln(v + ln(sum of 4 yE partials)) [+ pos], store fp32 + fp16 hi
__global__ void combine_split_kernel(const float* __restrict__ pos, int do_pos) {
    long row = blockIdx.x;                 // B*T
    const long P = 4096L * 256;
    float u = g_yE[row * DD + threadIdx.x] + g_yE[P + row * DD + threadIdx.x] +
              g_yE[2 * P + row * DD + threadIdx.x] + g_yE[3 * P + row * DD + threadIdx.x];
    float mu = blockReduceSum256(u) * (1.0f / DD);
    float d = u - mu;
    float var = blockReduceSum256(d * d) * (1.0f / DD);
    float w = g_v[row * DD + threadIdx.x] + d * rsqrtf(var + EPS);
    float mu2 = blockReduceSum256(w) * (1.0f / DD);
    float d2 = w - mu2;
    float var2 = blockReduceSum256(d2 * d2) * (1.0f / DD);
    float f = d2 * rsqrtf(var2 + EPS);
    if (do_pos) {
        int t = (int)(row & (TT - 1));
        f += pos[(long)t * DD + threadIdx.x];
    }
    g_v[row * DD + threadIdx.x] = f;
    g_v2a[row * DD + threadIdx.x] = __float2half_rn(f);
}

__global__ void ln_split_kernel() {
    long row = blockIdx.x;                 // B*H*T
    float x = g_a[row * DD + threadIdx.x];
    float mu = blockReduceSum256(x) * (1.0f / DD);
    float d = x - mu;
    float var = blockReduceSum256(d * d) * (1.0f / DD);
    float f = d * rsqrtf(var + EPS);
    g_a2[row * DD + threadIdx.x] = __float2half_rn(f);
}

// X [R,C] fp32 -> Y [C, 2R] fp16 (hi cols [0,R), lo cols [R,2R))
// PERM: 0 = none; 1 = permute OUT-ROW (X column) per 1024-block;
//       2 = permute OUT-COL (X row) per 1024-block.
__global__ void transpose_split_kernel(const float* __restrict__ X,
                                       __half* __restrict__ Y,
                                       int R, int C, long inZ, long outZ, int PERM) {
    __shared__ float tile[32][33];
    X += (long)blockIdx.z * inZ;
    Y += (long)blockIdx.z * outZ;
    int r0 = blockIdx.y * 32, c0 = blockIdx.x * 32;
    int tx = threadIdx.x, ty = threadIdx.y;   // (32,8)
    #pragma unroll
    for (int i = 0; i < 32; i += 8)
        tile[ty + i][tx] = X[(long)(r0 + ty + i) * C + c0 + tx];
    __syncthreads();
    #pragma unroll
    for (int i = 0; i < 32; i += 8) {
        float f = tile[tx][ty + i];           // X[r0+tx][c0+ty+i]
        __half h, l; split2h(f, h, l);
        int orowi = c0 + ty + i;
        int ocol  = r0 + tx;
        if (PERM == 1) {
            int blk = orowi & ~1023;
            orowi = blk + permk(orowi & 1023);
        } else if (PERM == 2) {
            int blk = ocol & ~1023;
            ocol = blk + permk(ocol & 1023);
        }
        long orow = (long)orowi * 2 * R;
        Y[orow + ocol] = h;
        Y[orow + R + ocol] = l;
    }
}

// ---------------- mma.sync GEMM (HMMA fp16 2-pass) ----------------
// C[M,N] = Ah[M,K] x (Bh+Bl)[N,2K]^T : A single fp16 (hi), B split hi/lo.
// Per 32-wide K chunk: load Ah, Bh, Bl tiles; passes AhBh + AhBl (ar reused).
// CTA tile 128x128, 3-stage cp.async pipeline (stage = 3 x 8192B = 24KB),
// XOR-swizzled 64B smem rows, single __syncthreads per chunk.
// 8 warps 2(m) x 4(n), warp tile 64x32.
// EPI: 0=fp32, 3=relu*G -> fp16 hi, 4=relu fp32 + fused RoPE -> Q split,
//      5=fp16 hi (scores)
// SYM: A==B symmetric tiles (mirror via smem transpose, hi only).
// Split-K: nsplit partials, sp = blockIdx.z % nsplit.
#define OPER_BYTES 8192                    // 128 rows x 64B
#define STAGE_BYTES (3 * OPER_BYTES)       // 24576: Ah|Bh|Bl
#define SMEM_GEMM_BYTES (3 * STAGE_BYTES)  // 73728

template<int EPI, bool SYM>
__global__ void __launch_bounds__(256, 2)
gemm_mma(const __half* __restrict__ A, const __half* __restrict__ B,
         void* __restrict__ Cv, const float* __restrict__ G,
         int Kd, int KdLo, int lda, int ldb, int ldc, int ldgt,
         long sAb, long sAh, long sBb, long sBh, long sCb, long sCh,
         long sGb, long sGh, int Hdim, int nsplit, long sSplitC,
         __half* __restrict__ Q, long sQb, long sQh,
         const float* __restrict__ CT, const float* __restrict__ ST)
{
    extern __shared__ char dsm[];
    uint32_t sbase = smem_u32(dsm);

    int tid = threadIdx.x;
    int lane = tid & 31;
    int wid = tid >> 5;
    int wm = wid >> 2;        // 0..1
    int wn = wid & 3;         // 0..3

    int zz = blockIdx.z;
    int sp = 0, z = zz;
    if (nsplit > 1) { sp = zz % nsplit; z = zz / nsplit; }
    int bb = z / Hdim, hh = z - bb * Hdim;
    A += bb * sAb + hh * sAh;
    B += bb * sBb + hh * sBh;
    long cOff = bb * sCb + hh * sCh + sp * sSplitC;
    if (EPI == 3) G += bb * sGb + hh * sGh;
    long qOff = 0;
    if (EPI == 4) qOff = bb * sQb + hh * sQh;

    int m0, n0, diag = 0;
    if (SYM) {
        int L = blockIdx.x, ii = 0;
        while (L >= 16 - ii) { L -= 16 - ii; ii++; }
        m0 = ii * 128; n0 = (ii + L) * 128;
        diag = (L == 0);
    } else {
        m0 = blockIdx.y * 128;
        n0 = blockIdx.x * 128;
    }

    const int KC = Kd >> 5;       // 32-wide chunks
    const int spK = sp * Kd;

    int lrow = tid >> 2;          // 0..63
    int lseg = tid & 3;

    auto issue = [&](int cc) {
        int koff = spK + (cc << 5);
        uint32_t st = sbase + (cc % 3) * STAGE_BYTES;
        #pragma unroll
        for (int i = 0; i < 2; i++) {
            uint32_t row = lrow + i * 64;
            uint32_t so = swz(row, (uint32_t)lseg);
            long go = lseg * 8;
            const __half* ga = A + (long)(m0 + row) * lda + koff + go;
            const __half* gb = B + (long)(n0 + row) * ldb + koff + go;
            CP_ASYNC16(st + so,                  ga);           // A hi
            CP_ASYNC16(st + OPER_BYTES + so,     gb);           // B hi
            CP_ASYNC16(st + 2 * OPER_BYTES + so, gb + KdLo);    // B lo
        }
    };

    float acc[4][4][4];
    #pragma unroll
    for (int i = 0; i < 4; i++)
        #pragma unroll
        for (int j = 0; j < 4; j++)
            #pragma unroll
            for (int r = 0; r < 4; r++) acc[i][j][r] = 0.0f;

    issue(0); CP_COMMIT();
    issue(1); CP_COMMIT();

    int rsel = lane & 15;
    int hi16 = lane >> 4;         // 0 or 1: second 16B seg of the k16 block

    for (int c = 0; c < KC; c++) {
        CP_WAIT1();              // chunk c data complete
        __syncthreads();         // copies visible; compute c-1 done

        uint32_t sah = sbase + (c % 3) * STAGE_BYTES;
        uint32_t sbh = sah + OPER_BYTES;
        uint32_t sbl = sah + 2 * OPER_BYTES;

        #pragma unroll
        for (int ks = 0; ks < 2; ks++) {
            uint32_t segb = (uint32_t)(ks * 2 + hi16);
            uint32_t ar[4][4], brh[2][4], brl[2][4];
            #pragma unroll
            for (int n2 = 0; n2 < 2; n2++) {
                uint32_t row = (uint32_t)(wn * 32 + n2 * 16 + rsel);
                LDSM_X4(brh[n2][0], brh[n2][1], brh[n2][2], brh[n2][3], sbh + swz(row, segb));
            }
            #pragma unroll
            for (int n2 = 0; n2 < 2; n2++) {
                uint32_t row = (uint32_t)(wn * 32 + n2 * 16 + rsel);
                LDSM_X4(brl[n2][0], brl[n2][1], brl[n2][2], brl[n2][3], sbl + swz(row, segb));
            }
            #pragma unroll
            for (int mt = 0; mt < 4; mt++) {
                uint32_t row = (uint32_t)(wm * 64 + mt * 16 + rsel);
                LDSM_X4(ar[mt][0], ar[mt][1], ar[mt][2], ar[mt][3], sah + swz(row, segb));
            }
            // pass 1: Ah x Bh
            #pragma unroll
            for (int mt = 0; mt < 4; mt++)
                #pragma unroll
                for (int nt = 0; nt < 4; nt++) {
                    int n2 = nt >> 1, j = nt & 1;
                    MMA16816(acc[mt][nt], ar[mt], brh[n2][j], brh[n2][2 + j]);
                }
            // hide next-chunk copy issue under the tensor-pipe shadow
            if (ks == 0) {
                if (c + 2 < KC) issue(c + 2);
                CP_COMMIT();
            }
            // pass 2: Ah x Bl (reuses ar)
            #pragma unroll
            for (int mt = 0; mt < 4; mt++)
                #pragma unroll
                for (int nt = 0; nt < 4; nt++) {
                    int n2 = nt >> 1, j = nt & 1;
                    MMA16816(acc[mt][nt], ar[mt], brl[n2][j], brl[n2][2 + j]);
                }
        }
    }

    // ---------------- epilogue ----------------
    int g = lane >> 2, tg = lane & 3;
    float* Cf = (float*)Cv;
    __half* Cb = (__half*)Cv;

    #pragma unroll
    for (int mt = 0; mt < 4; mt++) {
        #pragma unroll
        for (int half = 0; half < 2; half++) {
            long row = m0 + wm * 64 + mt * 16 + g + half * 8;
            #pragma unroll
            for (int nt = 0; nt < 4; nt++) {
                int co = n0 + wn * 32 + nt * 8 + tg * 2;
                float f0 = acc[mt][nt][half * 2 + 0];
                float f1 = acc[mt][nt][half * 2 + 1];
                if (EPI == 0) {
                    *reinterpret_cast<float2*>(&Cf[cOff + row * ldc + co]) =
                        make_float2(f0, f1);
                } else if (EPI == 4) {
                    f0 = fmaxf(f0, 0.f);
                    f1 = fmaxf(f1, 0.f);
                    *reinterpret_cast<float2*>(&Cf[cOff + row * ldc + co]) =
                        make_float2(f0, f1);
                    // RoPE: pair (co, co+1) = original (i, i+512), i = co/2
                    int i = co >> 1;
                    long tb = row * 512 + i;   // row == t
                    float cv = CT[tb], sv = ST[tb];
                    float qa = f0 * cv - f1 * sv;
                    float qb = f1 * cv + f0 * sv;
                    __half h0, l0, h1, l1;
                    split2h(qa, h0, l0);
                    split2h(qb, h1, l1);
                    *reinterpret_cast<uint32_t*>(&Q[qOff + row * 2048 + co]) = pack2(h0, h1);
                    *reinterpret_cast<uint32_t*>(&Q[qOff + row * 2048 + co + KK]) = pack2(l0, l1);
                } else if (EPI == 5) {
                    *reinterpret_cast<uint32_t*>(&Cb[cOff + row * ldc + co]) =
                        pack2(__float2half_rn(f0), __float2half_rn(f1));
                } else {  // EPI == 3
                    float2 gv = *reinterpret_cast<const float2*>(
                        &G[row * (long)ldgt + co]);
                    f0 = fmaxf(f0, 0.f) * gv.x;
                    f1 = fmaxf(f1, 0.f) * gv.y;
                    *reinterpret_cast<uint32_t*>(&Cb[cOff + row * ldc + co]) =
                        pack2(__float2half_rn(f0), __float2half_rn(f1));
                }
            }
        }
    }

    // mirror tile C[n,m] = C[m,n] via smem transpose (hi only, coalesced)
    if (SYM && !diag) {
        CP_WAIT0();
        __syncthreads();
        __half* sm = (__half*)dsm;   // 128 x 144 fp16
        #pragma unroll
        for (int mt = 0; mt < 4; mt++)
            #pragma unroll
            for (int half = 0; half < 2; half++) {
                int r = wm * 64 + mt * 16 + g + half * 8;
                #pragma unroll
                for (int nt = 0; nt < 4; nt++) {
                    int cc = wn * 32 + nt * 8 + tg * 2;
                    sm[cc * 144 + r]       = __float2half_rn(acc[mt][nt][half * 2 + 0]);
                    sm[(cc + 1) * 144 + r] = __float2half_rn(acc[mt][nt][half * 2 + 1]);
                }
            }
        __syncthreads();
        int cc2 = tid >> 1, seg = (tid & 1) * 64;
        const uint4* src = (const uint4*)(sm + cc2 * 144 + seg);
        uint4* dst = (uint4*)(&Cb[cOff + (long)(n0 + cc2) * ldc + m0 + seg]);
        #pragma unroll
        for (int u = 0; u < 8; u++) dst[u] = src[u];
    }
}

// ---------------- host launch ----------------
extern "C" void kernel_launch(void* const* d_in, const int* in_sizes, int n_in,
                              void* d_out, int out_size) {
    const int*   input_  = (const int*)d_in[0];
    const float* emb     = (const float*)d_in[1];
    const float* pos     = (const float*)d_in[2];
    const float* Dx      = (const float*)d_in[3];
    const float* Dy      = (const float*)d_in[4];
    const float* E       = (const float*)d_in[5];
    const float* readout = (const float*)d_in[6];
    float* out = (float*)d_out;

    cudaFuncSetAttribute(gemm_mma<0, false>, cudaFuncAttributeMaxDynamicSharedMemorySize, SMEM_GEMM_BYTES);
    cudaFuncSetAttribute(gemm_mma<3, false>, cudaFuncAttributeMaxDynamicSharedMemorySize, SMEM_GEMM_BYTES);
    cudaFuncSetAttribute(gemm_mma<4, false>, cudaFuncAttributeMaxDynamicSharedMemorySize, SMEM_GEMM_BYTES);
    cudaFuncSetAttribute(gemm_mma<5, true>,  cudaFuncAttributeMaxDynamicSharedMemorySize, SMEM_GEMM_BYTES);

    float *v, *x, *a, *yE, *ct, *st;
    __half *v2a, *vT2, *q2, *s2, *a2, *y2, *Dx2, *Dy2, *E2, *ro2;
    cudaGetSymbolAddress((void**)&v,   g_v);
    cudaGetSymbolAddress((void**)&v2a, g_v2a);
    cudaGetSymbolAddress((void**)&vT2, g_vT2);
    cudaGetSymbolAddress((void**)&x,   g_x);
    cudaGetSymbolAddress((void**)&q2,  g_q2);
    cudaGetSymbolAddress((void**)&s2,  g_s2);
    cudaGetSymbolAddress((void**)&a,   g_a);
    cudaGetSymbolAddress((void**)&a2,  g_a2);
    cudaGetSymbolAddress((void**)&y2,  g_y2);
    cudaGetSymbolAddress((void**)&yE,  g_yE);
    cudaGetSymbolAddress((void**)&Dx2, g_Dx2);
    cudaGetSymbolAddress((void**)&Dy2, g_Dy2);
    cudaGetSymbolAddress((void**)&E2,  g_E2);
    cudaGetSymbolAddress((void**)&ro2, g_ro2);
    cudaGetSymbolAddress((void**)&ct,  g_cos);
    cudaGetSymbolAddress((void**)&st,  g_sin);

    dim3 tb(32, 8);

    rope_table_kernel<<<(TT * 512 + 255) / 256, 256>>>();
    embed_ln_kernel<<<BB * TT, 256>>>(input_, emb, pos);
    transpose_split_kernel<<<dim3(KK / 32, DD / 32, HH), tb>>>(Dx, Dx2, DD, KK, (long)DD * KK, (long)KK * 2 * DD, 1);
    transpose_split_kernel<<<dim3(KK / 32, DD / 32, HH), tb>>>(Dy, Dy2, DD, KK, (long)DD * KK, (long)KK * 2 * DD, 1);
    transpose_split_kernel<<<dim3(DD / 32, NN_ / 32, 1), tb>>>(E, E2, NN_, DD, 0, 0, 2);
    transpose_split_kernel<<<dim3(BV / 32, DD / 32, 1), tb>>>(readout, ro2, DD, BV, 0, 0, 0);

    const long TK  = (long)TT * KK;
    const long TD  = (long)TT * DD;
    const long T2K = (long)TT * 2 * KK;
    const long TTl = (long)TT * TT;
    const long TN  = (long)TT * NN_;

    for (int l = 0; l < LL; l++) {
        transpose_split_kernel<<<dim3(DD / 32, TT / 32, BB), tb>>>(v, vT2, TT, DD, TD, (long)DD * 2 * TT, 0);

        // x = relu(v2a @ Dx2^T) fp32 (permuted cols) + fused RoPE -> q2 split
        gemm_mma<4, false><<<dim3(KK / 128, TT / 128, BB * HH), 256, SMEM_GEMM_BYTES>>>(
            v2a, Dx2, x, nullptr,
            DD, DD, DD, 2 * DD, KK, 0,
            TD, 0, 0, (long)KK * 2 * DD, (long)HH * TK, TK, 0, 0, HH, 1, 0,
            q2, (long)HH * T2K, T2K, ct, st);

        // s2[b,h] = qh @ (qh+ql)^T (hi-only out, SYMMETRIC) : 136 blocks
        gemm_mma<5, true><<<dim3(136, 1, BB * HH), 256, SMEM_GEMM_BYTES>>>(
            q2, q2, s2, nullptr,
            KK, KK, 2 * KK, 2 * KK, TT, 0,
            (long)HH * T2K, T2K, (long)HH * T2K, T2K, (long)HH * TTl, TTl, 0, 0, HH, 1, 0,
            nullptr, 0, 0, nullptr, nullptr);

        // a[b,h] = s2 @ vT2^T fp32 : M=2048 N=256 Kd=2048
        gemm_mma<0, false><<<dim3(DD / 128, TT / 128, BB * HH), 256, SMEM_GEMM_BYTES>>>(
            s2, vT2, a, nullptr,
            TT, TT, TT, 2 * TT, DD, 0,
            (long)HH * TTl, TTl, (long)DD * 2 * TT, 0, (long)HH * TD, TD, 0, 0, HH, 1, 0,
            nullptr, 0, 0, nullptr, nullptr);

        ln_split_kernel<<<BB * HH * TT, 256>>>();

        // y2[b,t,h*K+n'] = relu(a2 @ Dy2^T) * x (fp16 hi, permuted cols)
        gemm_mma<3, false><<<dim3(KK / 128, TT / 128, BB * HH), 256, SMEM_GEMM_BYTES>>>(
            a2, Dy2, y2, x,
            DD, DD, DD, 2 * DD, NN_, KK,
            (long)HH * TD, TD, 0, (long)KK * 2 * DD,
            TN, (long)KK, (long)HH * TK, TK, HH, 1, 0,
            nullptr, 0, 0, nullptr, nullptr);

        // yE partials = y2 @ E2^T (split-K=4) : M=4096 N=256
        gemm_mma<0, false><<<dim3(DD / 128, (BB * TT) / 128, 4), 256, SMEM_GEMM_BYTES>>>(
            y2, E2, yE, nullptr,
            NN_ / 4, NN_, NN_, 2 * NN_, DD, 0,
            0, 0, 0, 0, 0, 0, 0, 0, 1, 4, 4096L * 256,
            nullptr, 0, 0, nullptr, nullptr);

        combine_split_kernel<<<BB * TT, 256>>>(pos, l < LL - 1 ? 1 : 0);
    }

    // out = v2a @ ro2^T fp32 : M=4096 N=32000 Kd=256
    gemm_mma<0, false><<<dim3(BV / 128, (BB * TT) / 128, 1), 256, SMEM_GEMM_BYTES>>>(
        v2a, ro2, out, nullptr,
        DD, DD, DD, 2 * DD, BV, 0,
        0, 0, 0, 0, 0, 0, 0, 0, 1, 1, 0,
        nullptr, 0, 0, nullptr, nullptr);
}

// round 12
// speedup vs baseline: 4.1166x; 1.4263x over previous
#include <cuda_runtime.h>
#include <cuda_fp16.h>
#include <math.h>
#include <stdint.h>

// ---------------- problem constants ----------------
#define BV   32000
#define TT   2048
#define HH   4
#define NN_  4096
#define DD   256
#define LL   6
#define KK   1024
#define BB   2
#define EPS  1e-5f

// ---------------- device scratch (no mallocs allowed) ----------------
__device__ float  g_v   [4096L*256];
__device__ __half g_v2a [4096L*256];     // [B*T, D] hi only (A operand)
__device__ __half g_vT2 [2L*256*4096];   // [B][D, 2T] hi|lo
__device__ float  g_x   [8L*2048*1024];  // [B,H,T,K] fp32 gate (PERMUTED cols)
__device__ __half g_qh  [8L*2048*1024];  // [B,H,T,K]  q hi (PERMUTED cols)
__device__ __half g_qT  [8L*1024*4096];  // [B,H,K,2T] q^T hi|lo
__device__ __half g_wT  [8L*256*2048];   // [B,H,D,2K] w^T hi|lo, w = q^T v
__device__ float  g_a   [8L*2048*256];
__device__ __half g_a2  [8L*2048*256];   // hi only
__device__ __half g_y2  [2L*2048*4096];  // [B,T,N] hi only (PERMUTED cols/head)
__device__ float  g_yE  [4L*4096*256];   // 4 split-K partials
__device__ __half g_Dx2 [4L*1024*512];   // [H][K, 2D] hi|lo (PERMUTED rows)
__device__ __half g_Dy2 [4L*1024*512];
__device__ __half g_E2  [256L*8192];     // [D, 2N] hi|lo (PERMUTED cols/head)
__device__ __half g_ro2 [32000L*512];    // [V, 2D] hi|lo
__device__ float  g_cos [2048L*512];     // [T, 512]
__device__ float  g_sin [2048L*512];

// per-head column permutation: k<512 -> 2k ; k>=512 -> 2k-1023
__host__ __device__ __forceinline__ int permk(int k) {
    return (k < 512) ? (2 * k) : (2 * k - 1023);
}

// ---------------- PTX helpers (baseline ISA only: sm_80-class) ----------------
__device__ __forceinline__ uint32_t smem_u32(const void* p) {
    uint32_t a;
    asm("{ .reg .u64 t; cvta.to.shared.u64 t, %1; cvt.u32.u64 %0, t; }" : "=r"(a) : "l"(p));
    return a;
}
#define CP_ASYNC16(saddr, gaddr) \
    asm volatile("cp.async.cg.shared.global [%0], [%1], 16;" :: "r"(saddr), "l"(gaddr))
#define CP_COMMIT() asm volatile("cp.async.commit_group;" ::: "memory")
#define CP_WAIT1()  asm volatile("cp.async.wait_group 1;" ::: "memory")

#define LDSM_X4(r0, r1, r2, r3, addr) \
    asm volatile("ldmatrix.sync.aligned.m8n8.x4.shared.b16 {%0,%1,%2,%3}, [%4];" \
        : "=r"(r0), "=r"(r1), "=r"(r2), "=r"(r3) : "r"(addr))

#define MMA16816(d, a, b0, b1) \
    asm volatile("mma.sync.aligned.m16n8k16.row.col.f32.f16.f16.f32 " \
        "{%0,%1,%2,%3}, {%4,%5,%6,%7}, {%8,%9}, {%0,%1,%2,%3};" \
        : "+f"((d)[0]), "+f"((d)[1]), "+f"((d)[2]), "+f"((d)[3]) \
        : "r"((a)[0]), "r"((a)[1]), "r"((a)[2]), "r"((a)[3]), "r"(b0), "r"(b1))

__device__ __forceinline__ void split2h(float f, __half& h, __half& l) {
    h = __float2half_rn(f);
    l = __float2half_rn(f - __half2float(h));
}
__device__ __forceinline__ uint32_t pack2(__half a, __half b) {
    return (uint32_t)__half_as_ushort(a) | ((uint32_t)__half_as_ushort(b) << 16);
}

// swizzled smem offset: 64B rows, seg' = seg ^ ((row>>1)&3)
__device__ __forceinline__ uint32_t swz(uint32_t row, uint32_t seg) {
    return row * 64u + (((seg) ^ ((row >> 1) & 3u)) << 4);
}

// ---------------- block reduction (256 threads) ----------------
__device__ __forceinline__ float blockReduceSum256(float val) {
    __shared__ float s[8];
    __shared__ float res;
    int lane = threadIdx.x & 31, w = threadIdx.x >> 5;
    #pragma unroll
    for (int o = 16; o; o >>= 1) val += __shfl_xor_sync(0xffffffffu, val, o);
    if (lane == 0) s[w] = val;
    __syncthreads();
    if (threadIdx.x < 8) {
        float v = s[threadIdx.x];
        #pragma unroll
        for (int o = 4; o; o >>= 1) v += __shfl_xor_sync(0xffu, v, o);
        if (threadIdx.x == 0) res = v;
    }
    __syncthreads();
    float r = res;
    __syncthreads();
    return r;
}

// ---------------- elementwise kernels ----------------
__global__ void rope_table_kernel() {
    long idx = (long)blockIdx.x * blockDim.x + threadIdx.x;
    if (idx >= (long)TT * 512) return;
    int t = (int)(idx >> 9);
    int i = (int)(idx & 511);
    float ex  = (2.0f * (float)i) / (float)KK;
    float inv = 1.0f / powf(10000.0f, ex);
    float th  = (float)t * inv;
    g_cos[idx] = cosf(th);
    g_sin[idx] = sinf(th);
}

__global__ void embed_ln_kernel(const int* __restrict__ input_,
                                const float* __restrict__ emb,
                                const float* __restrict__ pos) {
    int row = blockIdx.x;                 // B*T
    int t = row & (TT - 1);
    int tok = input_[row];
    float x = emb[(long)tok * DD + threadIdx.x];
    float mu = blockReduceSum256(x) * (1.0f / DD);
    float d = x - mu;
    float var = blockReduceSum256(d * d) * (1.0f / DD);
    float f = d * rsqrtf(var + EPS) + pos[(long)t * DD + threadIdx.x];
    g_v[(long)row * DD + threadIdx.x] = f;
    g_v2a[(long)row * DD + threadIdx.x] = __float2half_rn(f);
}

__global__ void combine_split_kernel(const float* __restrict__ pos, int do_pos) {
    long row = blockIdx.x;                 // B*T
    const long P = 4096L * 256;
    float u = g_yE[row * DD + threadIdx.x] + g_yE[P + row * DD + threadIdx.x] +
              g_yE[2 * P + row * DD + threadIdx.x] + g_yE[3 * P + row * DD + threadIdx.x];
    float mu = blockReduceSum256(u) * (1.0f / DD);
    float d = u - mu;
    float var = blockReduceSum256(d * d) * (1.0f / DD);
    float w = g_v[row * DD + threadIdx.x] + d * rsqrtf(var + EPS);
    float mu2 = blockReduceSum256(w) * (1.0f / DD);
    float d2 = w - mu2;
    float var2 = blockReduceSum256(d2 * d2) * (1.0f / DD);
    float f = d2 * rsqrtf(var2 + EPS);
    if (do_pos) {
        int t = (int)(row & (TT - 1));
        f += pos[(long)t * DD + threadIdx.x];
    }
    g_v[row * DD + threadIdx.x] = f;
    g_v2a[row * DD + threadIdx.x] = __float2half_rn(f);
}

__global__ void ln_split_kernel() {
    long row = blockIdx.x;                 // B*H*T
    float x = g_a[row * DD + threadIdx.x];
    float mu = blockReduceSum256(x) * (1.0f / DD);
    float d = x - mu;
    float var = blockReduceSum256(d * d) * (1.0f / DD);
    float f = d * rsqrtf(var + EPS);
    g_a2[row * DD + threadIdx.x] = __float2half_rn(f);
}

// X [R,C] fp32 -> Y [C, 2R] fp16 (hi cols [0,R), lo cols [R,2R))
// PERM: 0 = none; 1 = permute OUT-ROW (X column) per 1024-block;
//       2 = permute OUT-COL (X row) per 1024-block.
__global__ void transpose_split_kernel(const float* __restrict__ X,
                                       __half* __restrict__ Y,
                                       int R, int C, long inZ, long outZ, int PERM) {
    __shared__ float tile[32][33];
    X += (long)blockIdx.z * inZ;
    Y += (long)blockIdx.z * outZ;
    int r0 = blockIdx.y * 32, c0 = blockIdx.x * 32;
    int tx = threadIdx.x, ty = threadIdx.y;   // (32,8)
    #pragma unroll
    for (int i = 0; i < 32; i += 8)
        tile[ty + i][tx] = X[(long)(r0 + ty + i) * C + c0 + tx];
    __syncthreads();
    #pragma unroll
    for (int i = 0; i < 32; i += 8) {
        float f = tile[tx][ty + i];           // X[r0+tx][c0+ty+i]
        __half h, l; split2h(f, h, l);
        int orowi = c0 + ty + i;
        int ocol  = r0 + tx;
        if (PERM == 1) {
            int blk = orowi & ~1023;
            orowi = blk + permk(orowi & 1023);
        } else if (PERM == 2) {
            int blk = ocol & ~1023;
            ocol = blk + permk(ocol & 1023);
        }
        long orow = (long)orowi * 2 * R;
        Y[orow + ocol] = h;
        Y[orow + R + ocol] = l;
    }
}

// ---------------- mma.sync GEMM (HMMA fp16 2-pass) ----------------
// C[M,N] = Ah[M,K] x (Bh+Bl)[N,2K]^T : A single fp16 (hi), B split hi/lo.
// Per 32-wide K chunk: load Ah, Bh, Bl tiles; passes AhBh + AhBl (ar reused).
// CTA tile 128x128, 3-stage cp.async pipeline (stage = 3 x 8192B = 24KB),
// XOR-swizzled 64B smem rows, single __syncthreads per chunk.
// 8 warps 2(m) x 4(n), warp tile 64x32.
// EPI: 0=fp32, 2=split fp16 hi/lo (loOff), 3=relu*G -> fp16 hi,
//      4=relu fp32 gate + fused RoPE -> q hi [t,k] AND qT hi|lo [k,2t]
// Split-K: nsplit partials, sp = blockIdx.z % nsplit.
#define OPER_BYTES 8192                    // 128 rows x 64B
#define STAGE_BYTES (3 * OPER_BYTES)       // 24576: Ah|Bh|Bl
#define SMEM_GEMM_BYTES (3 * STAGE_BYTES)  // 73728

template<int EPI>
__global__ void __launch_bounds__(256, 2)
gemm_mma(const __half* __restrict__ A, const __half* __restrict__ B,
         void* __restrict__ Cv, const float* __restrict__ G,
         int Kd, int KdLo, int lda, int ldb, int ldc, int ldgt, int loOff,
         long sAb, long sAh, long sBb, long sBh, long sCb, long sCh,
         long sGb, long sGh, int Hdim, int nsplit, long sSplitC,
         __half* __restrict__ Qh, __half* __restrict__ QT,
         const float* __restrict__ CT, const float* __restrict__ ST)
{
    extern __shared__ char dsm[];
    uint32_t sbase = smem_u32(dsm);

    int tid = threadIdx.x;
    int lane = tid & 31;
    int wid = tid >> 5;
    int wm = wid >> 2;        // 0..1
    int wn = wid & 3;         // 0..3

    int zz = blockIdx.z;
    int sp = 0, z = zz;
    if (nsplit > 1) { sp = zz % nsplit; z = zz / nsplit; }
    int bb = z / Hdim, hh = z - bb * Hdim;
    A += bb * sAb + hh * sAh;
    B += bb * sBb + hh * sBh;
    long cOff = bb * sCb + hh * sCh + sp * sSplitC;
    if (EPI == 3) G += bb * sGb + hh * sGh;
    long qhOff = 0, qtOff = 0;
    if (EPI == 4) {
        qhOff = (long)z * ((long)TT * KK);
        qtOff = (long)z * ((long)KK * 2 * TT);
    }

    int m0 = blockIdx.y * 128;
    int n0 = blockIdx.x * 128;

    const int KC = Kd >> 5;       // 32-wide chunks
    const int spK = sp * Kd;

    int lrow = tid >> 2;          // 0..63
    int lseg = tid & 3;

    auto issue = [&](int cc) {
        int koff = spK + (cc << 5);
        uint32_t st = sbase + (cc % 3) * STAGE_BYTES;
        #pragma unroll
        for (int i = 0; i < 2; i++) {
            uint32_t row = lrow + i * 64;
            uint32_t so = swz(row, (uint32_t)lseg);
            long go = lseg * 8;
            const __half* ga = A + (long)(m0 + row) * lda + koff + go;
            const __half* gb = B + (long)(n0 + row) * ldb + koff + go;
            CP_ASYNC16(st + so,                  ga);           // A hi
            CP_ASYNC16(st + OPER_BYTES + so,     gb);           // B hi
            CP_ASYNC16(st + 2 * OPER_BYTES + so, gb + KdLo);    // B lo
        }
    };

    float acc[4][4][4];
    #pragma unroll
    for (int i = 0; i < 4; i++)
        #pragma unroll
        for (int j = 0; j < 4; j++)
            #pragma unroll
            for (int r = 0; r < 4; r++) acc[i][j][r] = 0.0f;

    issue(0); CP_COMMIT();
    issue(1); CP_COMMIT();

    int rsel = lane & 15;
    int hi16 = lane >> 4;         // 0 or 1: second 16B seg of the k16 block

    for (int c = 0; c < KC; c++) {
        CP_WAIT1();              // chunk c data complete
        __syncthreads();         // copies visible; compute c-1 done

        uint32_t sah = sbase + (c % 3) * STAGE_BYTES;
        uint32_t sbh = sah + OPER_BYTES;
        uint32_t sbl = sah + 2 * OPER_BYTES;

        #pragma unroll
        for (int ks = 0; ks < 2; ks++) {
            uint32_t segb = (uint32_t)(ks * 2 + hi16);
            uint32_t ar[4][4], brh[2][4], brl[2][4];
            #pragma unroll
            for (int n2 = 0; n2 < 2; n2++) {
                uint32_t row = (uint32_t)(wn * 32 + n2 * 16 + rsel);
                LDSM_X4(brh[n2][0], brh[n2][1], brh[n2][2], brh[n2][3], sbh + swz(row, segb));
            }
            #pragma unroll
            for (int n2 = 0; n2 < 2; n2++) {
                uint32_t row = (uint32_t)(wn * 32 + n2 * 16 + rsel);
                LDSM_X4(brl[n2][0], brl[n2][1], brl[n2][2], brl[n2][3], sbl + swz(row, segb));
            }
            #pragma unroll
            for (int mt = 0; mt < 4; mt++) {
                uint32_t row = (uint32_t)(wm * 64 + mt * 16 + rsel);
                LDSM_X4(ar[mt][0], ar[mt][1], ar[mt][2], ar[mt][3], sah + swz(row, segb));
            }
            // pass 1: Ah x Bh
            #pragma unroll
            for (int mt = 0; mt < 4; mt++)
                #pragma unroll
                for (int nt = 0; nt < 4; nt++) {
                    int n2 = nt >> 1, j = nt & 1;
                    MMA16816(acc[mt][nt], ar[mt], brh[n2][j], brh[n2][2 + j]);
                }
            // hide next-chunk copy issue under the tensor-pipe shadow
            if (ks == 0) {
                if (c + 2 < KC) issue(c + 2);
                CP_COMMIT();
            }
            // pass 2: Ah x Bl (reuses ar)
            #pragma unroll
            for (int mt = 0; mt < 4; mt++)
                #pragma unroll
                for (int nt = 0; nt < 4; nt++) {
                    int n2 = nt >> 1, j = nt & 1;
                    MMA16816(acc[mt][nt], ar[mt], brl[n2][j], brl[n2][2 + j]);
                }
        }
    }

    // ---------------- epilogue ----------------
    int g = lane >> 2, tg = lane & 3;
    float* Cf = (float*)Cv;
    __half* Cb = (__half*)Cv;

    #pragma unroll
    for (int mt = 0; mt < 4; mt++) {
        #pragma unroll
        for (int half = 0; half < 2; half++) {
            long row = m0 + wm * 64 + mt * 16 + g + half * 8;
            #pragma unroll
            for (int nt = 0; nt < 4; nt++) {
                int co = n0 + wn * 32 + nt * 8 + tg * 2;
                float f0 = acc[mt][nt][half * 2 + 0];
                float f1 = acc[mt][nt][half * 2 + 1];
                if (EPI == 0) {
                    *reinterpret_cast<float2*>(&Cf[cOff + row * ldc + co]) =
                        make_float2(f0, f1);
                } else if (EPI == 2) {
                    __half h0, l0, h1, l1;
                    split2h(f0, h0, l0);
                    split2h(f1, h1, l1);
                    *reinterpret_cast<uint32_t*>(&Cb[cOff + row * ldc + co]) = pack2(h0, h1);
                    *reinterpret_cast<uint32_t*>(&Cb[cOff + row * ldc + co + loOff]) = pack2(l0, l1);
                } else if (EPI == 4) {
                    f0 = fmaxf(f0, 0.f);
                    f1 = fmaxf(f1, 0.f);
                    *reinterpret_cast<float2*>(&Cf[cOff + row * ldc + co]) =
                        make_float2(f0, f1);
                    // RoPE: pair (co, co+1) = original (i, i+512), i = co/2
                    int i = co >> 1;
                    long tb = row * 512 + i;   // row == t
                    float cv = CT[tb], sv = ST[tb];
                    float qa = f0 * cv - f1 * sv;
                    float qb = f1 * cv + f0 * sv;
                    __half h0, l0, h1, l1;
                    split2h(qa, h0, l0);
                    split2h(qb, h1, l1);
                    *reinterpret_cast<uint32_t*>(&Qh[qhOff + row * KK + co]) = pack2(h0, h1);
                    __half* qt = QT + qtOff + (long)co * (2 * TT) + row;
                    qt[0] = h0;
                    qt[TT] = l0;
                    qt[2 * TT] = h1;
                    qt[3 * TT] = l1;
                } else {  // EPI == 3
                    float2 gv = *reinterpret_cast<const float2*>(
                        &G[row * (long)ldgt + co]);
                    f0 = fmaxf(f0, 0.f) * gv.x;
                    f1 = fmaxf(f1, 0.f) * gv.y;
                    *reinterpret_cast<uint32_t*>(&Cb[cOff + row * ldc + co]) =
                        pack2(__float2half_rn(f0), __float2half_rn(f1));
                }
            }
        }
    }
}

// ---------------- host launch ----------------
extern "C" void kernel_launch(void* const* d_in, const int* in_sizes, int n_in,
                              void* d_out, int out_size) {
    const int*   input_  = (const int*)d_in[0];
    const float* emb     = (const float*)d_in[1];
    const float* pos     = (const float*)d_in[2];
    const float* Dx      = (const float*)d_in[3];
    const float* Dy      = (const float*)d_in[4];
    const float* E       = (const float*)d_in[5];
    const float* readout = (const float*)d_in[6];
    float* out = (float*)d_out;

    cudaFuncSetAttribute(gemm_mma<0>, cudaFuncAttributeMaxDynamicSharedMemorySize, SMEM_GEMM_BYTES);
    cudaFuncSetAttribute(gemm_mma<2>, cudaFuncAttributeMaxDynamicSharedMemorySize, SMEM_GEMM_BYTES);
    cudaFuncSetAttribute(gemm_mma<3>, cudaFuncAttributeMaxDynamicSharedMemorySize, SMEM_GEMM_BYTES);
    cudaFuncSetAttribute(gemm_mma<4>, cudaFuncAttributeMaxDynamicSharedMemorySize, SMEM_GEMM_BYTES);

    float *v, *x, *a, *yE, *ct, *st;
    __half *v2a, *vT2, *qh, *qT, *wT, *a2, *y2, *Dx2, *Dy2, *E2, *ro2;
    cudaGetSymbolAddress((void**)&v,   g_v);
    cudaGetSymbolAddress((void**)&v2a, g_v2a);
    cudaGetSymbolAddress((void**)&vT2, g_vT2);
    cudaGetSymbolAddress((void**)&x,   g_x);
    cudaGetSymbolAddress((void**)&qh,  g_qh);
    cudaGetSymbolAddress((void**)&qT,  g_qT);
    cudaGetSymbolAddress((void**)&wT,  g_wT);
    cudaGetSymbolAddress((void**)&a,   g_a);
    cudaGetSymbolAddress((void**)&a2,  g_a2);
    cudaGetSymbolAddress((void**)&y2,  g_y2);
    cudaGetSymbolAddress((void**)&yE,  g_yE);
    cudaGetSymbolAddress((void**)&Dx2, g_Dx2);
    cudaGetSymbolAddress((void**)&Dy2, g_Dy2);
    cudaGetSymbolAddress((void**)&E2,  g_E2);
    cudaGetSymbolAddress((void**)&ro2, g_ro2);
    cudaGetSymbolAddress((void**)&ct,  g_cos);
    cudaGetSymbolAddress((void**)&st,  g_sin);

    dim3 tb(32, 8);

    rope_table_kernel<<<(TT * 512 + 255) / 256, 256>>>();
    embed_ln_kernel<<<BB * TT, 256>>>(input_, emb, pos);
    transpose_split_kernel<<<dim3(KK / 32, DD / 32, HH), tb>>>(Dx, Dx2, DD, KK, (long)DD * KK, (long)KK * 2 * DD, 1);
    transpose_split_kernel<<<dim3(KK / 32, DD / 32, HH), tb>>>(Dy, Dy2, DD, KK, (long)DD * KK, (long)KK * 2 * DD, 1);
    transpose_split_kernel<<<dim3(DD / 32, NN_ / 32, 1), tb>>>(E, E2, NN_, DD, 0, 0, 2);
    transpose_split_kernel<<<dim3(BV / 32, DD / 32, 1), tb>>>(readout, ro2, DD, BV, 0, 0, 0);

    const long TK  = (long)TT * KK;
    const long TD  = (long)TT * DD;
    const long TN  = (long)TT * NN_;
    const long QTS = (long)KK * 2 * TT;    // qT per-bh stride
    const long WTS = (long)DD * 2 * KK;    // wT per-bh stride

    for (int l = 0; l < LL; l++) {
        transpose_split_kernel<<<dim3(DD / 32, TT / 32, BB), tb>>>(v, vT2, TT, DD, TD, (long)DD * 2 * TT, 0);

        // x = relu(v2a @ Dx2^T) fp32 gate (permuted) + RoPE -> qh [t,k], qT [k,2t]
        gemm_mma<4><<<dim3(KK / 128, TT / 128, BB * HH), 256, SMEM_GEMM_BYTES>>>(
            v2a, Dx2, x, nullptr,
            DD, DD, DD, 2 * DD, KK, 0, 0,
            TD, 0, 0, (long)KK * 2 * DD, (long)HH * TK, TK, 0, 0, HH, 1, 0,
            qh, qT, ct, st);

        // wT[b,h] = vT_hi @ qT^T (split out) : M=256(d) N=1024(k) Kc=2048(t)
        gemm_mma<2><<<dim3(KK / 128, DD / 128, BB * HH), 256, SMEM_GEMM_BYTES>>>(
            vT2, qT, wT, nullptr,
            TT, TT, 2 * TT, 2 * TT, 2 * KK, 0, KK,
            (long)DD * 2 * TT, 0, (long)HH * QTS, QTS, (long)HH * WTS, WTS, 0, 0, HH, 1, 0,
            nullptr, nullptr, nullptr, nullptr);

        // a[b,h] = qh @ wT^T fp32 : M=2048(t) N=256(d) Kc=1024(k)
        gemm_mma<0><<<dim3(DD / 128, TT / 128, BB * HH), 256, SMEM_GEMM_BYTES>>>(
            qh, wT, a, nullptr,
            KK, KK, KK, 2 * KK, DD, 0, 0,
            (long)HH * TK, TK, (long)HH * WTS, WTS, (long)HH * TD, TD, 0, 0, HH, 1, 0,
            nullptr, nullptr, nullptr, nullptr);

        ln_split_kernel<<<BB * HH * TT, 256>>>();

        // y2[b,t,h*K+n'] = relu(a2 @ Dy2^T) * x (fp16 hi, permuted cols)
        gemm_mma<3><<<dim3(KK / 128, TT / 128, BB * HH), 256, SMEM_GEMM_BYTES>>>(
            a2, Dy2, y2, x,
            DD, DD, DD, 2 * DD, NN_, KK, 0,
            (long)HH * TD, TD, 0, (long)KK * 2 * DD,
            TN, (long)KK, (long)HH * TK, TK, HH, 1, 0,
            nullptr, nullptr, nullptr, nullptr);

        // yE partials = y2 @ E2^T (split-K=4) : M=4096 N=256
        gemm_mma<0><<<dim3(DD / 128, (BB * TT) / 128, 4), 256, SMEM_GEMM_BYTES>>>(
            y2, E2, yE, nullptr,
            NN_ / 4, NN_, NN_, 2 * NN_, DD, 0, 0,
            0, 0, 0, 0, 0, 0, 0, 0, 1, 4, 4096L * 256,
            nullptr, nullptr, nullptr, nullptr);

        combine_split_kernel<<<BB * TT, 256>>>(pos, l < LL - 1 ? 1 : 0);
    }

    // out = v2a @ ro2^T fp32 : M=4096 N=32000 Kd=256
    gemm_mma<0><<<dim3(BV / 128, (BB * TT) / 128, 1), 256, SMEM_GEMM_BYTES>>>(
        v2a, ro2, out, nullptr,
        DD, DD, DD, 2 * DD, BV, 0, 0,
        0, 0, 0, 0, 0, 0, 0, 0, 1, 1, 0,
        nullptr, nullptr, nullptr, nullptr);
}

// round 13
// speedup vs baseline: 5.7969x; 1.4082x over previous
#include <cuda_runtime.h>
#include <cuda_fp16.h>
#include <math.h>
#include <stdint.h>

// ---------------- problem constants ----------------
#define BV   32000
#define TT   2048
#define HH   4
#define NN_  4096
#define DD   256
#define LL   6
#define KK   1024
#define BB   2
#define EPS  1e-5f

// ---------------- device scratch (no mallocs allowed) ----------------
__device__ float  g_v   [4096L*256];
__device__ __half g_v2a [4096L*256];     // [B*T, D] hi
__device__ __half g_vT  [2L*256*2048];   // [B][D, T] hi
__device__ float  g_x   [8L*2048*1024];  // [B,H,T,K] fp32 gate (PERMUTED cols)
__device__ __half g_qh  [8L*2048*1024];  // [B,H,T,K] q hi (PERMUTED cols)
__device__ __half g_qT  [8L*1024*2048];  // [B,H,K,T] q^T hi
__device__ __half g_wT  [8L*256*1024];   // [B,H,D,K] w^T hi, w = q^T v
__device__ float  g_a   [8L*2048*256];
__device__ __half g_a2  [8L*2048*256];   // hi
__device__ __half g_y2  [2L*2048*4096];  // [B,T,N] hi (PERMUTED cols/head)
__device__ float  g_yE  [4L*4096*256];   // 4 split-K partials
__device__ __half g_Dx2 [4L*1024*256];   // [H][K, D] hi (PERMUTED rows)
__device__ __half g_Dy2 [4L*1024*256];
__device__ __half g_E2  [256L*4096];     // [D, N] hi (PERMUTED cols/head)
__device__ __half g_ro2 [32000L*256];    // [V, D] hi
__device__ float  g_cos [2048L*512];     // [T, 512]
__device__ float  g_sin [2048L*512];

// per-head column permutation: k<512 -> 2k ; k>=512 -> 2k-1023
__host__ __device__ __forceinline__ int permk(int k) {
    return (k < 512) ? (2 * k) : (2 * k - 1023);
}

// ---------------- PTX helpers (baseline ISA only: sm_80-class) ----------------
__device__ __forceinline__ uint32_t smem_u32(const void* p) {
    uint32_t a;
    asm("{ .reg .u64 t; cvta.to.shared.u64 t, %1; cvt.u32.u64 %0, t; }" : "=r"(a) : "l"(p));
    return a;
}
#define CP_ASYNC16(saddr, gaddr) \
    asm volatile("cp.async.cg.shared.global [%0], [%1], 16;" :: "r"(saddr), "l"(gaddr))
#define CP_COMMIT() asm volatile("cp.async.commit_group;" ::: "memory")
#define CP_WAIT1()  asm volatile("cp.async.wait_group 1;" ::: "memory")

#define LDSM_X4(r0, r1, r2, r3, addr) \
    asm volatile("ldmatrix.sync.aligned.m8n8.x4.shared.b16 {%0,%1,%2,%3}, [%4];" \
        : "=r"(r0), "=r"(r1), "=r"(r2), "=r"(r3) : "r"(addr))

#define MMA16816(d, a, b0, b1) \
    asm volatile("mma.sync.aligned.m16n8k16.row.col.f32.f16.f16.f32 " \
        "{%0,%1,%2,%3}, {%4,%5,%6,%7}, {%8,%9}, {%0,%1,%2,%3};" \
        : "+f"((d)[0]), "+f"((d)[1]), "+f"((d)[2]), "+f"((d)[3]) \
        : "r"((a)[0]), "r"((a)[1]), "r"((a)[2]), "r"((a)[3]), "r"(b0), "r"(b1))

__device__ __forceinline__ uint32_t pack2(__half a, __half b) {
    return (uint32_t)__half_as_ushort(a) | ((uint32_t)__half_as_ushort(b) << 16);
}

// swizzled smem offset: 64B rows, seg' = seg ^ ((row>>1)&3)
__device__ __forceinline__ uint32_t swz(uint32_t row, uint32_t seg) {
    return row * 64u + (((seg) ^ ((row >> 1) & 3u)) << 4);
}

// ---------------- block reduction (256 threads) ----------------
__device__ __forceinline__ float blockReduceSum256(float val) {
    __shared__ float s[8];
    __shared__ float res;
    int lane = threadIdx.x & 31, w = threadIdx.x >> 5;
    #pragma unroll
    for (int o = 16; o; o >>= 1) val += __shfl_xor_sync(0xffffffffu, val, o);
    if (lane == 0) s[w] = val;
    __syncthreads();
    if (threadIdx.x < 8) {
        float v = s[threadIdx.x];
        #pragma unroll
        for (int o = 4; o; o >>= 1) v += __shfl_xor_sync(0xffu, v, o);
        if (threadIdx.x == 0) res = v;
    }
    __syncthreads();
    float r = res;
    __syncthreads();
    return r;
}

// ---------------- elementwise kernels ----------------
__global__ void rope_table_kernel() {
    long idx = (long)blockIdx.x * blockDim.x + threadIdx.x;
    if (idx >= (long)TT * 512) return;
    int t = (int)(idx >> 9);
    int i = (int)(idx & 511);
    float ex  = (2.0f * (float)i) / (float)KK;
    float inv = 1.0f / powf(10000.0f, ex);
    float th  = (float)t * inv;
    g_cos[idx] = cosf(th);
    g_sin[idx] = sinf(th);
}

__global__ void embed_ln_kernel(const int* __restrict__ input_,
                                const float* __restrict__ emb,
                                const float* __restrict__ pos) {
    int row = blockIdx.x;                 // B*T
    int t = row & (TT - 1);
    int tok = input_[row];
    float x = emb[(long)tok * DD + threadIdx.x];
    float mu = blockReduceSum256(x) * (1.0f / DD);
    float d = x - mu;
    float var = blockReduceSum256(d * d) * (1.0f / DD);
    float f = d * rsqrtf(var + EPS) + pos[(long)t * DD + threadIdx.x];
    g_v[(long)row * DD + threadIdx.x] = f;
    g_v2a[(long)row * DD + threadIdx.x] = __float2half_rn(f);
}

__global__ void combine_split_kernel(const float* __restrict__ pos, int do_pos) {
    long row = blockIdx.x;                 // B*T
    const long P = 4096L * 256;
    float u = g_yE[row * DD + threadIdx.x] + g_yE[P + row * DD + threadIdx.x] +
              g_yE[2 * P + row * DD + threadIdx.x] + g_yE[3 * P + row * DD + threadIdx.x];
    float mu = blockReduceSum256(u) * (1.0f / DD);
    float d = u - mu;
    float var = blockReduceSum256(d * d) * (1.0f / DD);
    float w = g_v[row * DD + threadIdx.x] + d * rsqrtf(var + EPS);
    float mu2 = blockReduceSum256(w) * (1.0f / DD);
    float d2 = w - mu2;
    float var2 = blockReduceSum256(d2 * d2) * (1.0f / DD);
    float f = d2 * rsqrtf(var2 + EPS);
    if (do_pos) {
        int t = (int)(row & (TT - 1));
        f += pos[(long)t * DD + threadIdx.x];
    }
    g_v[row * DD + threadIdx.x] = f;
    g_v2a[row * DD + threadIdx.x] = __float2half_rn(f);
}

__global__ void ln_split_kernel() {
    long row = blockIdx.x;                 // B*H*T
    float x = g_a[row * DD + threadIdx.x];
    float mu = blockReduceSum256(x) * (1.0f / DD);
    float d = x - mu;
    float var = blockReduceSum256(d * d) * (1.0f / DD);
    float f = d * rsqrtf(var + EPS);
    g_a2[row * DD + threadIdx.x] = __float2half_rn(f);
}

// X [R,C] fp32 -> Y [C, R] fp16 hi
// PERM: 0 = none; 1 = permute OUT-ROW (X column) per 1024-block;
//       2 = permute OUT-COL (X row) per 1024-block.
__global__ void transpose_half_kernel(const float* __restrict__ X,
                                      __half* __restrict__ Y,
                                      int R, int C, long inZ, long outZ, int PERM) {
    __shared__ float tile[32][33];
    X += (long)blockIdx.z * inZ;
    Y += (long)blockIdx.z * outZ;
    int r0 = blockIdx.y * 32, c0 = blockIdx.x * 32;
    int tx = threadIdx.x, ty = threadIdx.y;   // (32,8)
    #pragma unroll
    for (int i = 0; i < 32; i += 8)
        tile[ty + i][tx] = X[(long)(r0 + ty + i) * C + c0 + tx];
    __syncthreads();
    #pragma unroll
    for (int i = 0; i < 32; i += 8) {
        float f = tile[tx][ty + i];           // X[r0+tx][c0+ty+i]
        int orowi = c0 + ty + i;
        int ocol  = r0 + tx;
        if (PERM == 1) {
            int blk = orowi & ~1023;
            orowi = blk + permk(orowi & 1023);
        } else if (PERM == 2) {
            int blk = ocol & ~1023;
            ocol = blk + permk(ocol & 1023);
        }
        Y[(long)orowi * R + ocol] = __float2half_rn(f);
    }
}

// ---------------- mma.sync GEMM (HMMA fp16 single-pass hi x hi) ----------------
// C[M,N] = Ah[M,K] x Bh[N,K]^T, fp32 accum.
// CTA tile 128x128, 3-stage cp.async pipeline (stage = 2 x 8192B = 16KB),
// XOR-swizzled 64B smem rows, single __syncthreads per chunk.
// 8 warps 2(m) x 4(n), warp tile 64x32.
// EPI: 0=fp32, 1=fp16 hi, 3=relu*G -> fp16 hi,
//      4=relu fp32 gate + fused RoPE -> qh [t,k] + qT [k,t] (fp16 hi)
// Split-K: nsplit partials, sp = blockIdx.z % nsplit.
#define OPER_BYTES 8192                    // 128 rows x 64B
#define STAGE_BYTES (2 * OPER_BYTES)       // 16384: Ah|Bh
#define SMEM_GEMM_BYTES (3 * STAGE_BYTES)  // 49152

template<int EPI>
__global__ void __launch_bounds__(256, 2)
gemm_mma(const __half* __restrict__ A, const __half* __restrict__ B,
         void* __restrict__ Cv, const float* __restrict__ G,
         int Kd, int lda, int ldb, int ldc, int ldgt,
         long sAb, long sAh, long sBb, long sBh, long sCb, long sCh,
         long sGb, long sGh, int Hdim, int nsplit, long sSplitC,
         __half* __restrict__ Qh, __half* __restrict__ QT,
         const float* __restrict__ CT, const float* __restrict__ ST)
{
    extern __shared__ char dsm[];
    uint32_t sbase = smem_u32(dsm);

    int tid = threadIdx.x;
    int lane = tid & 31;
    int wid = tid >> 5;
    int wm = wid >> 2;        // 0..1
    int wn = wid & 3;         // 0..3

    int zz = blockIdx.z;
    int sp = 0, z = zz;
    if (nsplit > 1) { sp = zz % nsplit; z = zz / nsplit; }
    int bb = z / Hdim, hh = z - bb * Hdim;
    A += bb * sAb + hh * sAh;
    B += bb * sBb + hh * sBh;
    long cOff = bb * sCb + hh * sCh + sp * sSplitC;
    if (EPI == 3) G += bb * sGb + hh * sGh;
    long qhOff = 0, qtOff = 0;
    if (EPI == 4) {
        qhOff = (long)z * ((long)TT * KK);
        qtOff = (long)z * ((long)KK * TT);
    }

    int m0 = blockIdx.y * 128;
    int n0 = blockIdx.x * 128;

    const int KC = Kd >> 5;       // 32-wide chunks
    const int spK = sp * Kd;

    int lrow = tid >> 2;          // 0..63
    int lseg = tid & 3;

    auto issue = [&](int cc) {
        int koff = spK + (cc << 5);
        uint32_t st = sbase + (cc % 3) * STAGE_BYTES;
        #pragma unroll
        for (int i = 0; i < 2; i++) {
            uint32_t row = lrow + i * 64;
            uint32_t so = swz(row, (uint32_t)lseg);
            long go = lseg * 8;
            const __half* ga = A + (long)(m0 + row) * lda + koff + go;
            const __half* gb = B + (long)(n0 + row) * ldb + koff + go;
            CP_ASYNC16(st + so,              ga);
            CP_ASYNC16(st + OPER_BYTES + so, gb);
        }
    };

    float acc[4][4][4];
    #pragma unroll
    for (int i = 0; i < 4; i++)
        #pragma unroll
        for (int j = 0; j < 4; j++)
            #pragma unroll
            for (int r = 0; r < 4; r++) acc[i][j][r] = 0.0f;

    issue(0); CP_COMMIT();
    issue(1); CP_COMMIT();

    int rsel = lane & 15;
    int hi16 = lane >> 4;         // 0 or 1: second 16B seg of the k16 block

    for (int c = 0; c < KC; c++) {
        CP_WAIT1();              // chunk c data complete
        __syncthreads();         // copies visible; compute c-1 done

        uint32_t sah = sbase + (c % 3) * STAGE_BYTES;
        uint32_t sbh = sah + OPER_BYTES;

        #pragma unroll
        for (int ks = 0; ks < 2; ks++) {
            uint32_t segb = (uint32_t)(ks * 2 + hi16);
            uint32_t ar[4][4], br[2][4];
            #pragma unroll
            for (int n2 = 0; n2 < 2; n2++) {
                uint32_t row = (uint32_t)(wn * 32 + n2 * 16 + rsel);
                LDSM_X4(br[n2][0], br[n2][1], br[n2][2], br[n2][3], sbh + swz(row, segb));
            }
            #pragma unroll
            for (int mt = 0; mt < 4; mt++) {
                uint32_t row = (uint32_t)(wm * 64 + mt * 16 + rsel);
                LDSM_X4(ar[mt][0], ar[mt][1], ar[mt][2], ar[mt][3], sah + swz(row, segb));
            }
            #pragma unroll
            for (int mt = 0; mt < 4; mt++)
                #pragma unroll
                for (int nt = 0; nt < 4; nt++) {
                    int n2 = nt >> 1, j = nt & 1;
                    MMA16816(acc[mt][nt], ar[mt], br[n2][j], br[n2][2 + j]);
                }
            // hide next-chunk copy issue under the tensor-pipe shadow
            if (ks == 0) {
                if (c + 2 < KC) issue(c + 2);
                CP_COMMIT();
            }
        }
    }

    // ---------------- epilogue ----------------
    int g = lane >> 2, tg = lane & 3;
    float* Cf = (float*)Cv;
    __half* Cb = (__half*)Cv;

    #pragma unroll
    for (int mt = 0; mt < 4; mt++) {
        #pragma unroll
        for (int half = 0; half < 2; half++) {
            long row = m0 + wm * 64 + mt * 16 + g + half * 8;
            #pragma unroll
            for (int nt = 0; nt < 4; nt++) {
                int co = n0 + wn * 32 + nt * 8 + tg * 2;
                float f0 = acc[mt][nt][half * 2 + 0];
                float f1 = acc[mt][nt][half * 2 + 1];
                if (EPI == 0) {
                    *reinterpret_cast<float2*>(&Cf[cOff + row * ldc + co]) =
                        make_float2(f0, f1);
                } else if (EPI == 1) {
                    *reinterpret_cast<uint32_t*>(&Cb[cOff + row * ldc + co]) =
                        pack2(__float2half_rn(f0), __float2half_rn(f1));
                } else if (EPI == 4) {
                    f0 = fmaxf(f0, 0.f);
                    f1 = fmaxf(f1, 0.f);
                    *reinterpret_cast<float2*>(&Cf[cOff + row * ldc + co]) =
                        make_float2(f0, f1);
                    // RoPE: pair (co, co+1) = original (i, i+512), i = co/2
                    int i = co >> 1;
                    long tb = row * 512 + i;   // row == t
                    float cv = CT[tb], sv = ST[tb];
                    float qa = f0 * cv - f1 * sv;
                    float qb = f1 * cv + f0 * sv;
                    __half h0 = __float2half_rn(qa);
                    __half h1 = __float2half_rn(qb);
                    *reinterpret_cast<uint32_t*>(&Qh[qhOff + row * KK + co]) = pack2(h0, h1);
                    __half* qt = QT + qtOff + (long)co * TT + row;
                    qt[0]  = h0;
                    qt[TT] = h1;
                } else {  // EPI == 3
                    float2 gv = *reinterpret_cast<const float2*>(
                        &G[row * (long)ldgt + co]);
                    f0 = fmaxf(f0, 0.f) * gv.x;
                    f1 = fmaxf(f1, 0.f) * gv.y;
                    *reinterpret_cast<uint32_t*>(&Cb[cOff + row * ldc + co]) =
                        pack2(__float2half_rn(f0), __float2half_rn(f1));
                }
            }
        }
    }
}

// ---------------- host launch ----------------
extern "C" void kernel_launch(void* const* d_in, const int* in_sizes, int n_in,
                              void* d_out, int out_size) {
    const int*   input_  = (const int*)d_in[0];
    const float* emb     = (const float*)d_in[1];
    const float* pos     = (const float*)d_in[2];
    const float* Dx      = (const float*)d_in[3];
    const float* Dy      = (const float*)d_in[4];
    const float* E       = (const float*)d_in[5];
    const float* readout = (const float*)d_in[6];
    float* out = (float*)d_out;

    cudaFuncSetAttribute(gemm_mma<0>, cudaFuncAttributeMaxDynamicSharedMemorySize, SMEM_GEMM_BYTES);
    cudaFuncSetAttribute(gemm_mma<1>, cudaFuncAttributeMaxDynamicSharedMemorySize, SMEM_GEMM_BYTES);
    cudaFuncSetAttribute(gemm_mma<3>, cudaFuncAttributeMaxDynamicSharedMemorySize, SMEM_GEMM_BYTES);
    cudaFuncSetAttribute(gemm_mma<4>, cudaFuncAttributeMaxDynamicSharedMemorySize, SMEM_GEMM_BYTES);

    float *v, *x, *a, *yE, *ct, *st;
    __half *v2a, *vT, *qh, *qT, *wT, *a2, *y2, *Dx2, *Dy2, *E2, *ro2;
    cudaGetSymbolAddress((void**)&v,   g_v);
    cudaGetSymbolAddress((void**)&v2a, g_v2a);
    cudaGetSymbolAddress((void**)&vT,  g_vT);
    cudaGetSymbolAddress((void**)&x,   g_x);
    cudaGetSymbolAddress((void**)&qh,  g_qh);
    cudaGetSymbolAddress((void**)&qT,  g_qT);
    cudaGetSymbolAddress((void**)&wT,  g_wT);
    cudaGetSymbolAddress((void**)&a,   g_a);
    cudaGetSymbolAddress((void**)&a2,  g_a2);
    cudaGetSymbolAddress((void**)&y2,  g_y2);
    cudaGetSymbolAddress((void**)&yE,  g_yE);
    cudaGetSymbolAddress((void**)&Dx2, g_Dx2);
    cudaGetSymbolAddress((void**)&Dy2, g_Dy2);
    cudaGetSymbolAddress((void**)&E2,  g_E2);
    cudaGetSymbolAddress((void**)&ro2, g_ro2);
    cudaGetSymbolAddress((void**)&ct,  g_cos);
    cudaGetSymbolAddress((void**)&st,  g_sin);

    dim3 tb(32, 8);

    rope_table_kernel<<<(TT * 512 + 255) / 256, 256>>>();
    embed_ln_kernel<<<BB * TT, 256>>>(input_, emb, pos);
    transpose_half_kernel<<<dim3(KK / 32, DD / 32, HH), tb>>>(Dx, Dx2, DD, KK, (long)DD * KK, (long)KK * DD, 1);
    transpose_half_kernel<<<dim3(KK / 32, DD / 32, HH), tb>>>(Dy, Dy2, DD, KK, (long)DD * KK, (long)KK * DD, 1);
    transpose_half_kernel<<<dim3(DD / 32, NN_ / 32, 1), tb>>>(E, E2, NN_, DD, 0, 0, 2);
    transpose_half_kernel<<<dim3(BV / 32, DD / 32, 1), tb>>>(readout, ro2, DD, BV, 0, 0, 0);

    const long TK  = (long)TT * KK;
    const long TD  = (long)TT * DD;
    const long TN  = (long)TT * NN_;
    const long QTS = (long)KK * TT;        // qT per-bh stride
    const long WTS = (long)DD * KK;        // wT per-bh stride

    for (int l = 0; l < LL; l++) {
        transpose_half_kernel<<<dim3(DD / 32, TT / 32, BB), tb>>>(v, vT, TT, DD, TD, (long)DD * TT, 0);

        // x = relu(v2a @ Dx2^T) fp32 gate (permuted) + RoPE -> qh [t,k], qT [k,t]
        gemm_mma<4><<<dim3(KK / 128, TT / 128, BB * HH), 256, SMEM_GEMM_BYTES>>>(
            v2a, Dx2, x, nullptr,
            DD, DD, DD, KK, 0,
            TD, 0, 0, (long)KK * DD, (long)HH * TK, TK, 0, 0, HH, 1, 0,
            qh, qT, ct, st);

        // wT[b,h] = vT @ qT^T (fp16 hi) : M=256(d) N=1024(k) Kc=2048(t)
        gemm_mma<1><<<dim3(KK / 128, DD / 128, BB * HH), 256, SMEM_GEMM_BYTES>>>(
            vT, qT, wT, nullptr,
            TT, TT, TT, KK, 0,
            (long)DD * TT, 0, (long)HH * QTS, QTS, (long)HH * WTS, WTS, 0, 0, HH, 1, 0,
            nullptr, nullptr, nullptr, nullptr);

        // a[b,h] = qh @ wT^T fp32 : M=2048(t) N=256(d) Kc=1024(k)
        gemm_mma<0><<<dim3(DD / 128, TT / 128, BB * HH), 256, SMEM_GEMM_BYTES>>>(
            qh, wT, a, nullptr,
            KK, KK, KK, DD, 0,
            (long)HH * TK, TK, (long)HH * WTS, WTS, (long)HH * TD, TD, 0, 0, HH, 1, 0,
            nullptr, nullptr, nullptr, nullptr);

        ln_split_kernel<<<BB * HH * TT, 256>>>();

        // y2[b,t,h*K+n'] = relu(a2 @ Dy2^T) * x (fp16 hi, permuted cols)
        gemm_mma<3><<<dim3(KK / 128, TT / 128, BB * HH), 256, SMEM_GEMM_BYTES>>>(
            a2, Dy2, y2, x,
            DD, DD, DD, NN_, KK,
            (long)HH * TD, TD, 0, (long)KK * DD,
            TN, (long)KK, (long)HH * TK, TK, HH, 1, 0,
            nullptr, nullptr, nullptr, nullptr);

        // yE partials = y2 @ E2^T (split-K=4) : M=4096 N=256
        gemm_mma<0><<<dim3(DD / 128, (BB * TT) / 128, 4), 256, SMEM_GEMM_BYTES>>>(
            y2, E2, yE, nullptr,
            NN_ / 4, NN_, NN_, DD, 0,
            0, 0, 0, 0, 0, 0, 0, 0, 1, 4, 4096L * 256,
            nullptr, nullptr, nullptr, nullptr);

        combine_split_kernel<<<BB * TT, 256>>>(pos, l < LL - 1 ? 1 : 0);
    }

    // out = v2a @ ro2^T fp32 : M=4096 N=32000 Kd=256
    gemm_mma<0><<<dim3(BV / 128, (BB * TT) / 128, 1), 256, SMEM_GEMM_BYTES>>>(
        v2a, ro2, out, nullptr,
        DD, DD, DD, BV, 0,
        0, 0, 0, 0, 0, 0, 0, 0, 1, 1, 0,
        nullptr, nullptr, nullptr, nullptr);
}

// round 14
// speedup vs baseline: 5.8341x; 1.0064x over previous
#include <cuda_runtime.h>
#include <cuda_fp16.h>
#include <math.h>
#include <stdint.h>

// ---------------- problem constants ----------------
#define BV   32000
#define TT   2048
#define HH   4
#define NN_  4096
#define DD   256
#define LL   6
#define KK   1024
#define BB   2
#define EPS  1e-5f

// ---------------- device scratch (no mallocs allowed) ----------------
__device__ float  g_v   [4096L*256];
__device__ __half g_v2a [4096L*256];     // [B*T, D] hi
__device__ __half g_vT  [2L*256*2048];   // [B][D, T] hi
__device__ float  g_x   [8L*2048*1024];  // [B,H,T,K] fp32 gate (PERMUTED cols)
__device__ __half g_qh  [8L*2048*1024];  // [B,H,T,K] q hi (PERMUTED cols)
__device__ __half g_qT  [8L*1024*2048];  // [B,H,K,T] q^T hi
__device__ float  g_wP  [2L*8*256*1024]; // wGEMM split-K partials (fp32)
__device__ __half g_wT  [8L*256*1024];   // [B,H,D,K] w^T hi, w = q^T v
__device__ float  g_a   [8L*2048*256];
__device__ __half g_a2  [8L*2048*256];   // hi
__device__ __half g_y2  [2L*2048*4096];  // [B,T,N] hi (PERMUTED cols/head)
__device__ float  g_yE  [4L*4096*256];   // 4 split-K partials
__device__ __half g_Dx2 [4L*1024*256];   // [H][K, D] hi (PERMUTED rows)
__device__ __half g_Dy2 [4L*1024*256];
__device__ __half g_E2  [256L*4096];     // [D, N] hi (PERMUTED cols/head)
__device__ __half g_ro2 [32000L*256];    // [V, D] hi
__device__ float  g_cos [2048L*512];     // [T, 512]
__device__ float  g_sin [2048L*512];

// per-head column permutation: k<512 -> 2k ; k>=512 -> 2k-1023
__host__ __device__ __forceinline__ int permk(int k) {
    return (k < 512) ? (2 * k) : (2 * k - 1023);
}

// ---------------- PTX helpers (baseline ISA only: sm_80-class) ----------------
__device__ __forceinline__ uint32_t smem_u32(const void* p) {
    uint32_t a;
    asm("{ .reg .u64 t; cvta.to.shared.u64 t, %1; cvt.u32.u64 %0, t; }" : "=r"(a) : "l"(p));
    return a;
}
#define CP_ASYNC16(saddr, gaddr) \
    asm volatile("cp.async.cg.shared.global [%0], [%1], 16;" :: "r"(saddr), "l"(gaddr))
#define CP_COMMIT() asm volatile("cp.async.commit_group;" ::: "memory")
#define CP_WAIT1()  asm volatile("cp.async.wait_group 1;" ::: "memory")

#define LDSM_X4(r0, r1, r2, r3, addr) \
    asm volatile("ldmatrix.sync.aligned.m8n8.x4.shared.b16 {%0,%1,%2,%3}, [%4];" \
        : "=r"(r0), "=r"(r1), "=r"(r2), "=r"(r3) : "r"(addr))

#define MMA16816(d, a, b0, b1) \
    asm volatile("mma.sync.aligned.m16n8k16.row.col.f32.f16.f16.f32 " \
        "{%0,%1,%2,%3}, {%4,%5,%6,%7}, {%8,%9}, {%0,%1,%2,%3};" \
        : "+f"((d)[0]), "+f"((d)[1]), "+f"((d)[2]), "+f"((d)[3]) \
        : "r"((a)[0]), "r"((a)[1]), "r"((a)[2]), "r"((a)[3]), "r"(b0), "r"(b1))

__device__ __forceinline__ uint32_t pack2(__half a, __half b) {
    return (uint32_t)__half_as_ushort(a) | ((uint32_t)__half_as_ushort(b) << 16);
}

// swizzled smem offset: 64B rows, seg' = seg ^ ((row>>1)&3)
__device__ __forceinline__ uint32_t swz(uint32_t row, uint32_t seg) {
    return row * 64u + (((seg) ^ ((row >> 1) & 3u)) << 4);
}

// ---------------- block reduction (256 threads) ----------------
__device__ __forceinline__ float blockReduceSum256(float val) {
    __shared__ float s[8];
    __shared__ float res;
    int lane = threadIdx.x & 31, w = threadIdx.x >> 5;
    #pragma unroll
    for (int o = 16; o; o >>= 1) val += __shfl_xor_sync(0xffffffffu, val, o);
    if (lane == 0) s[w] = val;
    __syncthreads();
    if (threadIdx.x < 8) {
        float v = s[threadIdx.x];
        #pragma unroll
        for (int o = 4; o; o >>= 1) v += __shfl_xor_sync(0xffu, v, o);
        if (threadIdx.x == 0) res = v;
    }
    __syncthreads();
    float r = res;
    __syncthreads();
    return r;
}

// ---------------- elementwise kernels ----------------
__global__ void rope_table_kernel() {
    long idx = (long)blockIdx.x * blockDim.x + threadIdx.x;
    if (idx >= (long)TT * 512) return;
    int t = (int)(idx >> 9);
    int i = (int)(idx & 511);
    float ex  = (2.0f * (float)i) / (float)KK;
    float inv = 1.0f / powf(10000.0f, ex);
    float th  = (float)t * inv;
    g_cos[idx] = cosf(th);
    g_sin[idx] = sinf(th);
}

__global__ void embed_ln_kernel(const int* __restrict__ input_,
                                const float* __restrict__ emb,
                                const float* __restrict__ pos) {
    int row = blockIdx.x;                 // B*T
    int t = row & (TT - 1);
    int tok = input_[row];
    float x = emb[(long)tok * DD + threadIdx.x];
    float mu = blockReduceSum256(x) * (1.0f / DD);
    float d = x - mu;
    float var = blockReduceSum256(d * d) * (1.0f / DD);
    float f = d * rsqrtf(var + EPS) + pos[(long)t * DD + threadIdx.x];
    g_v[(long)row * DD + threadIdx.x] = f;
    g_v2a[(long)row * DD + threadIdx.x] = __float2half_rn(f);
}

__global__ void combine_split_kernel(const float* __restrict__ pos, int do_pos) {
    long row = blockIdx.x;                 // B*T
    const long P = 4096L * 256;
    float u = g_yE[row * DD + threadIdx.x] + g_yE[P + row * DD + threadIdx.x] +
              g_yE[2 * P + row * DD + threadIdx.x] + g_yE[3 * P + row * DD + threadIdx.x];
    float mu = blockReduceSum256(u) * (1.0f / DD);
    float d = u - mu;
    float var = blockReduceSum256(d * d) * (1.0f / DD);
    float w = g_v[row * DD + threadIdx.x] + d * rsqrtf(var + EPS);
    float mu2 = blockReduceSum256(w) * (1.0f / DD);
    float d2 = w - mu2;
    float var2 = blockReduceSum256(d2 * d2) * (1.0f / DD);
    float f = d2 * rsqrtf(var2 + EPS);
    if (do_pos) {
        int t = (int)(row & (TT - 1));
        f += pos[(long)t * DD + threadIdx.x];
    }
    g_v[row * DD + threadIdx.x] = f;
    g_v2a[row * DD + threadIdx.x] = __float2half_rn(f);
}

__global__ void ln_split_kernel() {
    long row = blockIdx.x;                 // B*H*T
    float x = g_a[row * DD + threadIdx.x];
    float mu = blockReduceSum256(x) * (1.0f / DD);
    float d = x - mu;
    float var = blockReduceSum256(d * d) * (1.0f / DD);
    float f = d * rsqrtf(var + EPS);
    g_a2[row * DD + threadIdx.x] = __float2half_rn(f);
}

// wT = fp16(wP[0] + wP[1])   (2M elements)
__global__ void wsum_kernel() {
    const long N2 = 8L * 256 * 1024;
    long idx = (long)blockIdx.x * blockDim.x + threadIdx.x;
    if (idx >= N2) return;
    g_wT[idx] = __float2half_rn(g_wP[idx] + g_wP[idx + N2]);
}

// X [R,C] fp32 -> Y [C, R] fp16 hi
// PERM: 0 = none; 1 = permute OUT-ROW (X column) per 1024-block;
//       2 = permute OUT-COL (X row) per 1024-block.
__global__ void transpose_half_kernel(const float* __restrict__ X,
                                      __half* __restrict__ Y,
                                      int R, int C, long inZ, long outZ, int PERM) {
    __shared__ float tile[32][33];
    X += (long)blockIdx.z * inZ;
    Y += (long)blockIdx.z * outZ;
    int r0 = blockIdx.y * 32, c0 = blockIdx.x * 32;
    int tx = threadIdx.x, ty = threadIdx.y;   // (32,8)
    #pragma unroll
    for (int i = 0; i < 32; i += 8)
        tile[ty + i][tx] = X[(long)(r0 + ty + i) * C + c0 + tx];
    __syncthreads();
    #pragma unroll
    for (int i = 0; i < 32; i += 8) {
        float f = tile[tx][ty + i];           // X[r0+tx][c0+ty+i]
        int orowi = c0 + ty + i;
        int ocol  = r0 + tx;
        if (PERM == 1) {
            int blk = orowi & ~1023;
            orowi = blk + permk(orowi & 1023);
        } else if (PERM == 2) {
            int blk = ocol & ~1023;
            ocol = blk + permk(ocol & 1023);
        }
        Y[(long)orowi * R + ocol] = __float2half_rn(f);
    }
}

// ---------------- mma.sync GEMM (HMMA fp16 single-pass hi x hi) ----------------
// C[M,N] = Ah[M,K] x Bh[N,K]^T, fp32 accum.
// CTA tile 128x128, 3-stage cp.async pipeline (stage = 2 x 8192B = 16KB),
// XOR-swizzled 64B smem rows, single __syncthreads per chunk.
// 8 warps 2(m) x 4(n), warp tile 64x32.
// EPI: 0=fp32, 1=fp16 hi, 3=relu*G -> fp16 hi,
//      4=relu fp32 gate + fused RoPE -> qh [t,k] + qT [k,t] (fp16 hi)
// Split-K: nsplit partials, sp = blockIdx.z % nsplit.
#define OPER_BYTES 8192                    // 128 rows x 64B
#define STAGE_BYTES (2 * OPER_BYTES)       // 16384: Ah|Bh
#define SMEM_GEMM_BYTES (3 * STAGE_BYTES)  // 49152

template<int EPI>
__global__ void __launch_bounds__(256, 2)
gemm_mma(const __half* __restrict__ A, const __half* __restrict__ B,
         void* __restrict__ Cv, const float* __restrict__ G,
         int Kd, int lda, int ldb, int ldc, int ldgt,
         long sAb, long sAh, long sBb, long sBh, long sCb, long sCh,
         long sGb, long sGh, int Hdim, int nsplit, long sSplitC,
         __half* __restrict__ Qh, __half* __restrict__ QT,
         const float* __restrict__ CT, const float* __restrict__ ST)
{
    extern __shared__ char dsm[];
    uint32_t sbase = smem_u32(dsm);

    int tid = threadIdx.x;
    int lane = tid & 31;
    int wid = tid >> 5;
    int wm = wid >> 2;        // 0..1
    int wn = wid & 3;         // 0..3

    int zz = blockIdx.z;
    int sp = 0, z = zz;
    if (nsplit > 1) { sp = zz % nsplit; z = zz / nsplit; }
    int bb = z / Hdim, hh = z - bb * Hdim;
    A += bb * sAb + hh * sAh;
    B += bb * sBb + hh * sBh;
    long cOff = bb * sCb + hh * sCh + sp * sSplitC;
    if (EPI == 3) G += bb * sGb + hh * sGh;
    long qhOff = 0, qtOff = 0;
    if (EPI == 4) {
        qhOff = (long)z * ((long)TT * KK);
        qtOff = (long)z * ((long)KK * TT);
    }

    int m0 = blockIdx.y * 128;
    int n0 = blockIdx.x * 128;

    const int KC = Kd >> 5;       // 32-wide chunks
    const int spK = sp * Kd;

    int lrow = tid >> 2;          // 0..63
    int lseg = tid & 3;

    auto issue = [&](int cc) {
        int koff = spK + (cc << 5);
        uint32_t st = sbase + (cc % 3) * STAGE_BYTES;
        #pragma unroll
        for (int i = 0; i < 2; i++) {
            uint32_t row = lrow + i * 64;
            uint32_t so = swz(row, (uint32_t)lseg);
            long go = lseg * 8;
            const __half* ga = A + (long)(m0 + row) * lda + koff + go;
            const __half* gb = B + (long)(n0 + row) * ldb + koff + go;
            CP_ASYNC16(st + so,              ga);
            CP_ASYNC16(st + OPER_BYTES + so, gb);
        }
    };

    float acc[4][4][4];
    #pragma unroll
    for (int i = 0; i < 4; i++)
        #pragma unroll
        for (int j = 0; j < 4; j++)
            #pragma unroll
            for (int r = 0; r < 4; r++) acc[i][j][r] = 0.0f;

    issue(0); CP_COMMIT();
    issue(1); CP_COMMIT();

    int rsel = lane & 15;
    int hi16 = lane >> 4;         // 0 or 1: second 16B seg of the k16 block

    for (int c = 0; c < KC; c++) {
        CP_WAIT1();              // chunk c data complete
        __syncthreads();         // copies visible; compute c-1 done

        uint32_t sah = sbase + (c % 3) * STAGE_BYTES;
        uint32_t sbh = sah + OPER_BYTES;

        #pragma unroll
        for (int ks = 0; ks < 2; ks++) {
            uint32_t segb = (uint32_t)(ks * 2 + hi16);
            uint32_t ar[4][4], br[2][4];
            #pragma unroll
            for (int n2 = 0; n2 < 2; n2++) {
                uint32_t row = (uint32_t)(wn * 32 + n2 * 16 + rsel);
                LDSM_X4(br[n2][0], br[n2][1], br[n2][2], br[n2][3], sbh + swz(row, segb));
            }
            #pragma unroll
            for (int mt = 0; mt < 4; mt++) {
                uint32_t row = (uint32_t)(wm * 64 + mt * 16 + rsel);
                LDSM_X4(ar[mt][0], ar[mt][1], ar[mt][2], ar[mt][3], sah + swz(row, segb));
            }
            #pragma unroll
            for (int mt = 0; mt < 4; mt++)
                #pragma unroll
                for (int nt = 0; nt < 4; nt++) {
                    int n2 = nt >> 1, j = nt & 1;
                    MMA16816(acc[mt][nt], ar[mt], br[n2][j], br[n2][2 + j]);
                }
            // hide next-chunk copy issue under the tensor-pipe shadow
            if (ks == 0) {
                if (c + 2 < KC) issue(c + 2);
                CP_COMMIT();
            }
        }
    }

    // ---------------- epilogue ----------------
    int g = lane >> 2, tg = lane & 3;
    float* Cf = (float*)Cv;
    __half* Cb = (__half*)Cv;

    #pragma unroll
    for (int mt = 0; mt < 4; mt++) {
        #pragma unroll
        for (int half = 0; half < 2; half++) {
            long row = m0 + wm * 64 + mt * 16 + g + half * 8;
            #pragma unroll
            for (int nt = 0; nt < 4; nt++) {
                int co = n0 + wn * 32 + nt * 8 + tg * 2;
                float f0 = acc[mt][nt][half * 2 + 0];
                float f1 = acc[mt][nt][half * 2 + 1];
                if (EPI == 0) {
                    *reinterpret_cast<float2*>(&Cf[cOff + row * ldc + co]) =
                        make_float2(f0, f1);
                } else if (EPI == 1) {
                    *reinterpret_cast<uint32_t*>(&Cb[cOff + row * ldc + co]) =
                        pack2(__float2half_rn(f0), __float2half_rn(f1));
                } else if (EPI == 4) {
                    f0 = fmaxf(f0, 0.f);
                    f1 = fmaxf(f1, 0.f);
                    *reinterpret_cast<float2*>(&Cf[cOff + row * ldc + co]) =
                        make_float2(f0, f1);
                    // RoPE: pair (co, co+1) = original (i, i+512), i = co/2
                    int i = co >> 1;
                    long tb = row * 512 + i;   // row == t
                    float cv = CT[tb], sv = ST[tb];
                    float qa = f0 * cv - f1 * sv;
                    float qb = f1 * cv + f0 * sv;
                    __half h0 = __float2half_rn(qa);
                    __half h1 = __float2half_rn(qb);
                    *reinterpret_cast<uint32_t*>(&Qh[qhOff + row * KK + co]) = pack2(h0, h1);
                    __half* qt = QT + qtOff + (long)co * TT + row;
                    qt[0]  = h0;
                    qt[TT] = h1;
                } else {  // EPI == 3
                    float2 gv = *reinterpret_cast<const float2*>(
                        &G[row * (long)ldgt + co]);
                    f0 = fmaxf(f0, 0.f) * gv.x;
                    f1 = fmaxf(f1, 0.f) * gv.y;
                    *reinterpret_cast<uint32_t*>(&Cb[cOff + row * ldc + co]) =
                        pack2(__float2half_rn(f0), __float2half_rn(f1));
                }
            }
        }
    }
}

// ---------------- host launch ----------------
extern "C" void kernel_launch(void* const* d_in, const int* in_sizes, int n_in,
                              void* d_out, int out_size) {
    const int*   input_  = (const int*)d_in[0];
    const float* emb     = (const float*)d_in[1];
    const float* pos     = (const float*)d_in[2];
    const float* Dx      = (const float*)d_in[3];
    const float* Dy      = (const float*)d_in[4];
    const float* E       = (const float*)d_in[5];
    const float* readout = (const float*)d_in[6];
    float* out = (float*)d_out;

    cudaFuncSetAttribute(gemm_mma<0>, cudaFuncAttributeMaxDynamicSharedMemorySize, SMEM_GEMM_BYTES);
    cudaFuncSetAttribute(gemm_mma<1>, cudaFuncAttributeMaxDynamicSharedMemorySize, SMEM_GEMM_BYTES);
    cudaFuncSetAttribute(gemm_mma<3>, cudaFuncAttributeMaxDynamicSharedMemorySize, SMEM_GEMM_BYTES);
    cudaFuncSetAttribute(gemm_mma<4>, cudaFuncAttributeMaxDynamicSharedMemorySize, SMEM_GEMM_BYTES);

    float *v, *x, *a, *yE, *ct, *st, *wP;
    __half *v2a, *vT, *qh, *qT, *wT, *a2, *y2, *Dx2, *Dy2, *E2, *ro2;
    cudaGetSymbolAddress((void**)&v,   g_v);
    cudaGetSymbolAddress((void**)&v2a, g_v2a);
    cudaGetSymbolAddress((void**)&vT,  g_vT);
    cudaGetSymbolAddress((void**)&x,   g_x);
    cudaGetSymbolAddress((void**)&qh,  g_qh);
    cudaGetSymbolAddress((void**)&qT,  g_qT);
    cudaGetSymbolAddress((void**)&wP,  g_wP);
    cudaGetSymbolAddress((void**)&wT,  g_wT);
    cudaGetSymbolAddress((void**)&a,   g_a);
    cudaGetSymbolAddress((void**)&a2,  g_a2);
    cudaGetSymbolAddress((void**)&y2,  g_y2);
    cudaGetSymbolAddress((void**)&yE,  g_yE);
    cudaGetSymbolAddress((void**)&Dx2, g_Dx2);
    cudaGetSymbolAddress((void**)&Dy2, g_Dy2);
    cudaGetSymbolAddress((void**)&E2,  g_E2);
    cudaGetSymbolAddress((void**)&ro2, g_ro2);
    cudaGetSymbolAddress((void**)&ct,  g_cos);
    cudaGetSymbolAddress((void**)&st,  g_sin);

    dim3 tb(32, 8);

    rope_table_kernel<<<(TT * 512 + 255) / 256, 256>>>();
    embed_ln_kernel<<<BB * TT, 256>>>(input_, emb, pos);
    transpose_half_kernel<<<dim3(KK / 32, DD / 32, HH), tb>>>(Dx, Dx2, DD, KK, (long)DD * KK, (long)KK * DD, 1);
    transpose_half_kernel<<<dim3(KK / 32, DD / 32, HH), tb>>>(Dy, Dy2, DD, KK, (long)DD * KK, (long)KK * DD, 1);
    transpose_half_kernel<<<dim3(DD / 32, NN_ / 32, 1), tb>>>(E, E2, NN_, DD, 0, 0, 2);
    transpose_half_kernel<<<dim3(BV / 32, DD / 32, 1), tb>>>(readout, ro2, DD, BV, 0, 0, 0);

    const long TK  = (long)TT * KK;
    const long TD  = (long)TT * DD;
    const long TN  = (long)TT * NN_;
    const long QTS = (long)KK * TT;        // qT per-bh stride
    const long WTS = (long)DD * KK;        // wT/wP per-bh stride

    for (int l = 0; l < LL; l++) {
        transpose_half_kernel<<<dim3(DD / 32, TT / 32, BB), tb>>>(v, vT, TT, DD, TD, (long)DD * TT, 0);

        // x = relu(v2a @ Dx2^T) fp32 gate (permuted) + RoPE -> qh [t,k], qT [k,t]
        gemm_mma<4><<<dim3(KK / 128, TT / 128, BB * HH), 256, SMEM_GEMM_BYTES>>>(
            v2a, Dx2, x, nullptr,
            DD, DD, DD, KK, 0,
            TD, 0, 0, (long)KK * DD, (long)HH * TK, TK, 0, 0, HH, 1, 0,
            qh, qT, ct, st);

        // wP[sp] = vT @ qT^T (split-K=2, fp32 partials) : M=256 N=1024 Kc=1024/split
        gemm_mma<0><<<dim3(KK / 128, DD / 128, BB * HH * 2), 256, SMEM_GEMM_BYTES>>>(
            vT, qT, wP, nullptr,
            TT / 2, TT, TT, KK, 0,
            (long)DD * TT, 0, (long)HH * QTS, QTS, (long)HH * WTS, WTS, 0, 0, HH, 2, 8L * 256 * 1024,
            nullptr, nullptr, nullptr, nullptr);

        // wT = fp16(wP[0] + wP[1])
        wsum_kernel<<<(int)((8L * 256 * 1024 + 255) / 256), 256>>>();

        // a[b,h] = qh @ wT^T fp32 : M=2048(t) N=256(d) Kc=1024(k)
        gemm_mma<0><<<dim3(DD / 128, TT / 128, BB * HH), 256, SMEM_GEMM_BYTES>>>(
            qh, wT, a, nullptr,
            KK, KK, KK, DD, 0,
            (long)HH * TK, TK, (long)HH * WTS, WTS, (long)HH * TD, TD, 0, 0, HH, 1, 0,
            nullptr, nullptr, nullptr, nullptr);

        ln_split_kernel<<<BB * HH * TT, 256>>>();

        // y2[b,t,h*K+n'] = relu(a2 @ Dy2^T) * x (fp16 hi, permuted cols)
        gemm_mma<3><<<dim3(KK / 128, TT / 128, BB * HH), 256, SMEM_GEMM_BYTES>>>(
            a2, Dy2, y2, x,
            DD, DD, DD, NN_, KK,
            (long)HH * TD, TD, 0, (long)KK * DD,
            TN, (long)KK, (long)HH * TK, TK, HH, 1, 0,
            nullptr, nullptr, nullptr, nullptr);

        // yE partials = y2 @ E2^T (split-K=4) : M=4096 N=256
        gemm_mma<0><<<dim3(DD / 128, (BB * TT) / 128, 4), 256, SMEM_GEMM_BYTES>>>(
            y2, E2, yE, nullptr,
            NN_ / 4, NN_, NN_, DD, 0,
            0, 0, 0, 0, 0, 0, 0, 0, 1, 4, 4096L * 256,
            nullptr, nullptr, nullptr, nullptr);

        combine_split_kernel<<<BB * TT, 256>>>(pos, l < LL - 1 ? 1 : 0);
    }

    // out = v2a @ ro2^T fp32 : M=4096 N=32000 Kd=256
    gemm_mma<0><<<dim3(BV / 128, (BB * TT) / 128, 1), 256, SMEM_GEMM_BYTES>>>(
        v2a, ro2, out, nullptr,
        DD, DD, DD, BV, 0,
        0, 0, 0, 0, 0, 0, 0, 0, 1, 1, 0,
        nullptr, nullptr, nullptr, nullptr);
}